// round 5
// baseline (speedup 1.0000x reference)
#include <cuda_runtime.h>
#include <cuda_bf16.h>
#include <cuda_fp16.h>
#include <math.h>
#include <stdint.h>

// ---------------------------------------------------------------------------
// Problem constants
// ---------------------------------------------------------------------------
#define B_   2
#define T_   2048
#define D_   1024
#define NH_  16
#define DH_  64
#define FFN_ 2736
#define FFNP 2816
#define M_   (B_ * T_)
#define EPS_ 1e-6f

// ---------------------------------------------------------------------------
// PTX helpers (arch-generic, sm_80+)
// ---------------------------------------------------------------------------
__device__ __forceinline__ uint32_t smem_u32(const void* p) {
    uint32_t a;
    asm("{ .reg .u64 t; cvta.to.shared.u64 t, %1; cvt.u32.u64 %0, t; }"
        : "=r"(a) : "l"(p));
    return a;
}
#define CP_ASYNC16(dst, src) \
    asm volatile("cp.async.cg.shared.global [%0], [%1], 16;" :: "r"(dst), "l"(src))
#define CP_COMMIT() asm volatile("cp.async.commit_group;" ::: "memory")
#define CP_WAIT0()  asm volatile("cp.async.wait_group 0;" ::: "memory")
#define CP_WAIT1()  asm volatile("cp.async.wait_group 1;" ::: "memory")
#define LDSM_X4(r0, r1, r2, r3, addr) \
    asm volatile("ldmatrix.sync.aligned.m8n8.x4.shared.b16 {%0,%1,%2,%3}, [%4];" \
                 : "=r"(r0), "=r"(r1), "=r"(r2), "=r"(r3) : "r"(addr))
#define MMA16816(d, a, b0, b1) \
    asm volatile("mma.sync.aligned.m16n8k16.row.col.f32.bf16.bf16.f32 " \
                 "{%0,%1,%2,%3},{%4,%5,%6,%7},{%8,%9},{%0,%1,%2,%3};" \
                 : "+f"((d)[0]), "+f"((d)[1]), "+f"((d)[2]), "+f"((d)[3]) \
                 : "r"((a)[0]), "r"((a)[1]), "r"((a)[2]), "r"((a)[3]), \
                   "r"(b0), "r"(b1))
#define MMAH16816(d, a, b0, b1) \
    asm volatile("mma.sync.aligned.m16n8k16.row.col.f32.f16.f16.f32 " \
                 "{%0,%1,%2,%3},{%4,%5,%6,%7},{%8,%9},{%0,%1,%2,%3};" \
                 : "+f"((d)[0]), "+f"((d)[1]), "+f"((d)[2]), "+f"((d)[3]) \
                 : "r"((a)[0]), "r"((a)[1]), "r"((a)[2]), "r"((a)[3]), \
                   "r"(b0), "r"(b1))
#define MMATF32(d, a, b0, b1) \
    asm volatile("mma.sync.aligned.m16n8k8.row.col.f32.tf32.tf32.f32 " \
                 "{%0,%1,%2,%3},{%4,%5,%6,%7},{%8,%9},{%0,%1,%2,%3};" \
                 : "+f"((d)[0]), "+f"((d)[1]), "+f"((d)[2]), "+f"((d)[3]) \
                 : "r"((a)[0]), "r"((a)[1]), "r"((a)[2]), "r"((a)[3]), \
                   "r"(b0), "r"(b1))
__device__ __forceinline__ uint32_t f2tf(float f) {
    uint32_t r;
    asm("cvt.rna.tf32.f32 %0, %1;" : "=r"(r) : "f"(f));
    return r;
}

// ---------------------------------------------------------------------------
// Device scratch
// ---------------------------------------------------------------------------
__device__ float s_glin[M_ * D_];
__device__ float s_xmix[M_ * D_];
__device__ float s_qkv [M_ * 3 * D_];
__device__ float s_dd  [M_ * NH_ * 16];
__device__ float s_csum[B_ * 16 * 256];
__device__ float s_qt  [B_ * NH_ * T_ * DH_];
__device__ float s_kt  [B_ * NH_ * T_ * DH_];
__device__ float s_vt  [B_ * NH_ * T_ * DH_];
__device__ float s_x2  [M_ * D_];
__device__ float s_gate[M_ * FFNP];
__device__ float s_up  [M_ * FFNP];
// bf16 split buffers (dd path only)
__device__ __nv_bfloat16 g_ah[(size_t)M_ * D_];
__device__ __nv_bfloat16 g_al[(size_t)M_ * D_];
__device__ __nv_bfloat16 g_wh[256 * D_];
__device__ __nv_bfloat16 g_wl[256 * D_];
// fp16 buffers (main GEMM path)
__device__ __half g_af [(size_t)M_ * FFNP];
__device__ __half g_wfh[3 * D_ * D_];
__device__ __half g_wfl[3 * D_ * D_];

// ---------------------------------------------------------------------------
// conversions
// ---------------------------------------------------------------------------
__global__ void convsplit(const float* __restrict__ src,
                          __nv_bfloat16* __restrict__ h,
                          __nv_bfloat16* __restrict__ l,
                          int rows, int cols, int rows_pad, int cols_pad)
{
    size_t i = (size_t)blockIdx.x * blockDim.x + threadIdx.x;
    size_t total = (size_t)rows_pad * cols_pad;
    if (i >= total) return;
    int r = (int)(i / cols_pad);
    int c = (int)(i - (size_t)r * cols_pad);
    float v = (r < rows && c < cols) ? src[(size_t)r * cols + c] : 0.f;
    __nv_bfloat16 hi = __float2bfloat16(v);
    h[i] = hi;
    l[i] = __float2bfloat16(v - __bfloat162float(hi));
}

// weights: fp32 -> fp16 hi/lo split with zero padding
__global__ void conv_wsplith(const float* __restrict__ src,
                             __half* __restrict__ h, __half* __restrict__ l,
                             int rows, int cols, int rows_pad, int cols_pad)
{
    size_t i = (size_t)blockIdx.x * blockDim.x + threadIdx.x;
    size_t total = (size_t)rows_pad * cols_pad;
    if (i >= total) return;
    int r = (int)(i / cols_pad);
    int c = (int)(i - (size_t)r * cols_pad);
    float v = (r < rows && c < cols) ? src[(size_t)r * cols + c] : 0.f;
    __half hi = __float2half(v);
    h[i] = hi;
    l[i] = __float2half(v - __half2float(hi));
}

// activations: fp32 -> fp16 single
__global__ void conv_half(const float* __restrict__ src, __half* __restrict__ d)
{
    size_t i = ((size_t)blockIdx.x * blockDim.x + threadIdx.x) * 4;
    float4 v = *(const float4*)(src + i);
    __half hb[4] = { __float2half(v.x), __float2half(v.y),
                     __float2half(v.z), __float2half(v.w) };
    *(uint2*)(d + i) = *(uint2*)hb;
}

// ---------------------------------------------------------------------------
// fp16 GEMM (A single fp16, W split fp16): C = A @ W^T (+bias)(+res)
// CTA 128x128, BK=32, 8 warps, double-buffered cp.async. 2 MMA per k16.
// ---------------------------------------------------------------------------
#define MATB 10240                        // 128 rows * 80 B
#define BUFB  (4 * MATB)                  // bf16 kernel stage (4 matrices)
#define BUFBH (3 * MATB)                  // fp16 kernel stage (3 matrices)

__global__ __launch_bounds__(256, 1) void mma_gemm_h(
    const __half* __restrict__ Af,
    const __half* __restrict__ Wh, const __half* __restrict__ Wl,
    const float* __restrict__ bias, const float* __restrict__ res,
    float* __restrict__ C, int K, int NKB, int ldc, int mode)
{
    extern __shared__ char smem[];
    const uint32_t su = smem_u32(smem);
    const int tid = threadIdx.x;
    const int wid = tid >> 5, lane = tid & 31;
    const int wm = wid >> 2, wn = wid & 3;
    const int m0 = blockIdx.y * 128, n0 = blockIdx.x * 128;

    const uint32_t a_lrow = (uint32_t)(wm * 64 + (lane & 15)) * 80u + ((lane >> 4) * 16u);
    const uint32_t b_lrow = (uint32_t)(wn * 32 + ((lane >> 4) & 1) * 8 + (lane & 7)) * 80u
                          + (((lane >> 3) & 1) * 16u);

    float acc[4][4][4] = {};

    const int ch0 = tid * 2;
    #define LOAD_BUFH(kb, b) do {                                             \
        _Pragma("unroll")                                                     \
        for (int c = 0; c < 2; c++) {                                         \
            const int ch = ch0 + c;                                           \
            const int row = ch >> 2, sub = ch & 3;                            \
            const uint32_t dst = su + (b) * BUFBH + (uint32_t)row * 80u + sub * 16u; \
            const size_t asrc = (size_t)(m0 + row) * K + (kb) * 32 + sub * 8; \
            const size_t wsrc = (size_t)(n0 + row) * K + (kb) * 32 + sub * 8; \
            CP_ASYNC16(dst +        0, Af + asrc);                            \
            CP_ASYNC16(dst +     MATB, Wh + wsrc);                            \
            CP_ASYNC16(dst + 2 * MATB, Wl + wsrc);                            \
        }                                                                     \
    } while (0)

    LOAD_BUFH(0, 0);
    CP_COMMIT();

    for (int kb = 0; kb < NKB; kb++) {
        if (kb + 1 < NKB) {
            LOAD_BUFH(kb + 1, (kb + 1) & 1);
            CP_COMMIT();
            CP_WAIT1();
        } else {
            CP_WAIT0();
        }
        __syncthreads();

        const uint32_t sb = su + (kb & 1) * BUFBH;
        #pragma unroll
        for (int ks = 0; ks < 2; ks++) {
            uint32_t af[4][4];
            uint32_t bh[2][4], bl[2][4];
            #pragma unroll
            for (int mt = 0; mt < 4; mt++) {
                const uint32_t ra = sb + a_lrow + (uint32_t)mt * 16u * 80u + ks * 32u;
                LDSM_X4(af[mt][0], af[mt][1], af[mt][2], af[mt][3], ra);
            }
            #pragma unroll
            for (int np = 0; np < 2; np++) {
                const uint32_t rb = sb + MATB + b_lrow + (uint32_t)np * 16u * 80u + ks * 32u;
                LDSM_X4(bh[np][0], bh[np][1], bh[np][2], bh[np][3], rb);
                LDSM_X4(bl[np][0], bl[np][1], bl[np][2], bl[np][3], rb + MATB);
            }
            #pragma unroll
            for (int mt = 0; mt < 4; mt++)
                #pragma unroll
                for (int nt = 0; nt < 4; nt++) {
                    const int np = nt >> 1, o = (nt & 1) * 2;
                    MMAH16816(acc[mt][nt], af[mt], bh[np][o], bh[np][o + 1]);
                    MMAH16816(acc[mt][nt], af[mt], bl[np][o], bl[np][o + 1]);
                }
        }
        __syncthreads();
    }

    const int qrow = lane >> 2, qcol = (lane & 3) * 2;
    #pragma unroll
    for (int mt = 0; mt < 4; mt++) {
        const int r0 = m0 + wm * 64 + mt * 16 + qrow;
        #pragma unroll
        for (int nt = 0; nt < 4; nt++) {
            const int c0 = n0 + wn * 32 + nt * 8 + qcol;
            float bx = 0.f, by = 0.f;
            if (mode & 1) { bx = bias[c0]; by = bias[c0 + 1]; }
            float2 v0 = make_float2(acc[mt][nt][0] + bx, acc[mt][nt][1] + by);
            float2 v1 = make_float2(acc[mt][nt][2] + bx, acc[mt][nt][3] + by);
            const size_t i0 = (size_t)r0 * ldc + c0;
            const size_t i1 = (size_t)(r0 + 8) * ldc + c0;
            if (mode & 2) {
                float2 r0v = *(const float2*)(res + i0);
                float2 r1v = *(const float2*)(res + i1);
                v0.x += r0v.x; v0.y += r0v.y;
                v1.x += r1v.x; v1.y += r1v.y;
            }
            *(float2*)(C + i0) = v0;
            *(float2*)(C + i1) = v1;
        }
    }
    #undef LOAD_BUFH
}

// ---------------------------------------------------------------------------
// bf16 3-term split GEMM (kept for the error-sensitive dd projection)
// ---------------------------------------------------------------------------
__global__ __launch_bounds__(256, 1) void mma_gemm(
    const __nv_bfloat16* __restrict__ Ah, const __nv_bfloat16* __restrict__ Al,
    const __nv_bfloat16* __restrict__ Wh, const __nv_bfloat16* __restrict__ Wl,
    const float* __restrict__ bias, const float* __restrict__ res,
    float* __restrict__ C, int K, int NKB, int ldc, int mode)
{
    extern __shared__ char smem[];
    const uint32_t su = smem_u32(smem);
    const int tid = threadIdx.x;
    const int wid = tid >> 5, lane = tid & 31;
    const int wm = wid >> 2, wn = wid & 3;
    const int m0 = blockIdx.y * 128, n0 = blockIdx.x * 128;

    const uint32_t a_lrow = (uint32_t)(wm * 64 + (lane & 15)) * 80u + ((lane >> 4) * 16u);
    const uint32_t b_lrow = (uint32_t)(wn * 32 + ((lane >> 4) & 1) * 8 + (lane & 7)) * 80u
                          + (((lane >> 3) & 1) * 16u);

    float acc[4][4][4] = {};

    const int ch0 = tid * 2;
    #define LOAD_BUF(kb, b) do {                                              \
        _Pragma("unroll")                                                     \
        for (int c = 0; c < 2; c++) {                                         \
            const int ch = ch0 + c;                                           \
            const int row = ch >> 2, sub = ch & 3;                            \
            const uint32_t dst = su + (b) * BUFB + (uint32_t)row * 80u + sub * 16u; \
            const size_t asrc = (size_t)(m0 + row) * K + (kb) * 32 + sub * 8; \
            const size_t wsrc = (size_t)(n0 + row) * K + (kb) * 32 + sub * 8; \
            CP_ASYNC16(dst +        0, Ah + asrc);                            \
            CP_ASYNC16(dst +     MATB, Al + asrc);                            \
            CP_ASYNC16(dst + 2 * MATB, Wh + wsrc);                            \
            CP_ASYNC16(dst + 3 * MATB, Wl + wsrc);                            \
        }                                                                     \
    } while (0)

    LOAD_BUF(0, 0);
    CP_COMMIT();

    for (int kb = 0; kb < NKB; kb++) {
        if (kb + 1 < NKB) {
            LOAD_BUF(kb + 1, (kb + 1) & 1);
            CP_COMMIT();
            CP_WAIT1();
        } else {
            CP_WAIT0();
        }
        __syncthreads();

        const uint32_t sb = su + (kb & 1) * BUFB;
        #pragma unroll
        for (int ks = 0; ks < 2; ks++) {
            uint32_t ah[4][4], al[4][4];
            uint32_t bh[2][4], bl[2][4];
            #pragma unroll
            for (int mt = 0; mt < 4; mt++) {
                const uint32_t ra = sb + a_lrow + (uint32_t)mt * 16u * 80u + ks * 32u;
                LDSM_X4(ah[mt][0], ah[mt][1], ah[mt][2], ah[mt][3], ra);
                LDSM_X4(al[mt][0], al[mt][1], al[mt][2], al[mt][3], ra + MATB);
            }
            #pragma unroll
            for (int np = 0; np < 2; np++) {
                const uint32_t rb = sb + 2 * MATB + b_lrow + (uint32_t)np * 16u * 80u + ks * 32u;
                LDSM_X4(bh[np][0], bh[np][1], bh[np][2], bh[np][3], rb);
                LDSM_X4(bl[np][0], bl[np][1], bl[np][2], bl[np][3], rb + MATB);
            }
            #pragma unroll
            for (int mt = 0; mt < 4; mt++)
                #pragma unroll
                for (int nt = 0; nt < 4; nt++) {
                    const int np = nt >> 1, o = (nt & 1) * 2;
                    MMA16816(acc[mt][nt], ah[mt], bh[np][o], bh[np][o + 1]);
                    MMA16816(acc[mt][nt], ah[mt], bl[np][o], bl[np][o + 1]);
                    MMA16816(acc[mt][nt], al[mt], bh[np][o], bh[np][o + 1]);
                }
        }
        __syncthreads();
    }

    const int qrow = lane >> 2, qcol = (lane & 3) * 2;
    #pragma unroll
    for (int mt = 0; mt < 4; mt++) {
        const int r0 = m0 + wm * 64 + mt * 16 + qrow;
        #pragma unroll
        for (int nt = 0; nt < 4; nt++) {
            const int c0 = n0 + wn * 32 + nt * 8 + qcol;
            float bx = 0.f, by = 0.f;
            if (mode & 1) { bx = bias[c0]; by = bias[c0 + 1]; }
            float2 v0 = make_float2(acc[mt][nt][0] + bx, acc[mt][nt][1] + by);
            float2 v1 = make_float2(acc[mt][nt][2] + bx, acc[mt][nt][3] + by);
            const size_t i0 = (size_t)r0 * ldc + c0;
            const size_t i1 = (size_t)(r0 + 8) * ldc + c0;
            if (mode & 2) {
                float2 r0v = *(const float2*)(res + i0);
                float2 r1v = *(const float2*)(res + i1);
                v0.x += r0v.x; v0.y += r0v.y;
                v1.x += r1v.x; v1.y += r1v.y;
            }
            *(float2*)(C + i0) = v0;
            *(float2*)(C + i1) = v1;
        }
    }
    #undef LOAD_BUF
}

// ---------------------------------------------------------------------------
// mix: xmix fp32 + bf16 hi/lo split (dd GEMM input)
// ---------------------------------------------------------------------------
__global__ void mix_split_kernel(const float* __restrict__ x,
                                 const float* __restrict__ glin,
                                 float* __restrict__ xmix,
                                 __nv_bfloat16* __restrict__ oh,
                                 __nv_bfloat16* __restrict__ ol)
{
    const size_t i = (size_t)blockIdx.x * blockDim.x + threadIdx.x;
    const int row = (int)(i >> 8);
    const int t = row & (T_ - 1);
    float4 xv = *(const float4*)(x + i * 4);
    float4 gv = *(const float4*)(glin + i * 4);
    float4 pv = make_float4(0.f, 0.f, 0.f, 0.f);
    if (t > 0) pv = *(const float4*)(x + (i - 256) * 4);
    float o[4]; float g;
    g = 1.f / (1.f + __expf(-gv.x)); o[0] = (1.f - g) * xv.x + g * pv.x;
    g = 1.f / (1.f + __expf(-gv.y)); o[1] = (1.f - g) * xv.y + g * pv.y;
    g = 1.f / (1.f + __expf(-gv.z)); o[2] = (1.f - g) * xv.z + g * pv.z;
    g = 1.f / (1.f + __expf(-gv.w)); o[3] = (1.f - g) * xv.w + g * pv.w;
    *(float4*)(xmix + i * 4) = make_float4(o[0], o[1], o[2], o[3]);
    __nv_bfloat16 hb[4], lb[4];
    #pragma unroll
    for (int j = 0; j < 4; j++) {
        hb[j] = __float2bfloat16(o[j]);
        lb[j] = __float2bfloat16(o[j] - __bfloat162float(hb[j]));
    }
    *(uint2*)(oh + i * 4) = *(uint2*)hb;
    *(uint2*)(ol + i * 4) = *(uint2*)lb;
}

// ---------------------------------------------------------------------------
// RMSNorm -> single fp16 output
// ---------------------------------------------------------------------------
__global__ __launch_bounds__(256) void rmsnorm_half_kernel(
    const float* __restrict__ x, const float* __restrict__ w,
    __half* __restrict__ oh)
{
    const int row = blockIdx.x;
    const int tid = threadIdx.x;
    const float* xr = x + (size_t)row * D_;
    float4 v = *(const float4*)(xr + tid * 4);
    float s = v.x * v.x + v.y * v.y + v.z * v.z + v.w * v.w;
    #pragma unroll
    for (int m = 16; m > 0; m >>= 1) s += __shfl_xor_sync(0xffffffffu, s, m);
    __shared__ float red[8];
    if ((tid & 31) == 0) red[tid >> 5] = s;
    __syncthreads();
    if (tid < 32) {
        float t = (tid < 8) ? red[tid] : 0.f;
        #pragma unroll
        for (int m = 4; m > 0; m >>= 1) t += __shfl_xor_sync(0xffffffffu, t, m);
        if (tid == 0) red[0] = t;
    }
    __syncthreads();
    const float inv = rsqrtf(red[0] / (float)D_ + EPS_);
    float4 wv = *(const float4*)(w + tid * 4);
    __half hb[4] = { __float2half(v.x * inv * wv.x), __float2half(v.y * inv * wv.y),
                     __float2half(v.z * inv * wv.z), __float2half(v.w * inv * wv.w) };
    *(uint2*)(oh + (size_t)row * D_ + tid * 4) = *(uint2*)hb;
}

// ---------------------------------------------------------------------------
// 3-phase cumsum
// ---------------------------------------------------------------------------
__global__ void cumsumA(const float* __restrict__ dd, float* __restrict__ cs)
{
    const int c = threadIdx.x;
    const int blk = blockIdx.x;
    const int b = blk >> 4, ch = blk & 15;
    size_t base = ((size_t)b * T_ + ch * 128) * 256 + c;
    float s = 0.f;
    #pragma unroll 8
    for (int t = 0; t < 128; t++) { s += dd[base]; base += 256; }
    cs[(size_t)blk * 256 + c] = s;
}
__global__ void cumsumB(float* __restrict__ cs)
{
    const int c = threadIdx.x;
    const int b = blockIdx.x;
    float run = 0.f;
    #pragma unroll
    for (int ch = 0; ch < 16; ch++) {
        size_t i = ((size_t)b * 16 + ch) * 256 + c;
        float t = cs[i];
        cs[i] = run;
        run += t;
    }
}
__global__ void cumsumC(float* __restrict__ dd, const float* __restrict__ cs)
{
    const int c = threadIdx.x;
    const int blk = blockIdx.x;
    const int b = blk >> 4, ch = blk & 15;
    float acc = cs[(size_t)blk * 256 + c];
    size_t base = ((size_t)b * T_ + ch * 128) * 256 + c;
    #pragma unroll 8
    for (int t = 0; t < 128; t++) { acc += dd[base]; dd[base] = acc; base += 256; }
}

// ---------------------------------------------------------------------------
// q/k head rmsnorm + hybrid rope + head-major scatter
// ---------------------------------------------------------------------------
__global__ __launch_bounds__(256) void qkv_transform_kernel(
    const float* __restrict__ qkv, const float* __restrict__ ddcum,
    const float* __restrict__ rc, const float* __restrict__ rs,
    const float* __restrict__ qnw, const float* __restrict__ knw,
    const float* __restrict__ qpb, const float* __restrict__ kpb,
    float* __restrict__ qt, float* __restrict__ kt, float* __restrict__ vt)
{
    const int w = blockIdx.x * 8 + (threadIdx.x >> 5);
    const int lane = threadIdx.x & 31;
    const int b = w >> 15;
    const int rem = w & 32767;
    const int t = rem >> 4;
    const int h = rem & 15;

    const size_t base = ((size_t)(b * T_ + t) * 3) * D_ + h * DH_;
    float q0 = qkv[base + lane],          q1 = qkv[base + 32 + lane];
    float k0 = qkv[base + D_ + lane],     k1 = qkv[base + D_ + 32 + lane];
    float v0 = qkv[base + 2 * D_ + lane], v1 = qkv[base + 2 * D_ + 32 + lane];

    float sq = q0 * q0 + q1 * q1;
    float sk = k0 * k0 + k1 * k1;
    #pragma unroll
    for (int m = 16; m > 0; m >>= 1) {
        sq += __shfl_xor_sync(0xffffffffu, sq, m);
        sk += __shfl_xor_sync(0xffffffffu, sk, m);
    }
    const float rq = rsqrtf(sq / 64.f + EPS_);
    const float rk = rsqrtf(sk / 64.f + EPS_);
    q0 *= rq * qnw[lane] * qpb[lane];
    q1 *= rq * qnw[lane + 32] * qpb[lane + 32];
    k0 *= rk * knw[lane] * kpb[lane];
    k1 *= rk * knw[lane + 32] * kpb[lane + 32];

    const int j = lane & 15;
    const float c = rc[t * 32 + j], s = rs[t * 32 + j];
    const float ang = ddcum[((size_t)(b * T_ + t)) * 256 + h * 16 + j];
    float s2, c2;
    sincosf(ang, &s2, &c2);

    const float qp0 = __shfl_xor_sync(0xffffffffu, q0, 16);
    const float qp1 = __shfl_xor_sync(0xffffffffu, q1, 16);
    const float kp0 = __shfl_xor_sync(0xffffffffu, k0, 16);
    const float kp1 = __shfl_xor_sync(0xffffffffu, k1, 16);
    float oq0, oq1, ok0, ok1;
    if (lane < 16) {
        oq0 = q0 * c - qp0 * s;  oq1 = q1 * c2 - qp1 * s2;
        ok0 = k0 * c - kp0 * s;  ok1 = k1 * c2 - kp1 * s2;
    } else {
        oq0 = q0 * c + qp0 * s;  oq1 = q1 * c2 + qp1 * s2;
        ok0 = k0 * c + kp0 * s;  ok1 = k1 * c2 + kp1 * s2;
    }

    const size_t ob = ((size_t)(b * NH_ + h) * T_ + t) * DH_;
    qt[ob + lane] = oq0;  qt[ob + 32 + lane] = oq1;
    kt[ob + lane] = ok0;  kt[ob + 32 + lane] = ok1;
    vt[ob + lane] = v0;   vt[ob + 32 + lane] = v1;
}

// ---------------------------------------------------------------------------
// Flash attention (tf32 mma, R4-validated) -> single fp16 output
// ---------------------------------------------------------------------------
#define KS_OFF 0
#define VS_OFF (64 * 72)
#define PS_OFF (2 * 64 * 72)
#define FSMEM ((2 * 64 * 72 + 128 * 68) * 4)

__global__ __launch_bounds__(256, 1) void flash_tc(
    const float* __restrict__ qt, const float* __restrict__ kt,
    const float* __restrict__ vt, __half* __restrict__ yh)
{
    extern __shared__ uint32_t fsm[];
    uint32_t* Ks = fsm + KS_OFF;
    uint32_t* Vs = fsm + VS_OFF;
    uint32_t* Ps = fsm + PS_OFF;

    const int tid = threadIdx.x, lane = tid & 31, w = tid >> 5;
    const int bx = blockIdx.x, bh = blockIdx.y;
    const int b = bh >> 4, h = bh & 15;
    const int m0 = bx * 128;

    const float* Qb = qt + (size_t)bh * T_ * DH_;
    const float* Kb = kt + (size_t)bh * T_ * DH_;
    const float* Vb = vt + (size_t)bh * T_ * DH_;

    const int r1 = m0 + w * 16 + (lane >> 2);
    uint32_t qf[8][4];
    {
        const float* q1 = Qb + (size_t)r1 * DH_;
        const float* q2 = q1 + 8 * DH_;
        #pragma unroll
        for (int k8 = 0; k8 < 8; k8++) {
            const int c = k8 * 8 + (lane & 3);
            qf[k8][0] = f2tf(q1[c] * 0.125f);
            qf[k8][1] = f2tf(q2[c] * 0.125f);
            qf[k8][2] = f2tf(q1[c + 4] * 0.125f);
            qf[k8][3] = f2tf(q2[c + 4] * 0.125f);
        }
    }

    float mi[2] = { -1e30f, -1e30f }, li[2] = { 0.f, 0.f };
    float O[8][4] = {};

    const int ntiles = 2 * bx + 2;
    for (int nt = 0; nt < ntiles; nt++) {
        const int n0 = nt * 64;
        __syncthreads();
        {
            const int key = tid >> 2, db = (tid & 3) * 16;
            const float* kp = Kb + (size_t)(n0 + key) * DH_ + db;
            const float* vp = Vb + (size_t)(n0 + key) * DH_ + db;
            #pragma unroll
            for (int i = 0; i < 16; i += 4) {
                float4 kv = *(const float4*)(kp + i);
                Ks[(db + i + 0) * 72 + key] = f2tf(kv.x);
                Ks[(db + i + 1) * 72 + key] = f2tf(kv.y);
                Ks[(db + i + 2) * 72 + key] = f2tf(kv.z);
                Ks[(db + i + 3) * 72 + key] = f2tf(kv.w);
                float4 vv = *(const float4*)(vp + i);
                uint4 vo;
                vo.x = f2tf(vv.x); vo.y = f2tf(vv.y);
                vo.z = f2tf(vv.z); vo.w = f2tf(vv.w);
                *(uint4*)&Vs[key * 72 + db + i] = vo;
            }
        }
        __syncthreads();

        float S[8][4] = {};
        #pragma unroll
        for (int k8 = 0; k8 < 8; k8++) {
            const uint32_t* kr0 = &Ks[(k8 * 8 + (lane & 3)) * 72 + (lane >> 2)];
            const uint32_t* kr1 = kr0 + 4 * 72;
            #pragma unroll
            for (int n8 = 0; n8 < 8; n8++) {
                MMATF32(S[n8], qf[k8], kr0[n8 * 8], kr1[n8 * 8]);
            }
        }
        if (nt >= 2 * bx) {
            #pragma unroll
            for (int n8 = 0; n8 < 8; n8++) {
                const int cb = n0 + n8 * 8 + 2 * (lane & 3);
                if (cb     > r1)     S[n8][0] = -1e30f;
                if (cb + 1 > r1)     S[n8][1] = -1e30f;
                if (cb     > r1 + 8) S[n8][2] = -1e30f;
                if (cb + 1 > r1 + 8) S[n8][3] = -1e30f;
            }
        }
        #pragma unroll
        for (int half = 0; half < 2; half++) {
            float mx = -1e30f;
            #pragma unroll
            for (int n8 = 0; n8 < 8; n8++)
                mx = fmaxf(mx, fmaxf(S[n8][half * 2], S[n8][half * 2 + 1]));
            mx = fmaxf(mx, __shfl_xor_sync(0xffffffffu, mx, 1));
            mx = fmaxf(mx, __shfl_xor_sync(0xffffffffu, mx, 2));
            const float mnew = fmaxf(mi[half], mx);
            const float corr = __expf(mi[half] - mnew);
            float rsum = 0.f;
            #pragma unroll
            for (int n8 = 0; n8 < 8; n8++) {
                float e0 = __expf(S[n8][half * 2]     - mnew);
                float e1 = __expf(S[n8][half * 2 + 1] - mnew);
                S[n8][half * 2] = e0; S[n8][half * 2 + 1] = e1;
                rsum += e0 + e1;
            }
            rsum += __shfl_xor_sync(0xffffffffu, rsum, 1);
            rsum += __shfl_xor_sync(0xffffffffu, rsum, 2);
            li[half] = li[half] * corr + rsum;
            mi[half] = mnew;
            #pragma unroll
            for (int n8 = 0; n8 < 8; n8++) {
                O[n8][half * 2]     *= corr;
                O[n8][half * 2 + 1] *= corr;
            }
        }
        {
            const int pr = w * 16 + (lane >> 2);
            #pragma unroll
            for (int n8 = 0; n8 < 8; n8++) {
                const int pc = n8 * 8 + 2 * (lane & 3);
                uint2 p0, p1;
                p0.x = f2tf(S[n8][0]); p0.y = f2tf(S[n8][1]);
                p1.x = f2tf(S[n8][2]); p1.y = f2tf(S[n8][3]);
                *(uint2*)&Ps[pr * 68 + pc]       = p0;
                *(uint2*)&Ps[(pr + 8) * 68 + pc] = p1;
            }
        }
        __syncwarp();
        #pragma unroll
        for (int k8 = 0; k8 < 8; k8++) {
            uint32_t a[4];
            const int pr = w * 16 + (lane >> 2);
            const int pc = k8 * 8 + (lane & 3);
            a[0] = Ps[pr * 68 + pc];
            a[1] = Ps[(pr + 8) * 68 + pc];
            a[2] = Ps[pr * 68 + pc + 4];
            a[3] = Ps[(pr + 8) * 68 + pc + 4];
            const uint32_t* vr0 = &Vs[(k8 * 8 + (lane & 3)) * 72 + (lane >> 2)];
            const uint32_t* vr1 = vr0 + 4 * 72;
            #pragma unroll
            for (int n8 = 0; n8 < 8; n8++) {
                MMATF32(O[n8], a, vr0[n8 * 8], vr1[n8 * 8]);
            }
        }
    }

    const float inv0 = 1.f / li[0], inv1 = 1.f / li[1];
    const size_t o1 = ((size_t)(b * T_ + r1)) * D_ + h * DH_ + 2 * (lane & 3);
    const size_t o2 = o1 + 8 * D_;
    #pragma unroll
    for (int n8 = 0; n8 < 8; n8++) {
        __half2 h0, h1;
        h0.x = __float2half(O[n8][0] * inv0); h0.y = __float2half(O[n8][1] * inv0);
        h1.x = __float2half(O[n8][2] * inv1); h1.y = __float2half(O[n8][3] * inv1);
        *(__half2*)(yh + o1 + n8 * 8) = h0;
        *(__half2*)(yh + o2 + n8 * 8) = h1;
    }
}

// ---------------------------------------------------------------------------
// act = silu(gate)*up -> single fp16
// ---------------------------------------------------------------------------
__global__ void act_half_kernel(const float* __restrict__ gate,
                                const float* __restrict__ up,
                                __half* __restrict__ oh)
{
    const size_t i = (size_t)blockIdx.x * blockDim.x + threadIdx.x;
    float4 g = *(const float4*)(gate + i * 4);
    float4 u = *(const float4*)(up + i * 4);
    __half hb[4];
    hb[0] = __float2half(g.x / (1.f + __expf(-g.x)) * u.x);
    hb[1] = __float2half(g.y / (1.f + __expf(-g.y)) * u.y);
    hb[2] = __float2half(g.z / (1.f + __expf(-g.z)) * u.z);
    hb[3] = __float2half(g.w / (1.f + __expf(-g.w)) * u.w);
    *(uint2*)(oh + i * 4) = *(uint2*)hb;
}

// ---------------------------------------------------------------------------
// Launch
// ---------------------------------------------------------------------------
static inline int cdiv(long long a, long long b) { return (int)((a + b - 1) / b); }

extern "C" void kernel_launch(void* const* d_in, const int* in_sizes, int n_in,
                              void* d_out, int out_size)
{
    const float* x     = (const float*)d_in[0];
    const float* rc    = (const float*)d_in[1];
    const float* rs    = (const float*)d_in[2];
    const float* lerpw = (const float*)d_in[3];
    const float* lerpb = (const float*)d_in[4];
    const float* anw   = (const float*)d_in[5];
    const float* wqkv  = (const float*)d_in[6];
    const float* qnw   = (const float*)d_in[7];
    const float* knw   = (const float*)d_in[8];
    const float* qpb   = (const float*)d_in[9];
    const float* kpb   = (const float*)d_in[10];
    const float* ddw   = (const float*)d_in[11];
    const float* ddb   = (const float*)d_in[12];
    const float* wo    = (const float*)d_in[13];
    const float* mnw   = (const float*)d_in[14];
    const float* gw    = (const float*)d_in[15];
    const float* uw    = (const float*)d_in[16];
    const float* dw    = (const float*)d_in[17];
    float* out = (float*)d_out;

    float *glin, *xmix, *qkv, *dd, *cs, *qt, *kt, *vt, *x2, *gate, *up;
    __nv_bfloat16 *ah, *al, *wh, *wl;
    __half *af, *wfh, *wfl;
    cudaGetSymbolAddress((void**)&glin, s_glin);
    cudaGetSymbolAddress((void**)&xmix, s_xmix);
    cudaGetSymbolAddress((void**)&qkv,  s_qkv);
    cudaGetSymbolAddress((void**)&dd,   s_dd);
    cudaGetSymbolAddress((void**)&cs,   s_csum);
    cudaGetSymbolAddress((void**)&qt,   s_qt);
    cudaGetSymbolAddress((void**)&kt,   s_kt);
    cudaGetSymbolAddress((void**)&vt,   s_vt);
    cudaGetSymbolAddress((void**)&x2,   s_x2);
    cudaGetSymbolAddress((void**)&gate, s_gate);
    cudaGetSymbolAddress((void**)&up,   s_up);
    cudaGetSymbolAddress((void**)&ah,   g_ah);
    cudaGetSymbolAddress((void**)&al,   g_al);
    cudaGetSymbolAddress((void**)&wh,   g_wh);
    cudaGetSymbolAddress((void**)&wl,   g_wl);
    cudaGetSymbolAddress((void**)&af,   g_af);
    cudaGetSymbolAddress((void**)&wfh,  g_wfh);
    cudaGetSymbolAddress((void**)&wfl,  g_wfl);

    cudaFuncSetAttribute(mma_gemm,
                         cudaFuncAttributeMaxDynamicSharedMemorySize, 2 * BUFB);
    cudaFuncSetAttribute(mma_gemm_h,
                         cudaFuncAttributeMaxDynamicSharedMemorySize, 2 * BUFBH);
    cudaFuncSetAttribute(flash_tc,
                         cudaFuncAttributeMaxDynamicSharedMemorySize, FSMEM);

    const dim3 blk(256);
    const int GSM  = 2 * BUFB;    // 81920
    const int GSMH = 2 * BUFBH;   // 61440

    #define CONVH(src, d, n) \
        conv_half<<<(int)(((long long)(n) / 4) / 256), blk>>>(src, d)
    #define CONVW(src, dh, dl, r, c, rp, cp) \
        conv_wsplith<<<cdiv((long long)(rp) * (cp), 256), blk>>>(src, dh, dl, r, c, rp, cp)

    // 1. glin = x @ lerp_w^T + lerp_b   (A = x fp16)
    CONVH(x, af, (long long)M_ * D_);
    CONVW(lerpw, wfh, wfl, D_, D_, D_, D_);
    mma_gemm_h<<<dim3(8, 32), blk, GSMH>>>(af, wfh, wfl, lerpb, nullptr, glin, D_, 32, D_, 1);
    // 2. xmix (fp32 + bf16 split for dd)
    mix_split_kernel<<<(M_ * D_ / 4) / 256, blk>>>(x, glin, xmix, ah, al);
    // 3. dd = xmix @ dd_w^T + dd_b (bf16 3-term — precision-critical)
    convsplit<<<cdiv(256LL * D_, 256), blk>>>(ddw, wh, wl, 256, D_, 256, D_);
    mma_gemm<<<dim3(2, 32), blk, GSM>>>(ah, al, wh, wl, ddb, nullptr, dd, D_, 32, 256, 1);
    // 4. cumsum along T
    cumsumA<<<B_ * 16, blk>>>(dd, cs);
    cumsumB<<<B_, blk>>>(cs);
    cumsumC<<<B_ * 16, blk>>>(dd, cs);
    // 5. h = rmsnorm(xmix) -> fp16
    rmsnorm_half_kernel<<<M_, blk>>>(xmix, anw, af);
    // 6. qkv = h @ w_qkv^T
    CONVW(wqkv, wfh, wfl, 3 * D_, D_, 3 * D_, D_);
    mma_gemm_h<<<dim3(24, 32), blk, GSMH>>>(af, wfh, wfl, nullptr, nullptr, qkv, D_, 32, 3 * D_, 0);
    // 7. q/k transform
    qkv_transform_kernel<<<(B_ * T_ * NH_) / 8, blk>>>(qkv, dd, rc, rs, qnw, knw,
                                                       qpb, kpb, qt, kt, vt);
    // 8. flash attention (tf32) -> y fp16
    flash_tc<<<dim3(T_ / 128, B_ * NH_), blk, FSMEM>>>(qt, kt, vt, af);
    // 9. x2 = xmix + y @ w_o^T
    CONVW(wo, wfh, wfl, D_, D_, D_, D_);
    mma_gemm_h<<<dim3(8, 32), blk, GSMH>>>(af, wfh, wfl, nullptr, xmix, x2, D_, 32, D_, 2);
    // 10. h = rmsnorm(x2) -> fp16
    rmsnorm_half_kernel<<<M_, blk>>>(x2, mnw, af);
    // 11/12. gate, up
    CONVW(gw, wfh, wfl, FFN_, D_, FFNP, D_);
    mma_gemm_h<<<dim3(22, 32), blk, GSMH>>>(af, wfh, wfl, nullptr, nullptr, gate, D_, 32, FFNP, 0);
    CONVW(uw, wfh, wfl, FFN_, D_, FFNP, D_);
    mma_gemm_h<<<dim3(22, 32), blk, GSMH>>>(af, wfh, wfl, nullptr, nullptr, up, D_, 32, FFNP, 0);
    // 13. act = silu(gate)*up -> fp16
    act_half_kernel<<<(M_ * FFNP / 4) / 256, blk>>>(gate, up, af);
    // 14. out = x2 + act @ down_w^T
    CONVW(dw, wfh, wfl, D_, FFN_, D_, FFNP);
    mma_gemm_h<<<dim3(8, 32), blk, GSMH>>>(af, wfh, wfl, nullptr, x2, out, FFNP, 88, D_, 2);
}

// round 6
// speedup vs baseline: 1.2159x; 1.2159x over previous
#include <cuda_runtime.h>
#include <cuda_bf16.h>
#include <math.h>
#include <stdint.h>

// ---------------------------------------------------------------------------
// Problem constants
// ---------------------------------------------------------------------------
#define B_   2
#define T_   2048
#define D_   1024
#define NH_  16
#define DH_  64
#define FFN_ 2736
#define FFNP 2816
#define M_   (B_ * T_)
#define EPS_ 1e-6f

// ---------------------------------------------------------------------------
// PTX helpers (arch-generic, sm_80+)
// ---------------------------------------------------------------------------
__device__ __forceinline__ uint32_t smem_u32(const void* p) {
    uint32_t a;
    asm("{ .reg .u64 t; cvta.to.shared.u64 t, %1; cvt.u32.u64 %0, t; }"
        : "=r"(a) : "l"(p));
    return a;
}
#define CP_ASYNC16(dst, src) \
    asm volatile("cp.async.cg.shared.global [%0], [%1], 16;" :: "r"(dst), "l"(src))
#define CP_COMMIT() asm volatile("cp.async.commit_group;" ::: "memory")
#define CP_WAIT0()  asm volatile("cp.async.wait_group 0;" ::: "memory")
#define CP_WAIT1()  asm volatile("cp.async.wait_group 1;" ::: "memory")
#define LDSM_X4(r0, r1, r2, r3, addr) \
    asm volatile("ldmatrix.sync.aligned.m8n8.x4.shared.b16 {%0,%1,%2,%3}, [%4];" \
                 : "=r"(r0), "=r"(r1), "=r"(r2), "=r"(r3) : "r"(addr))
#define MMA16816(d, a, b0, b1) \
    asm volatile("mma.sync.aligned.m16n8k16.row.col.f32.bf16.bf16.f32 " \
                 "{%0,%1,%2,%3},{%4,%5,%6,%7},{%8,%9},{%0,%1,%2,%3};" \
                 : "+f"((d)[0]), "+f"((d)[1]), "+f"((d)[2]), "+f"((d)[3]) \
                 : "r"((a)[0]), "r"((a)[1]), "r"((a)[2]), "r"((a)[3]), \
                   "r"(b0), "r"(b1))
#define MMATF32(d, a, b0, b1) \
    asm volatile("mma.sync.aligned.m16n8k8.row.col.f32.tf32.tf32.f32 " \
                 "{%0,%1,%2,%3},{%4,%5,%6,%7},{%8,%9},{%0,%1,%2,%3};" \
                 : "+f"((d)[0]), "+f"((d)[1]), "+f"((d)[2]), "+f"((d)[3]) \
                 : "r"((a)[0]), "r"((a)[1]), "r"((a)[2]), "r"((a)[3]), \
                   "r"(b0), "r"(b1))
__device__ __forceinline__ uint32_t f2tf(float f) {
    uint32_t r;
    asm("cvt.rna.tf32.f32 %0, %1;" : "=r"(r) : "f"(f));
    return r;
}

// ---------------------------------------------------------------------------
// Device scratch
// ---------------------------------------------------------------------------
__device__ float s_glin[M_ * D_];
__device__ float s_xmix[M_ * D_];
__device__ float s_qkv [M_ * 3 * D_];
__device__ float s_dd  [M_ * NH_ * 16];
__device__ float s_csum[B_ * 16 * 256];
__device__ float s_qt  [B_ * NH_ * T_ * DH_];
__device__ float s_kt  [B_ * NH_ * T_ * DH_];
__device__ float s_vt  [B_ * NH_ * T_ * DH_];
__device__ float s_x2  [M_ * D_];
__device__ float s_gu  [(size_t)M_ * 2 * FFNP];     // gate | up combined
__device__ __nv_bfloat16 g_ah[(size_t)M_ * FFNP];
__device__ __nv_bfloat16 g_al[(size_t)M_ * FFNP];
__device__ __nv_bfloat16 g_wh[(size_t)2 * FFNP * D_];
__device__ __nv_bfloat16 g_wl[(size_t)2 * FFNP * D_];

// ---------------------------------------------------------------------------
// fp32 -> bf16 hi/lo split with 2D zero-padding
// ---------------------------------------------------------------------------
__global__ void convsplit(const float* __restrict__ src,
                          __nv_bfloat16* __restrict__ h,
                          __nv_bfloat16* __restrict__ l,
                          int rows, int cols, int rows_pad, int cols_pad)
{
    size_t i = (size_t)blockIdx.x * blockDim.x + threadIdx.x;
    size_t total = (size_t)rows_pad * cols_pad;
    if (i >= total) return;
    int r = (int)(i / cols_pad);
    int c = (int)(i - (size_t)r * cols_pad);
    float v = (r < rows && c < cols) ? src[(size_t)r * cols + c] : 0.f;
    __nv_bfloat16 hi = __float2bfloat16(v);
    h[i] = hi;
    l[i] = __float2bfloat16(v - __bfloat162float(hi));
}

// ---------------------------------------------------------------------------
// mma.sync split-bf16 GEMM: C[M,N] = A[M,K] @ W[N,K]^T (+bias)(+res)
// CTA 128x128, BK=32, 8 warps, 3-stage cp.async pipeline,
// ONE __syncthreads per K-iteration, 2-iteration prefetch slack.
// ---------------------------------------------------------------------------
#define MATB 10240                        // 128 rows * 80 B
#define BUFB (4 * MATB)                   // per-stage (4 matrices)

__global__ __launch_bounds__(256, 1) void mma_gemm(
    const __nv_bfloat16* __restrict__ Ah, const __nv_bfloat16* __restrict__ Al,
    const __nv_bfloat16* __restrict__ Wh, const __nv_bfloat16* __restrict__ Wl,
    const float* __restrict__ bias, const float* __restrict__ res,
    float* __restrict__ C, int K, int NKB, int ldc, int mode)
{
    extern __shared__ char smem[];
    const uint32_t su = smem_u32(smem);
    const int tid = threadIdx.x;
    const int wid = tid >> 5, lane = tid & 31;
    const int wm = wid >> 2, wn = wid & 3;
    const int m0 = blockIdx.y * 128, n0 = blockIdx.x * 128;

    const uint32_t a_lrow = (uint32_t)(wm * 64 + (lane & 15)) * 80u + ((lane >> 4) * 16u);
    const uint32_t b_lrow = (uint32_t)(wn * 32 + ((lane >> 4) & 1) * 8 + (lane & 7)) * 80u
                          + (((lane >> 3) & 1) * 16u);

    float acc[4][4][4] = {};

    const int ch0 = tid * 2;
    #define LOAD_BUF(kb, b) do {                                              \
        _Pragma("unroll")                                                     \
        for (int c = 0; c < 2; c++) {                                         \
            const int ch = ch0 + c;                                           \
            const int row = ch >> 2, sub = ch & 3;                            \
            const uint32_t dst = su + (b) * BUFB + (uint32_t)row * 80u + sub * 16u; \
            const size_t asrc = (size_t)(m0 + row) * K + (kb) * 32 + sub * 8; \
            const size_t wsrc = (size_t)(n0 + row) * K + (kb) * 32 + sub * 8; \
            CP_ASYNC16(dst +        0, Ah + asrc);                            \
            CP_ASYNC16(dst +     MATB, Al + asrc);                            \
            CP_ASYNC16(dst + 2 * MATB, Wh + wsrc);                            \
            CP_ASYNC16(dst + 3 * MATB, Wl + wsrc);                            \
        }                                                                     \
    } while (0)

    LOAD_BUF(0, 0);
    CP_COMMIT();
    LOAD_BUF(1, 1);
    CP_COMMIT();

    int stage = 0;   // kb % 3
    for (int kb = 0; kb < NKB; kb++) {
        if (kb + 1 < NKB) { CP_WAIT1(); } else { CP_WAIT0(); }
        __syncthreads();
        if (kb + 2 < NKB) {
            int ns = stage + 2; if (ns >= 3) ns -= 3;
            LOAD_BUF(kb + 2, ns);
            CP_COMMIT();
        }

        const uint32_t sb = su + stage * BUFB;
        #pragma unroll
        for (int ks = 0; ks < 2; ks++) {
            uint32_t ah[4][4], al[4][4];
            uint32_t bh[2][4], bl[2][4];
            #pragma unroll
            for (int mt = 0; mt < 4; mt++) {
                const uint32_t ra = sb + a_lrow + (uint32_t)mt * 16u * 80u + ks * 32u;
                LDSM_X4(ah[mt][0], ah[mt][1], ah[mt][2], ah[mt][3], ra);
                LDSM_X4(al[mt][0], al[mt][1], al[mt][2], al[mt][3], ra + MATB);
            }
            #pragma unroll
            for (int np = 0; np < 2; np++) {
                const uint32_t rb = sb + 2 * MATB + b_lrow + (uint32_t)np * 16u * 80u + ks * 32u;
                LDSM_X4(bh[np][0], bh[np][1], bh[np][2], bh[np][3], rb);
                LDSM_X4(bl[np][0], bl[np][1], bl[np][2], bl[np][3], rb + MATB);
            }
            #pragma unroll
            for (int mt = 0; mt < 4; mt++)
                #pragma unroll
                for (int nt = 0; nt < 4; nt++) {
                    const int np = nt >> 1, o = (nt & 1) * 2;
                    MMA16816(acc[mt][nt], ah[mt], bh[np][o], bh[np][o + 1]);
                    MMA16816(acc[mt][nt], ah[mt], bl[np][o], bl[np][o + 1]);
                    MMA16816(acc[mt][nt], al[mt], bh[np][o], bh[np][o + 1]);
                }
        }
        stage++; if (stage >= 3) stage = 0;
    }

    const int qrow = lane >> 2, qcol = (lane & 3) * 2;
    #pragma unroll
    for (int mt = 0; mt < 4; mt++) {
        const int r0 = m0 + wm * 64 + mt * 16 + qrow;
        #pragma unroll
        for (int nt = 0; nt < 4; nt++) {
            const int c0 = n0 + wn * 32 + nt * 8 + qcol;
            float bx = 0.f, by = 0.f;
            if (mode & 1) { bx = bias[c0]; by = bias[c0 + 1]; }
            float2 v0 = make_float2(acc[mt][nt][0] + bx, acc[mt][nt][1] + by);
            float2 v1 = make_float2(acc[mt][nt][2] + bx, acc[mt][nt][3] + by);
            const size_t i0 = (size_t)r0 * ldc + c0;
            const size_t i1 = (size_t)(r0 + 8) * ldc + c0;
            if (mode & 2) {
                float2 r0v = *(const float2*)(res + i0);
                float2 r1v = *(const float2*)(res + i1);
                v0.x += r0v.x; v0.y += r0v.y;
                v1.x += r1v.x; v1.y += r1v.y;
            }
            *(float2*)(C + i0) = v0;
            *(float2*)(C + i1) = v1;
        }
    }
    #undef LOAD_BUF
}

// ---------------------------------------------------------------------------
// mix: xmix fp32 + bf16 hi/lo split fused
// ---------------------------------------------------------------------------
__global__ void mix_split_kernel(const float* __restrict__ x,
                                 const float* __restrict__ glin,
                                 float* __restrict__ xmix,
                                 __nv_bfloat16* __restrict__ oh,
                                 __nv_bfloat16* __restrict__ ol)
{
    const size_t i = (size_t)blockIdx.x * blockDim.x + threadIdx.x;
    const int row = (int)(i >> 8);
    const int t = row & (T_ - 1);
    float4 xv = *(const float4*)(x + i * 4);
    float4 gv = *(const float4*)(glin + i * 4);
    float4 pv = make_float4(0.f, 0.f, 0.f, 0.f);
    if (t > 0) pv = *(const float4*)(x + (i - 256) * 4);
    float o[4]; float g;
    g = 1.f / (1.f + __expf(-gv.x)); o[0] = (1.f - g) * xv.x + g * pv.x;
    g = 1.f / (1.f + __expf(-gv.y)); o[1] = (1.f - g) * xv.y + g * pv.y;
    g = 1.f / (1.f + __expf(-gv.z)); o[2] = (1.f - g) * xv.z + g * pv.z;
    g = 1.f / (1.f + __expf(-gv.w)); o[3] = (1.f - g) * xv.w + g * pv.w;
    *(float4*)(xmix + i * 4) = make_float4(o[0], o[1], o[2], o[3]);
    __nv_bfloat16 hb[4], lb[4];
    #pragma unroll
    for (int j = 0; j < 4; j++) {
        hb[j] = __float2bfloat16(o[j]);
        lb[j] = __float2bfloat16(o[j] - __bfloat162float(hb[j]));
    }
    *(uint2*)(oh + i * 4) = *(uint2*)hb;
    *(uint2*)(ol + i * 4) = *(uint2*)lb;
}

// ---------------------------------------------------------------------------
// RMSNorm fused with bf16 hi/lo split output
// ---------------------------------------------------------------------------
__global__ __launch_bounds__(256) void rmsnorm_split_kernel(
    const float* __restrict__ x, const float* __restrict__ w,
    __nv_bfloat16* __restrict__ oh, __nv_bfloat16* __restrict__ ol)
{
    const int row = blockIdx.x;
    const int tid = threadIdx.x;
    const float* xr = x + (size_t)row * D_;
    float4 v = *(const float4*)(xr + tid * 4);
    float s = v.x * v.x + v.y * v.y + v.z * v.z + v.w * v.w;
    #pragma unroll
    for (int m = 16; m > 0; m >>= 1) s += __shfl_xor_sync(0xffffffffu, s, m);
    __shared__ float red[8];
    if ((tid & 31) == 0) red[tid >> 5] = s;
    __syncthreads();
    if (tid < 32) {
        float t = (tid < 8) ? red[tid] : 0.f;
        #pragma unroll
        for (int m = 4; m > 0; m >>= 1) t += __shfl_xor_sync(0xffffffffu, t, m);
        if (tid == 0) red[0] = t;
    }
    __syncthreads();
    const float inv = rsqrtf(red[0] / (float)D_ + EPS_);
    float4 wv = *(const float4*)(w + tid * 4);
    float o[4] = { v.x * inv * wv.x, v.y * inv * wv.y,
                   v.z * inv * wv.z, v.w * inv * wv.w };
    __nv_bfloat16 hb[4], lb[4];
    #pragma unroll
    for (int j = 0; j < 4; j++) {
        hb[j] = __float2bfloat16(o[j]);
        lb[j] = __float2bfloat16(o[j] - __bfloat162float(hb[j]));
    }
    const size_t idx = (size_t)row * D_ + tid * 4;
    *(uint2*)(oh + idx) = *(uint2*)hb;
    *(uint2*)(ol + idx) = *(uint2*)lb;
}

// ---------------------------------------------------------------------------
// 3-phase cumsum
// ---------------------------------------------------------------------------
__global__ void cumsumA(const float* __restrict__ dd, float* __restrict__ cs)
{
    const int c = threadIdx.x;
    const int blk = blockIdx.x;
    const int b = blk >> 4, ch = blk & 15;
    size_t base = ((size_t)b * T_ + ch * 128) * 256 + c;
    float s = 0.f;
    #pragma unroll 8
    for (int t = 0; t < 128; t++) { s += dd[base]; base += 256; }
    cs[(size_t)blk * 256 + c] = s;
}
__global__ void cumsumB(float* __restrict__ cs)
{
    const int c = threadIdx.x;
    const int b = blockIdx.x;
    float run = 0.f;
    #pragma unroll
    for (int ch = 0; ch < 16; ch++) {
        size_t i = ((size_t)b * 16 + ch) * 256 + c;
        float t = cs[i];
        cs[i] = run;
        run += t;
    }
}
__global__ void cumsumC(float* __restrict__ dd, const float* __restrict__ cs)
{
    const int c = threadIdx.x;
    const int blk = blockIdx.x;
    const int b = blk >> 4, ch = blk & 15;
    float acc = cs[(size_t)blk * 256 + c];
    size_t base = ((size_t)b * T_ + ch * 128) * 256 + c;
    #pragma unroll 8
    for (int t = 0; t < 128; t++) { acc += dd[base]; dd[base] = acc; base += 256; }
}

// ---------------------------------------------------------------------------
// q/k head rmsnorm + hybrid rope + head-major scatter
// ---------------------------------------------------------------------------
__global__ __launch_bounds__(256) void qkv_transform_kernel(
    const float* __restrict__ qkv, const float* __restrict__ ddcum,
    const float* __restrict__ rc, const float* __restrict__ rs,
    const float* __restrict__ qnw, const float* __restrict__ knw,
    const float* __restrict__ qpb, const float* __restrict__ kpb,
    float* __restrict__ qt, float* __restrict__ kt, float* __restrict__ vt)
{
    const int w = blockIdx.x * 8 + (threadIdx.x >> 5);
    const int lane = threadIdx.x & 31;
    const int b = w >> 15;
    const int rem = w & 32767;
    const int t = rem >> 4;
    const int h = rem & 15;

    const size_t base = ((size_t)(b * T_ + t) * 3) * D_ + h * DH_;
    float q0 = qkv[base + lane],          q1 = qkv[base + 32 + lane];
    float k0 = qkv[base + D_ + lane],     k1 = qkv[base + D_ + 32 + lane];
    float v0 = qkv[base + 2 * D_ + lane], v1 = qkv[base + 2 * D_ + 32 + lane];

    float sq = q0 * q0 + q1 * q1;
    float sk = k0 * k0 + k1 * k1;
    #pragma unroll
    for (int m = 16; m > 0; m >>= 1) {
        sq += __shfl_xor_sync(0xffffffffu, sq, m);
        sk += __shfl_xor_sync(0xffffffffu, sk, m);
    }
    const float rq = rsqrtf(sq / 64.f + EPS_);
    const float rk = rsqrtf(sk / 64.f + EPS_);
    q0 *= rq * qnw[lane] * qpb[lane];
    q1 *= rq * qnw[lane + 32] * qpb[lane + 32];
    k0 *= rk * knw[lane] * kpb[lane];
    k1 *= rk * knw[lane + 32] * kpb[lane + 32];

    const int j = lane & 15;
    const float c = rc[t * 32 + j], s = rs[t * 32 + j];
    const float ang = ddcum[((size_t)(b * T_ + t)) * 256 + h * 16 + j];
    float s2, c2;
    sincosf(ang, &s2, &c2);

    const float qp0 = __shfl_xor_sync(0xffffffffu, q0, 16);
    const float qp1 = __shfl_xor_sync(0xffffffffu, q1, 16);
    const float kp0 = __shfl_xor_sync(0xffffffffu, k0, 16);
    const float kp1 = __shfl_xor_sync(0xffffffffu, k1, 16);
    float oq0, oq1, ok0, ok1;
    if (lane < 16) {
        oq0 = q0 * c - qp0 * s;  oq1 = q1 * c2 - qp1 * s2;
        ok0 = k0 * c - kp0 * s;  ok1 = k1 * c2 - kp1 * s2;
    } else {
        oq0 = q0 * c + qp0 * s;  oq1 = q1 * c2 + qp1 * s2;
        ok0 = k0 * c + kp0 * s;  ok1 = k1 * c2 + kp1 * s2;
    }

    const size_t ob = ((size_t)(b * NH_ + h) * T_ + t) * DH_;
    qt[ob + lane] = oq0;  qt[ob + 32 + lane] = oq1;
    kt[ob + lane] = ok0;  kt[ob + 32 + lane] = ok1;
    vt[ob + lane] = v0;   vt[ob + 32 + lane] = v1;
}

// ---------------------------------------------------------------------------
// Flash attention (tf32 mma, validated R4) -> bf16 split output
// ---------------------------------------------------------------------------
#define KS_OFF 0
#define VS_OFF (64 * 72)
#define PS_OFF (2 * 64 * 72)
#define FSMEM ((2 * 64 * 72 + 128 * 68) * 4)

__global__ __launch_bounds__(256, 1) void flash_tc(
    const float* __restrict__ qt, const float* __restrict__ kt,
    const float* __restrict__ vt,
    __nv_bfloat16* __restrict__ yh, __nv_bfloat16* __restrict__ yl)
{
    extern __shared__ uint32_t fsm[];
    uint32_t* Ks = fsm + KS_OFF;
    uint32_t* Vs = fsm + VS_OFF;
    uint32_t* Ps = fsm + PS_OFF;

    const int tid = threadIdx.x, lane = tid & 31, w = tid >> 5;
    const int bx = blockIdx.x, bh = blockIdx.y;
    const int b = bh >> 4, h = bh & 15;
    const int m0 = bx * 128;

    const float* Qb = qt + (size_t)bh * T_ * DH_;
    const float* Kb = kt + (size_t)bh * T_ * DH_;
    const float* Vb = vt + (size_t)bh * T_ * DH_;

    const int r1 = m0 + w * 16 + (lane >> 2);
    uint32_t qf[8][4];
    {
        const float* q1 = Qb + (size_t)r1 * DH_;
        const float* q2 = q1 + 8 * DH_;
        #pragma unroll
        for (int k8 = 0; k8 < 8; k8++) {
            const int c = k8 * 8 + (lane & 3);
            qf[k8][0] = f2tf(q1[c] * 0.125f);
            qf[k8][1] = f2tf(q2[c] * 0.125f);
            qf[k8][2] = f2tf(q1[c + 4] * 0.125f);
            qf[k8][3] = f2tf(q2[c + 4] * 0.125f);
        }
    }

    float mi[2] = { -1e30f, -1e30f }, li[2] = { 0.f, 0.f };
    float O[8][4] = {};

    const int ntiles = 2 * bx + 2;
    for (int nt = 0; nt < ntiles; nt++) {
        const int n0 = nt * 64;
        __syncthreads();
        {
            const int key = tid >> 2, db = (tid & 3) * 16;
            const float* kp = Kb + (size_t)(n0 + key) * DH_ + db;
            const float* vp = Vb + (size_t)(n0 + key) * DH_ + db;
            #pragma unroll
            for (int i = 0; i < 16; i += 4) {
                float4 kv = *(const float4*)(kp + i);
                Ks[(db + i + 0) * 72 + key] = f2tf(kv.x);
                Ks[(db + i + 1) * 72 + key] = f2tf(kv.y);
                Ks[(db + i + 2) * 72 + key] = f2tf(kv.z);
                Ks[(db + i + 3) * 72 + key] = f2tf(kv.w);
                float4 vv = *(const float4*)(vp + i);
                uint4 vo;
                vo.x = f2tf(vv.x); vo.y = f2tf(vv.y);
                vo.z = f2tf(vv.z); vo.w = f2tf(vv.w);
                *(uint4*)&Vs[key * 72 + db + i] = vo;
            }
        }
        __syncthreads();

        float S[8][4] = {};
        #pragma unroll
        for (int k8 = 0; k8 < 8; k8++) {
            const uint32_t* kr0 = &Ks[(k8 * 8 + (lane & 3)) * 72 + (lane >> 2)];
            const uint32_t* kr1 = kr0 + 4 * 72;
            #pragma unroll
            for (int n8 = 0; n8 < 8; n8++) {
                MMATF32(S[n8], qf[k8], kr0[n8 * 8], kr1[n8 * 8]);
            }
        }
        if (nt >= 2 * bx) {
            #pragma unroll
            for (int n8 = 0; n8 < 8; n8++) {
                const int cb = n0 + n8 * 8 + 2 * (lane & 3);
                if (cb     > r1)     S[n8][0] = -1e30f;
                if (cb + 1 > r1)     S[n8][1] = -1e30f;
                if (cb     > r1 + 8) S[n8][2] = -1e30f;
                if (cb + 1 > r1 + 8) S[n8][3] = -1e30f;
            }
        }
        #pragma unroll
        for (int half = 0; half < 2; half++) {
            float mx = -1e30f;
            #pragma unroll
            for (int n8 = 0; n8 < 8; n8++)
                mx = fmaxf(mx, fmaxf(S[n8][half * 2], S[n8][half * 2 + 1]));
            mx = fmaxf(mx, __shfl_xor_sync(0xffffffffu, mx, 1));
            mx = fmaxf(mx, __shfl_xor_sync(0xffffffffu, mx, 2));
            const float mnew = fmaxf(mi[half], mx);
            const float corr = __expf(mi[half] - mnew);
            float rsum = 0.f;
            #pragma unroll
            for (int n8 = 0; n8 < 8; n8++) {
                float e0 = __expf(S[n8][half * 2]     - mnew);
                float e1 = __expf(S[n8][half * 2 + 1] - mnew);
                S[n8][half * 2] = e0; S[n8][half * 2 + 1] = e1;
                rsum += e0 + e1;
            }
            rsum += __shfl_xor_sync(0xffffffffu, rsum, 1);
            rsum += __shfl_xor_sync(0xffffffffu, rsum, 2);
            li[half] = li[half] * corr + rsum;
            mi[half] = mnew;
            #pragma unroll
            for (int n8 = 0; n8 < 8; n8++) {
                O[n8][half * 2]     *= corr;
                O[n8][half * 2 + 1] *= corr;
            }
        }
        {
            const int pr = w * 16 + (lane >> 2);
            #pragma unroll
            for (int n8 = 0; n8 < 8; n8++) {
                const int pc = n8 * 8 + 2 * (lane & 3);
                uint2 p0, p1;
                p0.x = f2tf(S[n8][0]); p0.y = f2tf(S[n8][1]);
                p1.x = f2tf(S[n8][2]); p1.y = f2tf(S[n8][3]);
                *(uint2*)&Ps[pr * 68 + pc]       = p0;
                *(uint2*)&Ps[(pr + 8) * 68 + pc] = p1;
            }
        }
        __syncwarp();
        #pragma unroll
        for (int k8 = 0; k8 < 8; k8++) {
            uint32_t a[4];
            const int pr = w * 16 + (lane >> 2);
            const int pc = k8 * 8 + (lane & 3);
            a[0] = Ps[pr * 68 + pc];
            a[1] = Ps[(pr + 8) * 68 + pc];
            a[2] = Ps[pr * 68 + pc + 4];
            a[3] = Ps[(pr + 8) * 68 + pc + 4];
            const uint32_t* vr0 = &Vs[(k8 * 8 + (lane & 3)) * 72 + (lane >> 2)];
            const uint32_t* vr1 = vr0 + 4 * 72;
            #pragma unroll
            for (int n8 = 0; n8 < 8; n8++) {
                MMATF32(O[n8], a, vr0[n8 * 8], vr1[n8 * 8]);
            }
        }
    }

    const float inv0 = 1.f / li[0], inv1 = 1.f / li[1];
    const size_t o1 = ((size_t)(b * T_ + r1)) * D_ + h * DH_ + 2 * (lane & 3);
    const size_t o2 = o1 + 8 * D_;
    #pragma unroll
    for (int n8 = 0; n8 < 8; n8++) {
        float v0 = O[n8][0] * inv0, v1 = O[n8][1] * inv0;
        float v2 = O[n8][2] * inv1, v3 = O[n8][3] * inv1;
        __nv_bfloat162 h0, h1, l0, l1;
        h0.x = __float2bfloat16(v0); h0.y = __float2bfloat16(v1);
        h1.x = __float2bfloat16(v2); h1.y = __float2bfloat16(v3);
        l0.x = __float2bfloat16(v0 - __bfloat162float(h0.x));
        l0.y = __float2bfloat16(v1 - __bfloat162float(h0.y));
        l1.x = __float2bfloat16(v2 - __bfloat162float(h1.x));
        l1.y = __float2bfloat16(v3 - __bfloat162float(h1.y));
        *(__nv_bfloat162*)(yh + o1 + n8 * 8) = h0;
        *(__nv_bfloat162*)(yh + o2 + n8 * 8) = h1;
        *(__nv_bfloat162*)(yl + o1 + n8 * 8) = l0;
        *(__nv_bfloat162*)(yl + o2 + n8 * 8) = l1;
    }
}

// ---------------------------------------------------------------------------
// act = silu(gate)*up from combined [M, 2*FFNP] buffer -> bf16 split [M, FFNP]
// ---------------------------------------------------------------------------
__global__ void act_split_kernel(const float* __restrict__ gu,
                                 __nv_bfloat16* __restrict__ oh,
                                 __nv_bfloat16* __restrict__ ol)
{
    const size_t idx4 = (size_t)blockIdx.x * blockDim.x + threadIdx.x;
    const int row = (int)(idx4 / (FFNP / 4));
    const int c = (int)(idx4 % (FFNP / 4)) * 4;
    const float* gp = gu + (size_t)row * (2 * FFNP) + c;
    float4 g = *(const float4*)gp;
    float4 u = *(const float4*)(gp + FFNP);
    float o[4];
    o[0] = g.x / (1.f + __expf(-g.x)) * u.x;
    o[1] = g.y / (1.f + __expf(-g.y)) * u.y;
    o[2] = g.z / (1.f + __expf(-g.z)) * u.z;
    o[3] = g.w / (1.f + __expf(-g.w)) * u.w;
    __nv_bfloat16 hb[4], lb[4];
    #pragma unroll
    for (int j = 0; j < 4; j++) {
        hb[j] = __float2bfloat16(o[j]);
        lb[j] = __float2bfloat16(o[j] - __bfloat162float(hb[j]));
    }
    const size_t oi = (size_t)row * FFNP + c;
    *(uint2*)(oh + oi) = *(uint2*)hb;
    *(uint2*)(ol + oi) = *(uint2*)lb;
}

// ---------------------------------------------------------------------------
// Launch
// ---------------------------------------------------------------------------
static inline int cdiv(long long a, long long b) { return (int)((a + b - 1) / b); }

extern "C" void kernel_launch(void* const* d_in, const int* in_sizes, int n_in,
                              void* d_out, int out_size)
{
    const float* x     = (const float*)d_in[0];
    const float* rc    = (const float*)d_in[1];
    const float* rs    = (const float*)d_in[2];
    const float* lerpw = (const float*)d_in[3];
    const float* lerpb = (const float*)d_in[4];
    const float* anw   = (const float*)d_in[5];
    const float* wqkv  = (const float*)d_in[6];
    const float* qnw   = (const float*)d_in[7];
    const float* knw   = (const float*)d_in[8];
    const float* qpb   = (const float*)d_in[9];
    const float* kpb   = (const float*)d_in[10];
    const float* ddw   = (const float*)d_in[11];
    const float* ddb   = (const float*)d_in[12];
    const float* wo    = (const float*)d_in[13];
    const float* mnw   = (const float*)d_in[14];
    const float* gw    = (const float*)d_in[15];
    const float* uw    = (const float*)d_in[16];
    const float* dw    = (const float*)d_in[17];
    float* out = (float*)d_out;

    float *glin, *xmix, *qkv, *dd, *cs, *qt, *kt, *vt, *x2, *gu;
    __nv_bfloat16 *ah, *al, *wh, *wl;
    cudaGetSymbolAddress((void**)&glin, s_glin);
    cudaGetSymbolAddress((void**)&xmix, s_xmix);
    cudaGetSymbolAddress((void**)&qkv,  s_qkv);
    cudaGetSymbolAddress((void**)&dd,   s_dd);
    cudaGetSymbolAddress((void**)&cs,   s_csum);
    cudaGetSymbolAddress((void**)&qt,   s_qt);
    cudaGetSymbolAddress((void**)&kt,   s_kt);
    cudaGetSymbolAddress((void**)&vt,   s_vt);
    cudaGetSymbolAddress((void**)&x2,   s_x2);
    cudaGetSymbolAddress((void**)&gu,   s_gu);
    cudaGetSymbolAddress((void**)&ah,   g_ah);
    cudaGetSymbolAddress((void**)&al,   g_al);
    cudaGetSymbolAddress((void**)&wh,   g_wh);
    cudaGetSymbolAddress((void**)&wl,   g_wl);

    cudaFuncSetAttribute(mma_gemm,
                         cudaFuncAttributeMaxDynamicSharedMemorySize, 3 * BUFB);
    cudaFuncSetAttribute(flash_tc,
                         cudaFuncAttributeMaxDynamicSharedMemorySize, FSMEM);

    const dim3 blk(256);
    const int GSM = 3 * BUFB;   // 122880

    #define CONV(src, dh, dl, r, c, rp, cp) \
        convsplit<<<cdiv((long long)(rp) * (cp), 256), blk>>>(src, dh, dl, r, c, rp, cp)

    // 1. glin = x @ lerp_w^T + lerp_b
    CONV(x, ah, al, M_, D_, M_, D_);
    CONV(lerpw, wh, wl, D_, D_, D_, D_);
    mma_gemm<<<dim3(8, 32), blk, GSM>>>(ah, al, wh, wl, lerpb, nullptr, glin, D_, 32, D_, 1);
    // 2. xmix (fp32 + bf16 split)
    mix_split_kernel<<<(M_ * D_ / 4) / 256, blk>>>(x, glin, xmix, ah, al);
    // 3. dd = xmix @ dd_w^T + dd_b
    CONV(ddw, wh, wl, 256, D_, 256, D_);
    mma_gemm<<<dim3(2, 32), blk, GSM>>>(ah, al, wh, wl, ddb, nullptr, dd, D_, 32, 256, 1);
    // 4. cumsum along T
    cumsumA<<<B_ * 16, blk>>>(dd, cs);
    cumsumB<<<B_, blk>>>(cs);
    cumsumC<<<B_ * 16, blk>>>(dd, cs);
    // 5. h = rmsnorm(xmix) -> bf16 split
    rmsnorm_split_kernel<<<M_, blk>>>(xmix, anw, ah, al);
    // 6. qkv = h @ w_qkv^T
    CONV(wqkv, wh, wl, 3 * D_, D_, 3 * D_, D_);
    mma_gemm<<<dim3(24, 32), blk, GSM>>>(ah, al, wh, wl, nullptr, nullptr, qkv, D_, 32, 3 * D_, 0);
    // 7. q/k transform
    qkv_transform_kernel<<<(B_ * T_ * NH_) / 8, blk>>>(qkv, dd, rc, rs, qnw, knw,
                                                       qpb, kpb, qt, kt, vt);
    // 8. flash attention (tf32) -> y bf16 split
    flash_tc<<<dim3(T_ / 128, B_ * NH_), blk, FSMEM>>>(qt, kt, vt, ah, al);
    // 9. x2 = xmix + y @ w_o^T
    CONV(wo, wh, wl, D_, D_, D_, D_);
    mma_gemm<<<dim3(8, 32), blk, GSM>>>(ah, al, wh, wl, nullptr, xmix, x2, D_, 32, D_, 2);
    // 10. h = rmsnorm(x2) -> bf16 split
    rmsnorm_split_kernel<<<M_, blk>>>(x2, mnw, ah, al);
    // 11. combined gate|up GEMM: N = 2*FFNP = 5632
    CONV(gw, wh, wl, FFN_, D_, FFNP, D_);
    convsplit<<<cdiv((long long)FFNP * D_, 256), blk>>>(uw, wh + (size_t)FFNP * D_,
                                                        wl + (size_t)FFNP * D_,
                                                        FFN_, D_, FFNP, D_);
    mma_gemm<<<dim3(44, 32), blk, GSM>>>(ah, al, wh, wl, nullptr, nullptr, gu, D_, 32, 2 * FFNP, 0);
    // 12. act = silu(gate)*up -> bf16 split
    act_split_kernel<<<(M_ * FFNP / 4) / 256, blk>>>(gu, ah, al);
    // 13. out = x2 + act @ down_w^T
    CONV(dw, wh, wl, D_, FFN_, D_, FFNP);
    mma_gemm<<<dim3(8, 32), blk, GSM>>>(ah, al, wh, wl, nullptr, x2, out, FFNP, 88, D_, 2);
}

// round 7
// speedup vs baseline: 1.5223x; 1.2520x over previous
#include <cuda_runtime.h>
#include <cuda_bf16.h>
#include <cuda_fp16.h>
#include <math.h>
#include <stdint.h>

// ---------------------------------------------------------------------------
// Problem constants
// ---------------------------------------------------------------------------
#define B_   2
#define T_   2048
#define D_   1024
#define NH_  16
#define DH_  64
#define FFN_ 2736
#define FFNP 2816
#define M_   (B_ * T_)
#define EPS_ 1e-6f

// ---------------------------------------------------------------------------
// PTX helpers (arch-generic, sm_80+)
// ---------------------------------------------------------------------------
__device__ __forceinline__ uint32_t smem_u32(const void* p) {
    uint32_t a;
    asm("{ .reg .u64 t; cvta.to.shared.u64 t, %1; cvt.u32.u64 %0, t; }"
        : "=r"(a) : "l"(p));
    return a;
}
#define CP_ASYNC16(dst, src) \
    asm volatile("cp.async.cg.shared.global [%0], [%1], 16;" :: "r"(dst), "l"(src))
#define CP_COMMIT() asm volatile("cp.async.commit_group;" ::: "memory")
#define CP_WAIT0()  asm volatile("cp.async.wait_group 0;" ::: "memory")
#define CP_WAIT1()  asm volatile("cp.async.wait_group 1;" ::: "memory")
#define LDSM_X4(r0, r1, r2, r3, addr) \
    asm volatile("ldmatrix.sync.aligned.m8n8.x4.shared.b16 {%0,%1,%2,%3}, [%4];" \
                 : "=r"(r0), "=r"(r1), "=r"(r2), "=r"(r3) : "r"(addr))
#define MMA16816(d, a, b0, b1) \
    asm volatile("mma.sync.aligned.m16n8k16.row.col.f32.bf16.bf16.f32 " \
                 "{%0,%1,%2,%3},{%4,%5,%6,%7},{%8,%9},{%0,%1,%2,%3};" \
                 : "+f"((d)[0]), "+f"((d)[1]), "+f"((d)[2]), "+f"((d)[3]) \
                 : "r"((a)[0]), "r"((a)[1]), "r"((a)[2]), "r"((a)[3]), \
                   "r"(b0), "r"(b1))
#define MMAH16816(d, a, b0, b1) \
    asm volatile("mma.sync.aligned.m16n8k16.row.col.f32.f16.f16.f32 " \
                 "{%0,%1,%2,%3},{%4,%5,%6,%7},{%8,%9},{%0,%1,%2,%3};" \
                 : "+f"((d)[0]), "+f"((d)[1]), "+f"((d)[2]), "+f"((d)[3]) \
                 : "r"((a)[0]), "r"((a)[1]), "r"((a)[2]), "r"((a)[3]), \
                   "r"(b0), "r"(b1))
#define MMATF32(d, a, b0, b1) \
    asm volatile("mma.sync.aligned.m16n8k8.row.col.f32.tf32.tf32.f32 " \
                 "{%0,%1,%2,%3},{%4,%5,%6,%7},{%8,%9},{%0,%1,%2,%3};" \
                 : "+f"((d)[0]), "+f"((d)[1]), "+f"((d)[2]), "+f"((d)[3]) \
                 : "r"((a)[0]), "r"((a)[1]), "r"((a)[2]), "r"((a)[3]), \
                   "r"(b0), "r"(b1))
__device__ __forceinline__ uint32_t f2tf(float f) {
    uint32_t r;
    asm("cvt.rna.tf32.f32 %0, %1;" : "=r"(r) : "f"(f));
    return r;
}

// ---------------------------------------------------------------------------
// Device scratch
// ---------------------------------------------------------------------------
__device__ float s_glin[M_ * D_];
__device__ float s_xmix[M_ * D_];
__device__ float s_qkv [M_ * 3 * D_];
__device__ float s_dd  [M_ * NH_ * 16];
__device__ float s_csum[B_ * 16 * 256];
__device__ float s_qt  [B_ * NH_ * T_ * DH_];
__device__ float s_kt  [B_ * NH_ * T_ * DH_];
__device__ float s_vt  [B_ * NH_ * T_ * DH_];
__device__ float s_x2  [M_ * D_];
__device__ float s_gu  [(size_t)M_ * 2 * FFNP];     // gate | up combined
// bf16 split buffers (dd path only)
__device__ __nv_bfloat16 g_ah[(size_t)M_ * D_];
__device__ __nv_bfloat16 g_al[(size_t)M_ * D_];
__device__ __nv_bfloat16 g_wh[256 * D_];
__device__ __nv_bfloat16 g_wl[256 * D_];
// fp16 buffers (main GEMM path)
__device__ __half g_af [(size_t)M_ * FFNP];
__device__ __half g_wfh[(size_t)2 * FFNP * D_];
__device__ __half g_wfl[(size_t)2 * FFNP * D_];

// ---------------------------------------------------------------------------
// conversions
// ---------------------------------------------------------------------------
__global__ void convsplit(const float* __restrict__ src,
                          __nv_bfloat16* __restrict__ h,
                          __nv_bfloat16* __restrict__ l,
                          int rows, int cols, int rows_pad, int cols_pad)
{
    size_t i = (size_t)blockIdx.x * blockDim.x + threadIdx.x;
    size_t total = (size_t)rows_pad * cols_pad;
    if (i >= total) return;
    int r = (int)(i / cols_pad);
    int c = (int)(i - (size_t)r * cols_pad);
    float v = (r < rows && c < cols) ? src[(size_t)r * cols + c] : 0.f;
    __nv_bfloat16 hi = __float2bfloat16(v);
    h[i] = hi;
    l[i] = __float2bfloat16(v - __bfloat162float(hi));
}

__global__ void conv_wsplith(const float* __restrict__ src,
                             __half* __restrict__ h, __half* __restrict__ l,
                             int rows, int cols, int rows_pad, int cols_pad)
{
    size_t i = (size_t)blockIdx.x * blockDim.x + threadIdx.x;
    size_t total = (size_t)rows_pad * cols_pad;
    if (i >= total) return;
    int r = (int)(i / cols_pad);
    int c = (int)(i - (size_t)r * cols_pad);
    float v = (r < rows && c < cols) ? src[(size_t)r * cols + c] : 0.f;
    __half hi = __float2half(v);
    h[i] = hi;
    l[i] = __float2half(v - __half2float(hi));
}

__global__ void conv_half(const float* __restrict__ src, __half* __restrict__ d)
{
    size_t i = ((size_t)blockIdx.x * blockDim.x + threadIdx.x) * 4;
    float4 v = *(const float4*)(src + i);
    __half hb[4] = { __float2half(v.x), __float2half(v.y),
                     __float2half(v.z), __float2half(v.w) };
    *(uint2*)(d + i) = *(uint2*)hb;
}

// ---------------------------------------------------------------------------
// fp16 GEMM (A single fp16, W split fp16): C = A @ W^T (+bias)(+res)
// CTA 128x128, BK=32, 8 warps, 3-stage cp.async pipeline, 1 barrier/iter.
// ---------------------------------------------------------------------------
#define MATB  10240                       // 128 rows * 80 B
#define BUFB  (4 * MATB)                  // bf16 stage (4 matrices)
#define BUFBH (3 * MATB)                  // fp16 stage (3 matrices)

__global__ __launch_bounds__(256, 1) void mma_gemm_h(
    const __half* __restrict__ Af,
    const __half* __restrict__ Wh, const __half* __restrict__ Wl,
    const float* __restrict__ bias, const float* __restrict__ res,
    float* __restrict__ C, int K, int NKB, int ldc, int mode)
{
    extern __shared__ char smem[];
    const uint32_t su = smem_u32(smem);
    const int tid = threadIdx.x;
    const int wid = tid >> 5, lane = tid & 31;
    const int wm = wid >> 2, wn = wid & 3;
    const int m0 = blockIdx.y * 128, n0 = blockIdx.x * 128;

    const uint32_t a_lrow = (uint32_t)(wm * 64 + (lane & 15)) * 80u + ((lane >> 4) * 16u);
    const uint32_t b_lrow = (uint32_t)(wn * 32 + ((lane >> 4) & 1) * 8 + (lane & 7)) * 80u
                          + (((lane >> 3) & 1) * 16u);

    float acc[4][4][4] = {};

    const int ch0 = tid * 2;
    #define LOAD_BUFH(kb, b) do {                                             \
        _Pragma("unroll")                                                     \
        for (int c = 0; c < 2; c++) {                                         \
            const int ch = ch0 + c;                                           \
            const int row = ch >> 2, sub = ch & 3;                            \
            const uint32_t dst = su + (b) * BUFBH + (uint32_t)row * 80u + sub * 16u; \
            const size_t asrc = (size_t)(m0 + row) * K + (kb) * 32 + sub * 8; \
            const size_t wsrc = (size_t)(n0 + row) * K + (kb) * 32 + sub * 8; \
            CP_ASYNC16(dst +        0, Af + asrc);                            \
            CP_ASYNC16(dst +     MATB, Wh + wsrc);                            \
            CP_ASYNC16(dst + 2 * MATB, Wl + wsrc);                            \
        }                                                                     \
    } while (0)

    LOAD_BUFH(0, 0);
    CP_COMMIT();
    LOAD_BUFH(1, 1);
    CP_COMMIT();

    int stage = 0;
    for (int kb = 0; kb < NKB; kb++) {
        if (kb + 1 < NKB) { CP_WAIT1(); } else { CP_WAIT0(); }
        __syncthreads();
        if (kb + 2 < NKB) {
            int ns = stage + 2; if (ns >= 3) ns -= 3;
            LOAD_BUFH(kb + 2, ns);
            CP_COMMIT();
        }

        const uint32_t sb = su + stage * BUFBH;
        #pragma unroll
        for (int ks = 0; ks < 2; ks++) {
            uint32_t af[4][4];
            uint32_t bh[2][4], bl[2][4];
            #pragma unroll
            for (int mt = 0; mt < 4; mt++) {
                const uint32_t ra = sb + a_lrow + (uint32_t)mt * 16u * 80u + ks * 32u;
                LDSM_X4(af[mt][0], af[mt][1], af[mt][2], af[mt][3], ra);
            }
            #pragma unroll
            for (int np = 0; np < 2; np++) {
                const uint32_t rb = sb + MATB + b_lrow + (uint32_t)np * 16u * 80u + ks * 32u;
                LDSM_X4(bh[np][0], bh[np][1], bh[np][2], bh[np][3], rb);
                LDSM_X4(bl[np][0], bl[np][1], bl[np][2], bl[np][3], rb + MATB);
            }
            #pragma unroll
            for (int mt = 0; mt < 4; mt++)
                #pragma unroll
                for (int nt = 0; nt < 4; nt++) {
                    const int np = nt >> 1, o = (nt & 1) * 2;
                    MMAH16816(acc[mt][nt], af[mt], bh[np][o], bh[np][o + 1]);
                    MMAH16816(acc[mt][nt], af[mt], bl[np][o], bl[np][o + 1]);
                }
        }
        stage++; if (stage >= 3) stage = 0;
    }

    const int qrow = lane >> 2, qcol = (lane & 3) * 2;
    #pragma unroll
    for (int mt = 0; mt < 4; mt++) {
        const int r0 = m0 + wm * 64 + mt * 16 + qrow;
        #pragma unroll
        for (int nt = 0; nt < 4; nt++) {
            const int c0 = n0 + wn * 32 + nt * 8 + qcol;
            float bx = 0.f, by = 0.f;
            if (mode & 1) { bx = bias[c0]; by = bias[c0 + 1]; }
            float2 v0 = make_float2(acc[mt][nt][0] + bx, acc[mt][nt][1] + by);
            float2 v1 = make_float2(acc[mt][nt][2] + bx, acc[mt][nt][3] + by);
            const size_t i0 = (size_t)r0 * ldc + c0;
            const size_t i1 = (size_t)(r0 + 8) * ldc + c0;
            if (mode & 2) {
                float2 r0v = *(const float2*)(res + i0);
                float2 r1v = *(const float2*)(res + i1);
                v0.x += r0v.x; v0.y += r0v.y;
                v1.x += r1v.x; v1.y += r1v.y;
            }
            *(float2*)(C + i0) = v0;
            *(float2*)(C + i1) = v1;
        }
    }
    #undef LOAD_BUFH
}

// ---------------------------------------------------------------------------
// bf16 3-term split GEMM (dd projection only), 3-stage pipeline
// ---------------------------------------------------------------------------
__global__ __launch_bounds__(256, 1) void mma_gemm(
    const __nv_bfloat16* __restrict__ Ah, const __nv_bfloat16* __restrict__ Al,
    const __nv_bfloat16* __restrict__ Wh, const __nv_bfloat16* __restrict__ Wl,
    const float* __restrict__ bias, const float* __restrict__ res,
    float* __restrict__ C, int K, int NKB, int ldc, int mode)
{
    extern __shared__ char smem[];
    const uint32_t su = smem_u32(smem);
    const int tid = threadIdx.x;
    const int wid = tid >> 5, lane = tid & 31;
    const int wm = wid >> 2, wn = wid & 3;
    const int m0 = blockIdx.y * 128, n0 = blockIdx.x * 128;

    const uint32_t a_lrow = (uint32_t)(wm * 64 + (lane & 15)) * 80u + ((lane >> 4) * 16u);
    const uint32_t b_lrow = (uint32_t)(wn * 32 + ((lane >> 4) & 1) * 8 + (lane & 7)) * 80u
                          + (((lane >> 3) & 1) * 16u);

    float acc[4][4][4] = {};

    const int ch0 = tid * 2;
    #define LOAD_BUF(kb, b) do {                                              \
        _Pragma("unroll")                                                     \
        for (int c = 0; c < 2; c++) {                                         \
            const int ch = ch0 + c;                                           \
            const int row = ch >> 2, sub = ch & 3;                            \
            const uint32_t dst = su + (b) * BUFB + (uint32_t)row * 80u + sub * 16u; \
            const size_t asrc = (size_t)(m0 + row) * K + (kb) * 32 + sub * 8; \
            const size_t wsrc = (size_t)(n0 + row) * K + (kb) * 32 + sub * 8; \
            CP_ASYNC16(dst +        0, Ah + asrc);                            \
            CP_ASYNC16(dst +     MATB, Al + asrc);                            \
            CP_ASYNC16(dst + 2 * MATB, Wh + wsrc);                            \
            CP_ASYNC16(dst + 3 * MATB, Wl + wsrc);                            \
        }                                                                     \
    } while (0)

    LOAD_BUF(0, 0);
    CP_COMMIT();
    LOAD_BUF(1, 1);
    CP_COMMIT();

    int stage = 0;
    for (int kb = 0; kb < NKB; kb++) {
        if (kb + 1 < NKB) { CP_WAIT1(); } else { CP_WAIT0(); }
        __syncthreads();
        if (kb + 2 < NKB) {
            int ns = stage + 2; if (ns >= 3) ns -= 3;
            LOAD_BUF(kb + 2, ns);
            CP_COMMIT();
        }

        const uint32_t sb = su + stage * BUFB;
        #pragma unroll
        for (int ks = 0; ks < 2; ks++) {
            uint32_t ah[4][4], al[4][4];
            uint32_t bh[2][4], bl[2][4];
            #pragma unroll
            for (int mt = 0; mt < 4; mt++) {
                const uint32_t ra = sb + a_lrow + (uint32_t)mt * 16u * 80u + ks * 32u;
                LDSM_X4(ah[mt][0], ah[mt][1], ah[mt][2], ah[mt][3], ra);
                LDSM_X4(al[mt][0], al[mt][1], al[mt][2], al[mt][3], ra + MATB);
            }
            #pragma unroll
            for (int np = 0; np < 2; np++) {
                const uint32_t rb = sb + 2 * MATB + b_lrow + (uint32_t)np * 16u * 80u + ks * 32u;
                LDSM_X4(bh[np][0], bh[np][1], bh[np][2], bh[np][3], rb);
                LDSM_X4(bl[np][0], bl[np][1], bl[np][2], bl[np][3], rb + MATB);
            }
            #pragma unroll
            for (int mt = 0; mt < 4; mt++)
                #pragma unroll
                for (int nt = 0; nt < 4; nt++) {
                    const int np = nt >> 1, o = (nt & 1) * 2;
                    MMA16816(acc[mt][nt], ah[mt], bh[np][o], bh[np][o + 1]);
                    MMA16816(acc[mt][nt], ah[mt], bl[np][o], bl[np][o + 1]);
                    MMA16816(acc[mt][nt], al[mt], bh[np][o], bh[np][o + 1]);
                }
        }
        stage++; if (stage >= 3) stage = 0;
    }

    const int qrow = lane >> 2, qcol = (lane & 3) * 2;
    #pragma unroll
    for (int mt = 0; mt < 4; mt++) {
        const int r0 = m0 + wm * 64 + mt * 16 + qrow;
        #pragma unroll
        for (int nt = 0; nt < 4; nt++) {
            const int c0 = n0 + wn * 32 + nt * 8 + qcol;
            float bx = 0.f, by = 0.f;
            if (mode & 1) { bx = bias[c0]; by = bias[c0 + 1]; }
            float2 v0 = make_float2(acc[mt][nt][0] + bx, acc[mt][nt][1] + by);
            float2 v1 = make_float2(acc[mt][nt][2] + bx, acc[mt][nt][3] + by);
            const size_t i0 = (size_t)r0 * ldc + c0;
            const size_t i1 = (size_t)(r0 + 8) * ldc + c0;
            if (mode & 2) {
                float2 r0v = *(const float2*)(res + i0);
                float2 r1v = *(const float2*)(res + i1);
                v0.x += r0v.x; v0.y += r0v.y;
                v1.x += r1v.x; v1.y += r1v.y;
            }
            *(float2*)(C + i0) = v0;
            *(float2*)(C + i1) = v1;
        }
    }
    #undef LOAD_BUF
}

// ---------------------------------------------------------------------------
// mix: xmix fp32 + bf16 hi/lo split (dd GEMM input)
// ---------------------------------------------------------------------------
__global__ void mix_split_kernel(const float* __restrict__ x,
                                 const float* __restrict__ glin,
                                 float* __restrict__ xmix,
                                 __nv_bfloat16* __restrict__ oh,
                                 __nv_bfloat16* __restrict__ ol)
{
    const size_t i = (size_t)blockIdx.x * blockDim.x + threadIdx.x;
    const int row = (int)(i >> 8);
    const int t = row & (T_ - 1);
    float4 xv = *(const float4*)(x + i * 4);
    float4 gv = *(const float4*)(glin + i * 4);
    float4 pv = make_float4(0.f, 0.f, 0.f, 0.f);
    if (t > 0) pv = *(const float4*)(x + (i - 256) * 4);
    float o[4]; float g;
    g = 1.f / (1.f + __expf(-gv.x)); o[0] = (1.f - g) * xv.x + g * pv.x;
    g = 1.f / (1.f + __expf(-gv.y)); o[1] = (1.f - g) * xv.y + g * pv.y;
    g = 1.f / (1.f + __expf(-gv.z)); o[2] = (1.f - g) * xv.z + g * pv.z;
    g = 1.f / (1.f + __expf(-gv.w)); o[3] = (1.f - g) * xv.w + g * pv.w;
    *(float4*)(xmix + i * 4) = make_float4(o[0], o[1], o[2], o[3]);
    __nv_bfloat16 hb[4], lb[4];
    #pragma unroll
    for (int j = 0; j < 4; j++) {
        hb[j] = __float2bfloat16(o[j]);
        lb[j] = __float2bfloat16(o[j] - __bfloat162float(hb[j]));
    }
    *(uint2*)(oh + i * 4) = *(uint2*)hb;
    *(uint2*)(ol + i * 4) = *(uint2*)lb;
}

// ---------------------------------------------------------------------------
// RMSNorm -> single fp16 output
// ---------------------------------------------------------------------------
__global__ __launch_bounds__(256) void rmsnorm_half_kernel(
    const float* __restrict__ x, const float* __restrict__ w,
    __half* __restrict__ oh)
{
    const int row = blockIdx.x;
    const int tid = threadIdx.x;
    const float* xr = x + (size_t)row * D_;
    float4 v = *(const float4*)(xr + tid * 4);
    float s = v.x * v.x + v.y * v.y + v.z * v.z + v.w * v.w;
    #pragma unroll
    for (int m = 16; m > 0; m >>= 1) s += __shfl_xor_sync(0xffffffffu, s, m);
    __shared__ float red[8];
    if ((tid & 31) == 0) red[tid >> 5] = s;
    __syncthreads();
    if (tid < 32) {
        float t = (tid < 8) ? red[tid] : 0.f;
        #pragma unroll
        for (int m = 4; m > 0; m >>= 1) t += __shfl_xor_sync(0xffffffffu, t, m);
        if (tid == 0) red[0] = t;
    }
    __syncthreads();
    const float inv = rsqrtf(red[0] / (float)D_ + EPS_);
    float4 wv = *(const float4*)(w + tid * 4);
    __half hb[4] = { __float2half(v.x * inv * wv.x), __float2half(v.y * inv * wv.y),
                     __float2half(v.z * inv * wv.z), __float2half(v.w * inv * wv.w) };
    *(uint2*)(oh + (size_t)row * D_ + tid * 4) = *(uint2*)hb;
}

// ---------------------------------------------------------------------------
// 3-phase cumsum
// ---------------------------------------------------------------------------
__global__ void cumsumA(const float* __restrict__ dd, float* __restrict__ cs)
{
    const int c = threadIdx.x;
    const int blk = blockIdx.x;
    const int b = blk >> 4, ch = blk & 15;
    size_t base = ((size_t)b * T_ + ch * 128) * 256 + c;
    float s = 0.f;
    #pragma unroll 8
    for (int t = 0; t < 128; t++) { s += dd[base]; base += 256; }
    cs[(size_t)blk * 256 + c] = s;
}
__global__ void cumsumB(float* __restrict__ cs)
{
    const int c = threadIdx.x;
    const int b = blockIdx.x;
    float run = 0.f;
    #pragma unroll
    for (int ch = 0; ch < 16; ch++) {
        size_t i = ((size_t)b * 16 + ch) * 256 + c;
        float t = cs[i];
        cs[i] = run;
        run += t;
    }
}
__global__ void cumsumC(float* __restrict__ dd, const float* __restrict__ cs)
{
    const int c = threadIdx.x;
    const int blk = blockIdx.x;
    const int b = blk >> 4, ch = blk & 15;
    float acc = cs[(size_t)blk * 256 + c];
    size_t base = ((size_t)b * T_ + ch * 128) * 256 + c;
    #pragma unroll 8
    for (int t = 0; t < 128; t++) { acc += dd[base]; dd[base] = acc; base += 256; }
}

// ---------------------------------------------------------------------------
// q/k head rmsnorm + hybrid rope + head-major scatter
// ---------------------------------------------------------------------------
__global__ __launch_bounds__(256) void qkv_transform_kernel(
    const float* __restrict__ qkv, const float* __restrict__ ddcum,
    const float* __restrict__ rc, const float* __restrict__ rs,
    const float* __restrict__ qnw, const float* __restrict__ knw,
    const float* __restrict__ qpb, const float* __restrict__ kpb,
    float* __restrict__ qt, float* __restrict__ kt, float* __restrict__ vt)
{
    const int w = blockIdx.x * 8 + (threadIdx.x >> 5);
    const int lane = threadIdx.x & 31;
    const int b = w >> 15;
    const int rem = w & 32767;
    const int t = rem >> 4;
    const int h = rem & 15;

    const size_t base = ((size_t)(b * T_ + t) * 3) * D_ + h * DH_;
    float q0 = qkv[base + lane],          q1 = qkv[base + 32 + lane];
    float k0 = qkv[base + D_ + lane],     k1 = qkv[base + D_ + 32 + lane];
    float v0 = qkv[base + 2 * D_ + lane], v1 = qkv[base + 2 * D_ + 32 + lane];

    float sq = q0 * q0 + q1 * q1;
    float sk = k0 * k0 + k1 * k1;
    #pragma unroll
    for (int m = 16; m > 0; m >>= 1) {
        sq += __shfl_xor_sync(0xffffffffu, sq, m);
        sk += __shfl_xor_sync(0xffffffffu, sk, m);
    }
    const float rq = rsqrtf(sq / 64.f + EPS_);
    const float rk = rsqrtf(sk / 64.f + EPS_);
    q0 *= rq * qnw[lane] * qpb[lane];
    q1 *= rq * qnw[lane + 32] * qpb[lane + 32];
    k0 *= rk * knw[lane] * kpb[lane];
    k1 *= rk * knw[lane + 32] * kpb[lane + 32];

    const int j = lane & 15;
    const float c = rc[t * 32 + j], s = rs[t * 32 + j];
    const float ang = ddcum[((size_t)(b * T_ + t)) * 256 + h * 16 + j];
    float s2, c2;
    sincosf(ang, &s2, &c2);

    const float qp0 = __shfl_xor_sync(0xffffffffu, q0, 16);
    const float qp1 = __shfl_xor_sync(0xffffffffu, q1, 16);
    const float kp0 = __shfl_xor_sync(0xffffffffu, k0, 16);
    const float kp1 = __shfl_xor_sync(0xffffffffu, k1, 16);
    float oq0, oq1, ok0, ok1;
    if (lane < 16) {
        oq0 = q0 * c - qp0 * s;  oq1 = q1 * c2 - qp1 * s2;
        ok0 = k0 * c - kp0 * s;  ok1 = k1 * c2 - kp1 * s2;
    } else {
        oq0 = q0 * c + qp0 * s;  oq1 = q1 * c2 + qp1 * s2;
        ok0 = k0 * c + kp0 * s;  ok1 = k1 * c2 + kp1 * s2;
    }

    const size_t ob = ((size_t)(b * NH_ + h) * T_ + t) * DH_;
    qt[ob + lane] = oq0;  qt[ob + 32 + lane] = oq1;
    kt[ob + lane] = ok0;  kt[ob + 32 + lane] = ok1;
    vt[ob + lane] = v0;   vt[ob + 32 + lane] = v1;
}

// ---------------------------------------------------------------------------
// Flash attention (tf32 mma) -> single fp16 output; heavy tiles first
// ---------------------------------------------------------------------------
#define KS_OFF 0
#define VS_OFF (64 * 72)
#define PS_OFF (2 * 64 * 72)
#define FSMEM ((2 * 64 * 72 + 128 * 68) * 4)

__global__ __launch_bounds__(256, 1) void flash_tc(
    const float* __restrict__ qt, const float* __restrict__ kt,
    const float* __restrict__ vt, __half* __restrict__ yh)
{
    extern __shared__ uint32_t fsm[];
    uint32_t* Ks = fsm + KS_OFF;
    uint32_t* Vs = fsm + VS_OFF;
    uint32_t* Ps = fsm + PS_OFF;

    const int tid = threadIdx.x, lane = tid & 31, w = tid >> 5;
    const int bx = gridDim.x - 1 - blockIdx.x;     // heavy q-tiles first
    const int bh = blockIdx.y;
    const int b = bh >> 4, h = bh & 15;
    const int m0 = bx * 128;

    const float* Qb = qt + (size_t)bh * T_ * DH_;
    const float* Kb = kt + (size_t)bh * T_ * DH_;
    const float* Vb = vt + (size_t)bh * T_ * DH_;

    const int r1 = m0 + w * 16 + (lane >> 2);
    uint32_t qf[8][4];
    {
        const float* q1 = Qb + (size_t)r1 * DH_;
        const float* q2 = q1 + 8 * DH_;
        #pragma unroll
        for (int k8 = 0; k8 < 8; k8++) {
            const int c = k8 * 8 + (lane & 3);
            qf[k8][0] = f2tf(q1[c] * 0.125f);
            qf[k8][1] = f2tf(q2[c] * 0.125f);
            qf[k8][2] = f2tf(q1[c + 4] * 0.125f);
            qf[k8][3] = f2tf(q2[c + 4] * 0.125f);
        }
    }

    float mi[2] = { -1e30f, -1e30f }, li[2] = { 0.f, 0.f };
    float O[8][4] = {};

    const int ntiles = 2 * bx + 2;
    for (int nt = 0; nt < ntiles; nt++) {
        const int n0 = nt * 64;
        __syncthreads();
        {
            const int key = tid >> 2, db = (tid & 3) * 16;
            const float* kp = Kb + (size_t)(n0 + key) * DH_ + db;
            const float* vp = Vb + (size_t)(n0 + key) * DH_ + db;
            #pragma unroll
            for (int i = 0; i < 16; i += 4) {
                float4 kv = *(const float4*)(kp + i);
                Ks[(db + i + 0) * 72 + key] = f2tf(kv.x);
                Ks[(db + i + 1) * 72 + key] = f2tf(kv.y);
                Ks[(db + i + 2) * 72 + key] = f2tf(kv.z);
                Ks[(db + i + 3) * 72 + key] = f2tf(kv.w);
                float4 vv = *(const float4*)(vp + i);
                uint4 vo;
                vo.x = f2tf(vv.x); vo.y = f2tf(vv.y);
                vo.z = f2tf(vv.z); vo.w = f2tf(vv.w);
                *(uint4*)&Vs[key * 72 + db + i] = vo;
            }
        }
        __syncthreads();

        float S[8][4] = {};
        #pragma unroll
        for (int k8 = 0; k8 < 8; k8++) {
            const uint32_t* kr0 = &Ks[(k8 * 8 + (lane & 3)) * 72 + (lane >> 2)];
            const uint32_t* kr1 = kr0 + 4 * 72;
            #pragma unroll
            for (int n8 = 0; n8 < 8; n8++) {
                MMATF32(S[n8], qf[k8], kr0[n8 * 8], kr1[n8 * 8]);
            }
        }
        if (nt >= 2 * bx) {
            #pragma unroll
            for (int n8 = 0; n8 < 8; n8++) {
                const int cb = n0 + n8 * 8 + 2 * (lane & 3);
                if (cb     > r1)     S[n8][0] = -1e30f;
                if (cb + 1 > r1)     S[n8][1] = -1e30f;
                if (cb     > r1 + 8) S[n8][2] = -1e30f;
                if (cb + 1 > r1 + 8) S[n8][3] = -1e30f;
            }
        }
        #pragma unroll
        for (int half = 0; half < 2; half++) {
            float mx = -1e30f;
            #pragma unroll
            for (int n8 = 0; n8 < 8; n8++)
                mx = fmaxf(mx, fmaxf(S[n8][half * 2], S[n8][half * 2 + 1]));
            mx = fmaxf(mx, __shfl_xor_sync(0xffffffffu, mx, 1));
            mx = fmaxf(mx, __shfl_xor_sync(0xffffffffu, mx, 2));
            const float mnew = fmaxf(mi[half], mx);
            const float corr = __expf(mi[half] - mnew);
            float rsum = 0.f;
            #pragma unroll
            for (int n8 = 0; n8 < 8; n8++) {
                float e0 = __expf(S[n8][half * 2]     - mnew);
                float e1 = __expf(S[n8][half * 2 + 1] - mnew);
                S[n8][half * 2] = e0; S[n8][half * 2 + 1] = e1;
                rsum += e0 + e1;
            }
            rsum += __shfl_xor_sync(0xffffffffu, rsum, 1);
            rsum += __shfl_xor_sync(0xffffffffu, rsum, 2);
            li[half] = li[half] * corr + rsum;
            mi[half] = mnew;
            #pragma unroll
            for (int n8 = 0; n8 < 8; n8++) {
                O[n8][half * 2]     *= corr;
                O[n8][half * 2 + 1] *= corr;
            }
        }
        {
            const int pr = w * 16 + (lane >> 2);
            #pragma unroll
            for (int n8 = 0; n8 < 8; n8++) {
                const int pc = n8 * 8 + 2 * (lane & 3);
                uint2 p0, p1;
                p0.x = f2tf(S[n8][0]); p0.y = f2tf(S[n8][1]);
                p1.x = f2tf(S[n8][2]); p1.y = f2tf(S[n8][3]);
                *(uint2*)&Ps[pr * 68 + pc]       = p0;
                *(uint2*)&Ps[(pr + 8) * 68 + pc] = p1;
            }
        }
        __syncwarp();
        #pragma unroll
        for (int k8 = 0; k8 < 8; k8++) {
            uint32_t a[4];
            const int pr = w * 16 + (lane >> 2);
            const int pc = k8 * 8 + (lane & 3);
            a[0] = Ps[pr * 68 + pc];
            a[1] = Ps[(pr + 8) * 68 + pc];
            a[2] = Ps[pr * 68 + pc + 4];
            a[3] = Ps[(pr + 8) * 68 + pc + 4];
            const uint32_t* vr0 = &Vs[(k8 * 8 + (lane & 3)) * 72 + (lane >> 2)];
            const uint32_t* vr1 = vr0 + 4 * 72;
            #pragma unroll
            for (int n8 = 0; n8 < 8; n8++) {
                MMATF32(O[n8], a, vr0[n8 * 8], vr1[n8 * 8]);
            }
        }
    }

    const float inv0 = 1.f / li[0], inv1 = 1.f / li[1];
    const size_t o1 = ((size_t)(b * T_ + r1)) * D_ + h * DH_ + 2 * (lane & 3);
    const size_t o2 = o1 + 8 * D_;
    #pragma unroll
    for (int n8 = 0; n8 < 8; n8++) {
        __half2 h0, h1;
        h0.x = __float2half(O[n8][0] * inv0); h0.y = __float2half(O[n8][1] * inv0);
        h1.x = __float2half(O[n8][2] * inv1); h1.y = __float2half(O[n8][3] * inv1);
        *(__half2*)(yh + o1 + n8 * 8) = h0;
        *(__half2*)(yh + o2 + n8 * 8) = h1;
    }
}

// ---------------------------------------------------------------------------
// act = silu(gate)*up from combined [M, 2*FFNP] buffer -> fp16 [M, FFNP]
// ---------------------------------------------------------------------------
__global__ void act_half_kernel(const float* __restrict__ gu,
                                __half* __restrict__ oh)
{
    const size_t idx4 = (size_t)blockIdx.x * blockDim.x + threadIdx.x;
    const int row = (int)(idx4 / (FFNP / 4));
    const int c = (int)(idx4 % (FFNP / 4)) * 4;
    const float* gp = gu + (size_t)row * (2 * FFNP) + c;
    float4 g = *(const float4*)gp;
    float4 u = *(const float4*)(gp + FFNP);
    __half hb[4];
    hb[0] = __float2half(g.x / (1.f + __expf(-g.x)) * u.x);
    hb[1] = __float2half(g.y / (1.f + __expf(-g.y)) * u.y);
    hb[2] = __float2half(g.z / (1.f + __expf(-g.z)) * u.z);
    hb[3] = __float2half(g.w / (1.f + __expf(-g.w)) * u.w);
    *(uint2*)(oh + (size_t)row * FFNP + c) = *(uint2*)hb;
}

// ---------------------------------------------------------------------------
// Launch
// ---------------------------------------------------------------------------
static inline int cdiv(long long a, long long b) { return (int)((a + b - 1) / b); }

extern "C" void kernel_launch(void* const* d_in, const int* in_sizes, int n_in,
                              void* d_out, int out_size)
{
    const float* x     = (const float*)d_in[0];
    const float* rc    = (const float*)d_in[1];
    const float* rs    = (const float*)d_in[2];
    const float* lerpw = (const float*)d_in[3];
    const float* lerpb = (const float*)d_in[4];
    const float* anw   = (const float*)d_in[5];
    const float* wqkv  = (const float*)d_in[6];
    const float* qnw   = (const float*)d_in[7];
    const float* knw   = (const float*)d_in[8];
    const float* qpb   = (const float*)d_in[9];
    const float* kpb   = (const float*)d_in[10];
    const float* ddw   = (const float*)d_in[11];
    const float* ddb   = (const float*)d_in[12];
    const float* wo    = (const float*)d_in[13];
    const float* mnw   = (const float*)d_in[14];
    const float* gw    = (const float*)d_in[15];
    const float* uw    = (const float*)d_in[16];
    const float* dw    = (const float*)d_in[17];
    float* out = (float*)d_out;

    float *glin, *xmix, *qkv, *dd, *cs, *qt, *kt, *vt, *x2, *gu;
    __nv_bfloat16 *ah, *al, *wh, *wl;
    __half *af, *wfh, *wfl;
    cudaGetSymbolAddress((void**)&glin, s_glin);
    cudaGetSymbolAddress((void**)&xmix, s_xmix);
    cudaGetSymbolAddress((void**)&qkv,  s_qkv);
    cudaGetSymbolAddress((void**)&dd,   s_dd);
    cudaGetSymbolAddress((void**)&cs,   s_csum);
    cudaGetSymbolAddress((void**)&qt,   s_qt);
    cudaGetSymbolAddress((void**)&kt,   s_kt);
    cudaGetSymbolAddress((void**)&vt,   s_vt);
    cudaGetSymbolAddress((void**)&x2,   s_x2);
    cudaGetSymbolAddress((void**)&gu,   s_gu);
    cudaGetSymbolAddress((void**)&ah,   g_ah);
    cudaGetSymbolAddress((void**)&al,   g_al);
    cudaGetSymbolAddress((void**)&wh,   g_wh);
    cudaGetSymbolAddress((void**)&wl,   g_wl);
    cudaGetSymbolAddress((void**)&af,   g_af);
    cudaGetSymbolAddress((void**)&wfh,  g_wfh);
    cudaGetSymbolAddress((void**)&wfl,  g_wfl);

    cudaFuncSetAttribute(mma_gemm,
                         cudaFuncAttributeMaxDynamicSharedMemorySize, 3 * BUFB);
    cudaFuncSetAttribute(mma_gemm_h,
                         cudaFuncAttributeMaxDynamicSharedMemorySize, 3 * BUFBH);
    cudaFuncSetAttribute(flash_tc,
                         cudaFuncAttributeMaxDynamicSharedMemorySize, FSMEM);

    const dim3 blk(256);
    const int GSM  = 3 * BUFB;    // 122880
    const int GSMH = 3 * BUFBH;   // 92160

    #define CONVH(src, d, n) \
        conv_half<<<(int)(((long long)(n) / 4) / 256), blk>>>(src, d)
    #define CONVW(src, dh, dl, r, c, rp, cp) \
        conv_wsplith<<<cdiv((long long)(rp) * (cp), 256), blk>>>(src, dh, dl, r, c, rp, cp)

    // 1. glin = x @ lerp_w^T + lerp_b
    CONVH(x, af, (long long)M_ * D_);
    CONVW(lerpw, wfh, wfl, D_, D_, D_, D_);
    mma_gemm_h<<<dim3(8, 32), blk, GSMH>>>(af, wfh, wfl, lerpb, nullptr, glin, D_, 32, D_, 1);
    // 2. xmix (fp32 + bf16 split for dd)
    mix_split_kernel<<<(M_ * D_ / 4) / 256, blk>>>(x, glin, xmix, ah, al);
    // 3. dd = xmix @ dd_w^T + dd_b (bf16 3-term)
    convsplit<<<cdiv(256LL * D_, 256), blk>>>(ddw, wh, wl, 256, D_, 256, D_);
    mma_gemm<<<dim3(2, 32), blk, GSM>>>(ah, al, wh, wl, ddb, nullptr, dd, D_, 32, 256, 1);
    // 4. cumsum along T
    cumsumA<<<B_ * 16, blk>>>(dd, cs);
    cumsumB<<<B_, blk>>>(cs);
    cumsumC<<<B_ * 16, blk>>>(dd, cs);
    // 5. h = rmsnorm(xmix) -> fp16
    rmsnorm_half_kernel<<<M_, blk>>>(xmix, anw, af);
    // 6. qkv = h @ w_qkv^T
    CONVW(wqkv, wfh, wfl, 3 * D_, D_, 3 * D_, D_);
    mma_gemm_h<<<dim3(24, 32), blk, GSMH>>>(af, wfh, wfl, nullptr, nullptr, qkv, D_, 32, 3 * D_, 0);
    // 7. q/k transform
    qkv_transform_kernel<<<(B_ * T_ * NH_) / 8, blk>>>(qkv, dd, rc, rs, qnw, knw,
                                                       qpb, kpb, qt, kt, vt);
    // 8. flash attention (tf32) -> y fp16
    flash_tc<<<dim3(T_ / 128, B_ * NH_), blk, FSMEM>>>(qt, kt, vt, af);
    // 9. x2 = xmix + y @ w_o^T
    CONVW(wo, wfh, wfl, D_, D_, D_, D_);
    mma_gemm_h<<<dim3(8, 32), blk, GSMH>>>(af, wfh, wfl, nullptr, xmix, x2, D_, 32, D_, 2);
    // 10. h = rmsnorm(x2) -> fp16
    rmsnorm_half_kernel<<<M_, blk>>>(x2, mnw, af);
    // 11. combined gate|up GEMM: N = 2*FFNP = 5632
    CONVW(gw, wfh, wfl, FFN_, D_, FFNP, D_);
    conv_wsplith<<<cdiv((long long)FFNP * D_, 256), blk>>>(uw, wfh + (size_t)FFNP * D_,
                                                           wfl + (size_t)FFNP * D_,
                                                           FFN_, D_, FFNP, D_);
    mma_gemm_h<<<dim3(44, 32), blk, GSMH>>>(af, wfh, wfl, nullptr, nullptr, gu, D_, 32, 2 * FFNP, 0);
    // 12. act = silu(gate)*up -> fp16
    act_half_kernel<<<(M_ * FFNP / 4) / 256, blk>>>(gu, af);
    // 13. out = x2 + act @ down_w^T
    CONVW(dw, wfh, wfl, D_, FFN_, D_, FFNP);
    mma_gemm_h<<<dim3(8, 32), blk, GSMH>>>(af, wfh, wfl, nullptr, x2, out, FFNP, 88, D_, 2);
}

// round 8
// speedup vs baseline: 1.7600x; 1.1562x over previous
#include <cuda_runtime.h>
#include <cuda_bf16.h>
#include <cuda_fp16.h>
#include <math.h>
#include <stdint.h>

// ---------------------------------------------------------------------------
// Problem constants
// ---------------------------------------------------------------------------
#define B_   2
#define T_   2048
#define D_   1024
#define NH_  16
#define DH_  64
#define FFN_ 2736
#define FFNP 2816
#define M_   (B_ * T_)
#define EPS_ 1e-6f

// ---------------------------------------------------------------------------
// PTX helpers (arch-generic, sm_80+)
// ---------------------------------------------------------------------------
__device__ __forceinline__ uint32_t smem_u32(const void* p) {
    uint32_t a;
    asm("{ .reg .u64 t; cvta.to.shared.u64 t, %1; cvt.u32.u64 %0, t; }"
        : "=r"(a) : "l"(p));
    return a;
}
#define CP_ASYNC16(dst, src) \
    asm volatile("cp.async.cg.shared.global [%0], [%1], 16;" :: "r"(dst), "l"(src))
#define CP_COMMIT() asm volatile("cp.async.commit_group;" ::: "memory")
#define CP_WAIT0()  asm volatile("cp.async.wait_group 0;" ::: "memory")
#define CP_WAIT1()  asm volatile("cp.async.wait_group 1;" ::: "memory")
#define LDSM_X4(r0, r1, r2, r3, addr) \
    asm volatile("ldmatrix.sync.aligned.m8n8.x4.shared.b16 {%0,%1,%2,%3}, [%4];" \
                 : "=r"(r0), "=r"(r1), "=r"(r2), "=r"(r3) : "r"(addr))
#define MMA16816(d, a, b0, b1) \
    asm volatile("mma.sync.aligned.m16n8k16.row.col.f32.bf16.bf16.f32 " \
                 "{%0,%1,%2,%3},{%4,%5,%6,%7},{%8,%9},{%0,%1,%2,%3};" \
                 : "+f"((d)[0]), "+f"((d)[1]), "+f"((d)[2]), "+f"((d)[3]) \
                 : "r"((a)[0]), "r"((a)[1]), "r"((a)[2]), "r"((a)[3]), \
                   "r"(b0), "r"(b1))
#define MMAH16816(d, a, b0, b1) \
    asm volatile("mma.sync.aligned.m16n8k16.row.col.f32.f16.f16.f32 " \
                 "{%0,%1,%2,%3},{%4,%5,%6,%7},{%8,%9},{%0,%1,%2,%3};" \
                 : "+f"((d)[0]), "+f"((d)[1]), "+f"((d)[2]), "+f"((d)[3]) \
                 : "r"((a)[0]), "r"((a)[1]), "r"((a)[2]), "r"((a)[3]), \
                   "r"(b0), "r"(b1))
#define MMATF32(d, a, b0, b1) \
    asm volatile("mma.sync.aligned.m16n8k8.row.col.f32.tf32.tf32.f32 " \
                 "{%0,%1,%2,%3},{%4,%5,%6,%7},{%8,%9},{%0,%1,%2,%3};" \
                 : "+f"((d)[0]), "+f"((d)[1]), "+f"((d)[2]), "+f"((d)[3]) \
                 : "r"((a)[0]), "r"((a)[1]), "r"((a)[2]), "r"((a)[3]), \
                   "r"(b0), "r"(b1))
__device__ __forceinline__ uint32_t f2tf(float f) {
    uint32_t r;
    asm("cvt.rna.tf32.f32 %0, %1;" : "=r"(r) : "f"(f));
    return r;
}

// ---------------------------------------------------------------------------
// Device scratch
// ---------------------------------------------------------------------------
__device__ float s_glin[M_ * D_];
__device__ float s_xmix[M_ * D_];
__device__ float s_qkv [M_ * 3 * D_];
__device__ float s_dd  [M_ * NH_ * 16];
__device__ float s_csum[B_ * 16 * 256];
__device__ float s_qt  [B_ * NH_ * T_ * DH_];
__device__ float s_kt  [B_ * NH_ * T_ * DH_];
__device__ float s_vt  [B_ * NH_ * T_ * DH_];
__device__ float s_x2  [M_ * D_];
__device__ __half s_guh[(size_t)M_ * 2 * FFNP];     // gate | up combined (fp16)
// bf16 split buffers (dd path only)
__device__ __nv_bfloat16 g_ah[(size_t)M_ * D_];
__device__ __nv_bfloat16 g_al[(size_t)M_ * D_];
__device__ __nv_bfloat16 g_wh[256 * D_];
__device__ __nv_bfloat16 g_wl[256 * D_];
// fp16 buffers (main GEMM path)
__device__ __half g_af [(size_t)M_ * FFNP];
__device__ __half g_wfh[(size_t)2 * FFNP * D_];
__device__ __half g_wfl[(size_t)2 * FFNP * D_];

// ---------------------------------------------------------------------------
// conversions
// ---------------------------------------------------------------------------
__global__ void convsplit(const float* __restrict__ src,
                          __nv_bfloat16* __restrict__ h,
                          __nv_bfloat16* __restrict__ l,
                          int rows, int cols, int rows_pad, int cols_pad)
{
    size_t i = (size_t)blockIdx.x * blockDim.x + threadIdx.x;
    size_t total = (size_t)rows_pad * cols_pad;
    if (i >= total) return;
    int r = (int)(i / cols_pad);
    int c = (int)(i - (size_t)r * cols_pad);
    float v = (r < rows && c < cols) ? src[(size_t)r * cols + c] : 0.f;
    __nv_bfloat16 hi = __float2bfloat16(v);
    h[i] = hi;
    l[i] = __float2bfloat16(v - __bfloat162float(hi));
}

__global__ void conv_wsplith(const float* __restrict__ src,
                             __half* __restrict__ h, __half* __restrict__ l,
                             int rows, int cols, int rows_pad, int cols_pad)
{
    size_t i = (size_t)blockIdx.x * blockDim.x + threadIdx.x;
    size_t total = (size_t)rows_pad * cols_pad;
    if (i >= total) return;
    int r = (int)(i / cols_pad);
    int c = (int)(i - (size_t)r * cols_pad);
    float v = (r < rows && c < cols) ? src[(size_t)r * cols + c] : 0.f;
    __half hi = __float2half(v);
    h[i] = hi;
    l[i] = __float2half(v - __half2float(hi));
}

__global__ void conv_half(const float* __restrict__ src, __half* __restrict__ d)
{
    size_t i = ((size_t)blockIdx.x * blockDim.x + threadIdx.x) * 4;
    float4 v = *(const float4*)(src + i);
    __half hb[4] = { __float2half(v.x), __float2half(v.y),
                     __float2half(v.z), __float2half(v.w) };
    *(uint2*)(d + i) = *(uint2*)hb;
}

// ---------------------------------------------------------------------------
// fp16 GEMM (A single fp16, W split fp16): C = A @ W^T (+bias)(+res)
// CTA 128x128, BK=32, 8 warps, 3-stage cp.async pipeline, 1 barrier/iter.
// __launch_bounds__(256,2): 2 CTAs/SM (184KB smem, 128 regs cap).
// mode&4: write fp16 output (C reinterpreted as __half*).
// ---------------------------------------------------------------------------
#define MATB  10240                       // 128 rows * 80 B
#define BUFB  (4 * MATB)                  // bf16 stage (4 matrices)
#define BUFBH (3 * MATB)                  // fp16 stage (3 matrices)

__global__ __launch_bounds__(256, 2) void mma_gemm_h(
    const __half* __restrict__ Af,
    const __half* __restrict__ Wh, const __half* __restrict__ Wl,
    const float* __restrict__ bias, const float* __restrict__ res,
    float* __restrict__ C, int K, int NKB, int ldc, int mode)
{
    extern __shared__ char smem[];
    const uint32_t su = smem_u32(smem);
    const int tid = threadIdx.x;
    const int wid = tid >> 5, lane = tid & 31;
    const int wm = wid >> 2, wn = wid & 3;
    const int m0 = blockIdx.y * 128, n0 = blockIdx.x * 128;

    const uint32_t a_lrow = (uint32_t)(wm * 64 + (lane & 15)) * 80u + ((lane >> 4) * 16u);
    const uint32_t b_lrow = (uint32_t)(wn * 32 + ((lane >> 4) & 1) * 8 + (lane & 7)) * 80u
                          + (((lane >> 3) & 1) * 16u);

    float acc[4][4][4] = {};

    const int ch0 = tid * 2;
    #define LOAD_BUFH(kb, b) do {                                             \
        _Pragma("unroll")                                                     \
        for (int c = 0; c < 2; c++) {                                         \
            const int ch = ch0 + c;                                           \
            const int row = ch >> 2, sub = ch & 3;                            \
            const uint32_t dst = su + (b) * BUFBH + (uint32_t)row * 80u + sub * 16u; \
            const size_t asrc = (size_t)(m0 + row) * K + (kb) * 32 + sub * 8; \
            const size_t wsrc = (size_t)(n0 + row) * K + (kb) * 32 + sub * 8; \
            CP_ASYNC16(dst +        0, Af + asrc);                            \
            CP_ASYNC16(dst +     MATB, Wh + wsrc);                            \
            CP_ASYNC16(dst + 2 * MATB, Wl + wsrc);                            \
        }                                                                     \
    } while (0)

    LOAD_BUFH(0, 0);
    CP_COMMIT();
    LOAD_BUFH(1, 1);
    CP_COMMIT();

    int stage = 0;
    for (int kb = 0; kb < NKB; kb++) {
        if (kb + 1 < NKB) { CP_WAIT1(); } else { CP_WAIT0(); }
        __syncthreads();
        if (kb + 2 < NKB) {
            int ns = stage + 2; if (ns >= 3) ns -= 3;
            LOAD_BUFH(kb + 2, ns);
            CP_COMMIT();
        }

        const uint32_t sb = su + stage * BUFBH;
        #pragma unroll
        for (int ks = 0; ks < 2; ks++) {
            uint32_t af[4][4];
            uint32_t bh[2][4], bl[2][4];
            #pragma unroll
            for (int mt = 0; mt < 4; mt++) {
                const uint32_t ra = sb + a_lrow + (uint32_t)mt * 16u * 80u + ks * 32u;
                LDSM_X4(af[mt][0], af[mt][1], af[mt][2], af[mt][3], ra);
            }
            #pragma unroll
            for (int np = 0; np < 2; np++) {
                const uint32_t rb = sb + MATB + b_lrow + (uint32_t)np * 16u * 80u + ks * 32u;
                LDSM_X4(bh[np][0], bh[np][1], bh[np][2], bh[np][3], rb);
                LDSM_X4(bl[np][0], bl[np][1], bl[np][2], bl[np][3], rb + MATB);
            }
            #pragma unroll
            for (int mt = 0; mt < 4; mt++)
                #pragma unroll
                for (int nt = 0; nt < 4; nt++) {
                    const int np = nt >> 1, o = (nt & 1) * 2;
                    MMAH16816(acc[mt][nt], af[mt], bh[np][o], bh[np][o + 1]);
                    MMAH16816(acc[mt][nt], af[mt], bl[np][o], bl[np][o + 1]);
                }
        }
        stage++; if (stage >= 3) stage = 0;
    }

    const int qrow = lane >> 2, qcol = (lane & 3) * 2;
    #pragma unroll
    for (int mt = 0; mt < 4; mt++) {
        const int r0 = m0 + wm * 64 + mt * 16 + qrow;
        #pragma unroll
        for (int nt = 0; nt < 4; nt++) {
            const int c0 = n0 + wn * 32 + nt * 8 + qcol;
            float bx = 0.f, by = 0.f;
            if (mode & 1) { bx = bias[c0]; by = bias[c0 + 1]; }
            float2 v0 = make_float2(acc[mt][nt][0] + bx, acc[mt][nt][1] + by);
            float2 v1 = make_float2(acc[mt][nt][2] + bx, acc[mt][nt][3] + by);
            const size_t i0 = (size_t)r0 * ldc + c0;
            const size_t i1 = (size_t)(r0 + 8) * ldc + c0;
            if (mode & 2) {
                float2 r0v = *(const float2*)(res + i0);
                float2 r1v = *(const float2*)(res + i1);
                v0.x += r0v.x; v0.y += r0v.y;
                v1.x += r1v.x; v1.y += r1v.y;
            }
            if (mode & 4) {
                __half* Ch = (__half*)C;
                __half2 h0, h1;
                h0.x = __float2half(v0.x); h0.y = __float2half(v0.y);
                h1.x = __float2half(v1.x); h1.y = __float2half(v1.y);
                *(__half2*)(Ch + i0) = h0;
                *(__half2*)(Ch + i1) = h1;
            } else {
                *(float2*)(C + i0) = v0;
                *(float2*)(C + i1) = v1;
            }
        }
    }
    #undef LOAD_BUFH
}

// ---------------------------------------------------------------------------
// bf16 3-term split GEMM (dd projection only), 3-stage pipeline
// ---------------------------------------------------------------------------
__global__ __launch_bounds__(256, 1) void mma_gemm(
    const __nv_bfloat16* __restrict__ Ah, const __nv_bfloat16* __restrict__ Al,
    const __nv_bfloat16* __restrict__ Wh, const __nv_bfloat16* __restrict__ Wl,
    const float* __restrict__ bias, const float* __restrict__ res,
    float* __restrict__ C, int K, int NKB, int ldc, int mode)
{
    extern __shared__ char smem[];
    const uint32_t su = smem_u32(smem);
    const int tid = threadIdx.x;
    const int wid = tid >> 5, lane = tid & 31;
    const int wm = wid >> 2, wn = wid & 3;
    const int m0 = blockIdx.y * 128, n0 = blockIdx.x * 128;

    const uint32_t a_lrow = (uint32_t)(wm * 64 + (lane & 15)) * 80u + ((lane >> 4) * 16u);
    const uint32_t b_lrow = (uint32_t)(wn * 32 + ((lane >> 4) & 1) * 8 + (lane & 7)) * 80u
                          + (((lane >> 3) & 1) * 16u);

    float acc[4][4][4] = {};

    const int ch0 = tid * 2;
    #define LOAD_BUF(kb, b) do {                                              \
        _Pragma("unroll")                                                     \
        for (int c = 0; c < 2; c++) {                                         \
            const int ch = ch0 + c;                                           \
            const int row = ch >> 2, sub = ch & 3;                            \
            const uint32_t dst = su + (b) * BUFB + (uint32_t)row * 80u + sub * 16u; \
            const size_t asrc = (size_t)(m0 + row) * K + (kb) * 32 + sub * 8; \
            const size_t wsrc = (size_t)(n0 + row) * K + (kb) * 32 + sub * 8; \
            CP_ASYNC16(dst +        0, Ah + asrc);                            \
            CP_ASYNC16(dst +     MATB, Al + asrc);                            \
            CP_ASYNC16(dst + 2 * MATB, Wh + wsrc);                            \
            CP_ASYNC16(dst + 3 * MATB, Wl + wsrc);                            \
        }                                                                     \
    } while (0)

    LOAD_BUF(0, 0);
    CP_COMMIT();
    LOAD_BUF(1, 1);
    CP_COMMIT();

    int stage = 0;
    for (int kb = 0; kb < NKB; kb++) {
        if (kb + 1 < NKB) { CP_WAIT1(); } else { CP_WAIT0(); }
        __syncthreads();
        if (kb + 2 < NKB) {
            int ns = stage + 2; if (ns >= 3) ns -= 3;
            LOAD_BUF(kb + 2, ns);
            CP_COMMIT();
        }

        const uint32_t sb = su + stage * BUFB;
        #pragma unroll
        for (int ks = 0; ks < 2; ks++) {
            uint32_t ah[4][4], al[4][4];
            uint32_t bh[2][4], bl[2][4];
            #pragma unroll
            for (int mt = 0; mt < 4; mt++) {
                const uint32_t ra = sb + a_lrow + (uint32_t)mt * 16u * 80u + ks * 32u;
                LDSM_X4(ah[mt][0], ah[mt][1], ah[mt][2], ah[mt][3], ra);
                LDSM_X4(al[mt][0], al[mt][1], al[mt][2], al[mt][3], ra + MATB);
            }
            #pragma unroll
            for (int np = 0; np < 2; np++) {
                const uint32_t rb = sb + 2 * MATB + b_lrow + (uint32_t)np * 16u * 80u + ks * 32u;
                LDSM_X4(bh[np][0], bh[np][1], bh[np][2], bh[np][3], rb);
                LDSM_X4(bl[np][0], bl[np][1], bl[np][2], bl[np][3], rb + MATB);
            }
            #pragma unroll
            for (int mt = 0; mt < 4; mt++)
                #pragma unroll
                for (int nt = 0; nt < 4; nt++) {
                    const int np = nt >> 1, o = (nt & 1) * 2;
                    MMA16816(acc[mt][nt], ah[mt], bh[np][o], bh[np][o + 1]);
                    MMA16816(acc[mt][nt], ah[mt], bl[np][o], bl[np][o + 1]);
                    MMA16816(acc[mt][nt], al[mt], bh[np][o], bh[np][o + 1]);
                }
        }
        stage++; if (stage >= 3) stage = 0;
    }

    const int qrow = lane >> 2, qcol = (lane & 3) * 2;
    #pragma unroll
    for (int mt = 0; mt < 4; mt++) {
        const int r0 = m0 + wm * 64 + mt * 16 + qrow;
        #pragma unroll
        for (int nt = 0; nt < 4; nt++) {
            const int c0 = n0 + wn * 32 + nt * 8 + qcol;
            float bx = 0.f, by = 0.f;
            if (mode & 1) { bx = bias[c0]; by = bias[c0 + 1]; }
            float2 v0 = make_float2(acc[mt][nt][0] + bx, acc[mt][nt][1] + by);
            float2 v1 = make_float2(acc[mt][nt][2] + bx, acc[mt][nt][3] + by);
            const size_t i0 = (size_t)r0 * ldc + c0;
            const size_t i1 = (size_t)(r0 + 8) * ldc + c0;
            if (mode & 2) {
                float2 r0v = *(const float2*)(res + i0);
                float2 r1v = *(const float2*)(res + i1);
                v0.x += r0v.x; v0.y += r0v.y;
                v1.x += r1v.x; v1.y += r1v.y;
            }
            *(float2*)(C + i0) = v0;
            *(float2*)(C + i1) = v1;
        }
    }
    #undef LOAD_BUF
}

// ---------------------------------------------------------------------------
// mix: xmix fp32 + bf16 hi/lo split (dd GEMM input)
// ---------------------------------------------------------------------------
__global__ void mix_split_kernel(const float* __restrict__ x,
                                 const float* __restrict__ glin,
                                 float* __restrict__ xmix,
                                 __nv_bfloat16* __restrict__ oh,
                                 __nv_bfloat16* __restrict__ ol)
{
    const size_t i = (size_t)blockIdx.x * blockDim.x + threadIdx.x;
    const int row = (int)(i >> 8);
    const int t = row & (T_ - 1);
    float4 xv = *(const float4*)(x + i * 4);
    float4 gv = *(const float4*)(glin + i * 4);
    float4 pv = make_float4(0.f, 0.f, 0.f, 0.f);
    if (t > 0) pv = *(const float4*)(x + (i - 256) * 4);
    float o[4]; float g;
    g = 1.f / (1.f + __expf(-gv.x)); o[0] = (1.f - g) * xv.x + g * pv.x;
    g = 1.f / (1.f + __expf(-gv.y)); o[1] = (1.f - g) * xv.y + g * pv.y;
    g = 1.f / (1.f + __expf(-gv.z)); o[2] = (1.f - g) * xv.z + g * pv.z;
    g = 1.f / (1.f + __expf(-gv.w)); o[3] = (1.f - g) * xv.w + g * pv.w;
    *(float4*)(xmix + i * 4) = make_float4(o[0], o[1], o[2], o[3]);
    __nv_bfloat16 hb[4], lb[4];
    #pragma unroll
    for (int j = 0; j < 4; j++) {
        hb[j] = __float2bfloat16(o[j]);
        lb[j] = __float2bfloat16(o[j] - __bfloat162float(hb[j]));
    }
    *(uint2*)(oh + i * 4) = *(uint2*)hb;
    *(uint2*)(ol + i * 4) = *(uint2*)lb;
}

// ---------------------------------------------------------------------------
// RMSNorm -> single fp16 output
// ---------------------------------------------------------------------------
__global__ __launch_bounds__(256) void rmsnorm_half_kernel(
    const float* __restrict__ x, const float* __restrict__ w,
    __half* __restrict__ oh)
{
    const int row = blockIdx.x;
    const int tid = threadIdx.x;
    const float* xr = x + (size_t)row * D_;
    float4 v = *(const float4*)(xr + tid * 4);
    float s = v.x * v.x + v.y * v.y + v.z * v.z + v.w * v.w;
    #pragma unroll
    for (int m = 16; m > 0; m >>= 1) s += __shfl_xor_sync(0xffffffffu, s, m);
    __shared__ float red[8];
    if ((tid & 31) == 0) red[tid >> 5] = s;
    __syncthreads();
    if (tid < 32) {
        float t = (tid < 8) ? red[tid] : 0.f;
        #pragma unroll
        for (int m = 4; m > 0; m >>= 1) t += __shfl_xor_sync(0xffffffffu, t, m);
        if (tid == 0) red[0] = t;
    }
    __syncthreads();
    const float inv = rsqrtf(red[0] / (float)D_ + EPS_);
    float4 wv = *(const float4*)(w + tid * 4);
    __half hb[4] = { __float2half(v.x * inv * wv.x), __float2half(v.y * inv * wv.y),
                     __float2half(v.z * inv * wv.z), __float2half(v.w * inv * wv.w) };
    *(uint2*)(oh + (size_t)row * D_ + tid * 4) = *(uint2*)hb;
}

// ---------------------------------------------------------------------------
// 3-phase cumsum
// ---------------------------------------------------------------------------
__global__ void cumsumA(const float* __restrict__ dd, float* __restrict__ cs)
{
    const int c = threadIdx.x;
    const int blk = blockIdx.x;
    const int b = blk >> 4, ch = blk & 15;
    size_t base = ((size_t)b * T_ + ch * 128) * 256 + c;
    float s = 0.f;
    #pragma unroll 8
    for (int t = 0; t < 128; t++) { s += dd[base]; base += 256; }
    cs[(size_t)blk * 256 + c] = s;
}
__global__ void cumsumB(float* __restrict__ cs)
{
    const int c = threadIdx.x;
    const int b = blockIdx.x;
    float run = 0.f;
    #pragma unroll
    for (int ch = 0; ch < 16; ch++) {
        size_t i = ((size_t)b * 16 + ch) * 256 + c;
        float t = cs[i];
        cs[i] = run;
        run += t;
    }
}
__global__ void cumsumC(float* __restrict__ dd, const float* __restrict__ cs)
{
    const int c = threadIdx.x;
    const int blk = blockIdx.x;
    const int b = blk >> 4, ch = blk & 15;
    float acc = cs[(size_t)blk * 256 + c];
    size_t base = ((size_t)b * T_ + ch * 128) * 256 + c;
    #pragma unroll 8
    for (int t = 0; t < 128; t++) { acc += dd[base]; dd[base] = acc; base += 256; }
}

// ---------------------------------------------------------------------------
// q/k head rmsnorm + hybrid rope + head-major scatter
// ---------------------------------------------------------------------------
__global__ __launch_bounds__(256) void qkv_transform_kernel(
    const float* __restrict__ qkv, const float* __restrict__ ddcum,
    const float* __restrict__ rc, const float* __restrict__ rs,
    const float* __restrict__ qnw, const float* __restrict__ knw,
    const float* __restrict__ qpb, const float* __restrict__ kpb,
    float* __restrict__ qt, float* __restrict__ kt, float* __restrict__ vt)
{
    const int w = blockIdx.x * 8 + (threadIdx.x >> 5);
    const int lane = threadIdx.x & 31;
    const int b = w >> 15;
    const int rem = w & 32767;
    const int t = rem >> 4;
    const int h = rem & 15;

    const size_t base = ((size_t)(b * T_ + t) * 3) * D_ + h * DH_;
    float q0 = qkv[base + lane],          q1 = qkv[base + 32 + lane];
    float k0 = qkv[base + D_ + lane],     k1 = qkv[base + D_ + 32 + lane];
    float v0 = qkv[base + 2 * D_ + lane], v1 = qkv[base + 2 * D_ + 32 + lane];

    float sq = q0 * q0 + q1 * q1;
    float sk = k0 * k0 + k1 * k1;
    #pragma unroll
    for (int m = 16; m > 0; m >>= 1) {
        sq += __shfl_xor_sync(0xffffffffu, sq, m);
        sk += __shfl_xor_sync(0xffffffffu, sk, m);
    }
    const float rq = rsqrtf(sq / 64.f + EPS_);
    const float rk = rsqrtf(sk / 64.f + EPS_);
    q0 *= rq * qnw[lane] * qpb[lane];
    q1 *= rq * qnw[lane + 32] * qpb[lane + 32];
    k0 *= rk * knw[lane] * kpb[lane];
    k1 *= rk * knw[lane + 32] * kpb[lane + 32];

    const int j = lane & 15;
    const float c = rc[t * 32 + j], s = rs[t * 32 + j];
    const float ang = ddcum[((size_t)(b * T_ + t)) * 256 + h * 16 + j];
    float s2, c2;
    sincosf(ang, &s2, &c2);

    const float qp0 = __shfl_xor_sync(0xffffffffu, q0, 16);
    const float qp1 = __shfl_xor_sync(0xffffffffu, q1, 16);
    const float kp0 = __shfl_xor_sync(0xffffffffu, k0, 16);
    const float kp1 = __shfl_xor_sync(0xffffffffu, k1, 16);
    float oq0, oq1, ok0, ok1;
    if (lane < 16) {
        oq0 = q0 * c - qp0 * s;  oq1 = q1 * c2 - qp1 * s2;
        ok0 = k0 * c - kp0 * s;  ok1 = k1 * c2 - kp1 * s2;
    } else {
        oq0 = q0 * c + qp0 * s;  oq1 = q1 * c2 + qp1 * s2;
        ok0 = k0 * c + kp0 * s;  ok1 = k1 * c2 + kp1 * s2;
    }

    const size_t ob = ((size_t)(b * NH_ + h) * T_ + t) * DH_;
    qt[ob + lane] = oq0;  qt[ob + 32 + lane] = oq1;
    kt[ob + lane] = ok0;  kt[ob + 32 + lane] = ok1;
    vt[ob + lane] = v0;   vt[ob + 32 + lane] = v1;
}

// ---------------------------------------------------------------------------
// Flash attention (tf32 mma) -> single fp16 output; heavy tiles first
// ---------------------------------------------------------------------------
#define KS_OFF 0
#define VS_OFF (64 * 72)
#define PS_OFF (2 * 64 * 72)
#define FSMEM ((2 * 64 * 72 + 128 * 68) * 4)

__global__ __launch_bounds__(256, 1) void flash_tc(
    const float* __restrict__ qt, const float* __restrict__ kt,
    const float* __restrict__ vt, __half* __restrict__ yh)
{
    extern __shared__ uint32_t fsm[];
    uint32_t* Ks = fsm + KS_OFF;
    uint32_t* Vs = fsm + VS_OFF;
    uint32_t* Ps = fsm + PS_OFF;

    const int tid = threadIdx.x, lane = tid & 31, w = tid >> 5;
    const int bx = gridDim.x - 1 - blockIdx.x;     // heavy q-tiles first
    const int bh = blockIdx.y;
    const int b = bh >> 4, h = bh & 15;
    const int m0 = bx * 128;

    const float* Qb = qt + (size_t)bh * T_ * DH_;
    const float* Kb = kt + (size_t)bh * T_ * DH_;
    const float* Vb = vt + (size_t)bh * T_ * DH_;

    const int r1 = m0 + w * 16 + (lane >> 2);
    uint32_t qf[8][4];
    {
        const float* q1 = Qb + (size_t)r1 * DH_;
        const float* q2 = q1 + 8 * DH_;
        #pragma unroll
        for (int k8 = 0; k8 < 8; k8++) {
            const int c = k8 * 8 + (lane & 3);
            qf[k8][0] = f2tf(q1[c] * 0.125f);
            qf[k8][1] = f2tf(q2[c] * 0.125f);
            qf[k8][2] = f2tf(q1[c + 4] * 0.125f);
            qf[k8][3] = f2tf(q2[c + 4] * 0.125f);
        }
    }

    float mi[2] = { -1e30f, -1e30f }, li[2] = { 0.f, 0.f };
    float O[8][4] = {};

    const int ntiles = 2 * bx + 2;
    for (int nt = 0; nt < ntiles; nt++) {
        const int n0 = nt * 64;
        __syncthreads();
        {
            const int key = tid >> 2, db = (tid & 3) * 16;
            const float* kp = Kb + (size_t)(n0 + key) * DH_ + db;
            const float* vp = Vb + (size_t)(n0 + key) * DH_ + db;
            #pragma unroll
            for (int i = 0; i < 16; i += 4) {
                float4 kv = *(const float4*)(kp + i);
                Ks[(db + i + 0) * 72 + key] = f2tf(kv.x);
                Ks[(db + i + 1) * 72 + key] = f2tf(kv.y);
                Ks[(db + i + 2) * 72 + key] = f2tf(kv.z);
                Ks[(db + i + 3) * 72 + key] = f2tf(kv.w);
                float4 vv = *(const float4*)(vp + i);
                uint4 vo;
                vo.x = f2tf(vv.x); vo.y = f2tf(vv.y);
                vo.z = f2tf(vv.z); vo.w = f2tf(vv.w);
                *(uint4*)&Vs[key * 72 + db + i] = vo;
            }
        }
        __syncthreads();

        float S[8][4] = {};
        #pragma unroll
        for (int k8 = 0; k8 < 8; k8++) {
            const uint32_t* kr0 = &Ks[(k8 * 8 + (lane & 3)) * 72 + (lane >> 2)];
            const uint32_t* kr1 = kr0 + 4 * 72;
            #pragma unroll
            for (int n8 = 0; n8 < 8; n8++) {
                MMATF32(S[n8], qf[k8], kr0[n8 * 8], kr1[n8 * 8]);
            }
        }
        if (nt >= 2 * bx) {
            #pragma unroll
            for (int n8 = 0; n8 < 8; n8++) {
                const int cb = n0 + n8 * 8 + 2 * (lane & 3);
                if (cb     > r1)     S[n8][0] = -1e30f;
                if (cb + 1 > r1)     S[n8][1] = -1e30f;
                if (cb     > r1 + 8) S[n8][2] = -1e30f;
                if (cb + 1 > r1 + 8) S[n8][3] = -1e30f;
            }
        }
        #pragma unroll
        for (int half = 0; half < 2; half++) {
            float mx = -1e30f;
            #pragma unroll
            for (int n8 = 0; n8 < 8; n8++)
                mx = fmaxf(mx, fmaxf(S[n8][half * 2], S[n8][half * 2 + 1]));
            mx = fmaxf(mx, __shfl_xor_sync(0xffffffffu, mx, 1));
            mx = fmaxf(mx, __shfl_xor_sync(0xffffffffu, mx, 2));
            const float mnew = fmaxf(mi[half], mx);
            const float corr = __expf(mi[half] - mnew);
            float rsum = 0.f;
            #pragma unroll
            for (int n8 = 0; n8 < 8; n8++) {
                float e0 = __expf(S[n8][half * 2]     - mnew);
                float e1 = __expf(S[n8][half * 2 + 1] - mnew);
                S[n8][half * 2] = e0; S[n8][half * 2 + 1] = e1;
                rsum += e0 + e1;
            }
            rsum += __shfl_xor_sync(0xffffffffu, rsum, 1);
            rsum += __shfl_xor_sync(0xffffffffu, rsum, 2);
            li[half] = li[half] * corr + rsum;
            mi[half] = mnew;
            #pragma unroll
            for (int n8 = 0; n8 < 8; n8++) {
                O[n8][half * 2]     *= corr;
                O[n8][half * 2 + 1] *= corr;
            }
        }
        {
            const int pr = w * 16 + (lane >> 2);
            #pragma unroll
            for (int n8 = 0; n8 < 8; n8++) {
                const int pc = n8 * 8 + 2 * (lane & 3);
                uint2 p0, p1;
                p0.x = f2tf(S[n8][0]); p0.y = f2tf(S[n8][1]);
                p1.x = f2tf(S[n8][2]); p1.y = f2tf(S[n8][3]);
                *(uint2*)&Ps[pr * 68 + pc]       = p0;
                *(uint2*)&Ps[(pr + 8) * 68 + pc] = p1;
            }
        }
        __syncwarp();
        #pragma unroll
        for (int k8 = 0; k8 < 8; k8++) {
            uint32_t a[4];
            const int pr = w * 16 + (lane >> 2);
            const int pc = k8 * 8 + (lane & 3);
            a[0] = Ps[pr * 68 + pc];
            a[1] = Ps[(pr + 8) * 68 + pc];
            a[2] = Ps[pr * 68 + pc + 4];
            a[3] = Ps[(pr + 8) * 68 + pc + 4];
            const uint32_t* vr0 = &Vs[(k8 * 8 + (lane & 3)) * 72 + (lane >> 2)];
            const uint32_t* vr1 = vr0 + 4 * 72;
            #pragma unroll
            for (int n8 = 0; n8 < 8; n8++) {
                MMATF32(O[n8], a, vr0[n8 * 8], vr1[n8 * 8]);
            }
        }
    }

    const float inv0 = 1.f / li[0], inv1 = 1.f / li[1];
    const size_t o1 = ((size_t)(b * T_ + r1)) * D_ + h * DH_ + 2 * (lane & 3);
    const size_t o2 = o1 + 8 * D_;
    #pragma unroll
    for (int n8 = 0; n8 < 8; n8++) {
        __half2 h0, h1;
        h0.x = __float2half(O[n8][0] * inv0); h0.y = __float2half(O[n8][1] * inv0);
        h1.x = __float2half(O[n8][2] * inv1); h1.y = __float2half(O[n8][3] * inv1);
        *(__half2*)(yh + o1 + n8 * 8) = h0;
        *(__half2*)(yh + o2 + n8 * 8) = h1;
    }
}

// ---------------------------------------------------------------------------
// act = silu(gate)*up from fp16 combined [M, 2*FFNP] -> fp16 [M, FFNP]
// ---------------------------------------------------------------------------
__global__ void act_half_kernel(const __half* __restrict__ gu,
                                __half* __restrict__ oh)
{
    const size_t idx4 = (size_t)blockIdx.x * blockDim.x + threadIdx.x;
    const int row = (int)(idx4 / (FFNP / 4));
    const int c = (int)(idx4 % (FFNP / 4)) * 4;
    const __half* gp = gu + (size_t)row * (2 * FFNP) + c;
    __half gh[4], uh[4];
    *(uint2*)gh = *(const uint2*)gp;
    *(uint2*)uh = *(const uint2*)(gp + FFNP);
    __half hb[4];
    #pragma unroll
    for (int j = 0; j < 4; j++) {
        float g = __half2float(gh[j]);
        float u = __half2float(uh[j]);
        hb[j] = __float2half(g / (1.f + __expf(-g)) * u);
    }
    *(uint2*)(oh + (size_t)row * FFNP + c) = *(uint2*)hb;
}

// ---------------------------------------------------------------------------
// Launch
// ---------------------------------------------------------------------------
static inline int cdiv(long long a, long long b) { return (int)((a + b - 1) / b); }

extern "C" void kernel_launch(void* const* d_in, const int* in_sizes, int n_in,
                              void* d_out, int out_size)
{
    const float* x     = (const float*)d_in[0];
    const float* rc    = (const float*)d_in[1];
    const float* rs    = (const float*)d_in[2];
    const float* lerpw = (const float*)d_in[3];
    const float* lerpb = (const float*)d_in[4];
    const float* anw   = (const float*)d_in[5];
    const float* wqkv  = (const float*)d_in[6];
    const float* qnw   = (const float*)d_in[7];
    const float* knw   = (const float*)d_in[8];
    const float* qpb   = (const float*)d_in[9];
    const float* kpb   = (const float*)d_in[10];
    const float* ddw   = (const float*)d_in[11];
    const float* ddb   = (const float*)d_in[12];
    const float* wo    = (const float*)d_in[13];
    const float* mnw   = (const float*)d_in[14];
    const float* gw    = (const float*)d_in[15];
    const float* uw    = (const float*)d_in[16];
    const float* dw    = (const float*)d_in[17];
    float* out = (float*)d_out;

    float *glin, *xmix, *qkv, *dd, *cs, *qt, *kt, *vt, *x2;
    __half *guh;
    __nv_bfloat16 *ah, *al, *wh, *wl;
    __half *af, *wfh, *wfl;
    cudaGetSymbolAddress((void**)&glin, s_glin);
    cudaGetSymbolAddress((void**)&xmix, s_xmix);
    cudaGetSymbolAddress((void**)&qkv,  s_qkv);
    cudaGetSymbolAddress((void**)&dd,   s_dd);
    cudaGetSymbolAddress((void**)&cs,   s_csum);
    cudaGetSymbolAddress((void**)&qt,   s_qt);
    cudaGetSymbolAddress((void**)&kt,   s_kt);
    cudaGetSymbolAddress((void**)&vt,   s_vt);
    cudaGetSymbolAddress((void**)&x2,   s_x2);
    cudaGetSymbolAddress((void**)&guh,  s_guh);
    cudaGetSymbolAddress((void**)&ah,   g_ah);
    cudaGetSymbolAddress((void**)&al,   g_al);
    cudaGetSymbolAddress((void**)&wh,   g_wh);
    cudaGetSymbolAddress((void**)&wl,   g_wl);
    cudaGetSymbolAddress((void**)&af,   g_af);
    cudaGetSymbolAddress((void**)&wfh,  g_wfh);
    cudaGetSymbolAddress((void**)&wfl,  g_wfl);

    cudaFuncSetAttribute(mma_gemm,
                         cudaFuncAttributeMaxDynamicSharedMemorySize, 3 * BUFB);
    cudaFuncSetAttribute(mma_gemm_h,
                         cudaFuncAttributeMaxDynamicSharedMemorySize, 3 * BUFBH);
    cudaFuncSetAttribute(flash_tc,
                         cudaFuncAttributeMaxDynamicSharedMemorySize, FSMEM);

    const dim3 blk(256);
    const int GSM  = 3 * BUFB;    // 122880
    const int GSMH = 3 * BUFBH;   // 92160

    #define CONVH(src, d, n) \
        conv_half<<<(int)(((long long)(n) / 4) / 256), blk>>>(src, d)
    #define CONVW(src, dh, dl, r, c, rp, cp) \
        conv_wsplith<<<cdiv((long long)(rp) * (cp), 256), blk>>>(src, dh, dl, r, c, rp, cp)

    // 1. glin = x @ lerp_w^T + lerp_b
    CONVH(x, af, (long long)M_ * D_);
    CONVW(lerpw, wfh, wfl, D_, D_, D_, D_);
    mma_gemm_h<<<dim3(8, 32), blk, GSMH>>>(af, wfh, wfl, lerpb, nullptr, glin, D_, 32, D_, 1);
    // 2. xmix (fp32 + bf16 split for dd)
    mix_split_kernel<<<(M_ * D_ / 4) / 256, blk>>>(x, glin, xmix, ah, al);
    // 3. dd = xmix @ dd_w^T + dd_b (bf16 3-term)
    convsplit<<<cdiv(256LL * D_, 256), blk>>>(ddw, wh, wl, 256, D_, 256, D_);
    mma_gemm<<<dim3(2, 32), blk, GSM>>>(ah, al, wh, wl, ddb, nullptr, dd, D_, 32, 256, 1);
    // 4. cumsum along T
    cumsumA<<<B_ * 16, blk>>>(dd, cs);
    cumsumB<<<B_, blk>>>(cs);
    cumsumC<<<B_ * 16, blk>>>(dd, cs);
    // 5. h = rmsnorm(xmix) -> fp16
    rmsnorm_half_kernel<<<M_, blk>>>(xmix, anw, af);
    // 6. qkv = h @ w_qkv^T
    CONVW(wqkv, wfh, wfl, 3 * D_, D_, 3 * D_, D_);
    mma_gemm_h<<<dim3(24, 32), blk, GSMH>>>(af, wfh, wfl, nullptr, nullptr, qkv, D_, 32, 3 * D_, 0);
    // 7. q/k transform
    qkv_transform_kernel<<<(B_ * T_ * NH_) / 8, blk>>>(qkv, dd, rc, rs, qnw, knw,
                                                       qpb, kpb, qt, kt, vt);
    // 8. flash attention (tf32) -> y fp16
    flash_tc<<<dim3(T_ / 128, B_ * NH_), blk, FSMEM>>>(qt, kt, vt, af);
    // 9. x2 = xmix + y @ w_o^T
    CONVW(wo, wfh, wfl, D_, D_, D_, D_);
    mma_gemm_h<<<dim3(8, 32), blk, GSMH>>>(af, wfh, wfl, nullptr, xmix, x2, D_, 32, D_, 2);
    // 10. h = rmsnorm(x2) -> fp16
    rmsnorm_half_kernel<<<M_, blk>>>(x2, mnw, af);
    // 11. combined gate|up GEMM: N = 2*FFNP = 5632, fp16 output
    CONVW(gw, wfh, wfl, FFN_, D_, FFNP, D_);
    conv_wsplith<<<cdiv((long long)FFNP * D_, 256), blk>>>(uw, wfh + (size_t)FFNP * D_,
                                                           wfl + (size_t)FFNP * D_,
                                                           FFN_, D_, FFNP, D_);
    mma_gemm_h<<<dim3(44, 32), blk, GSMH>>>(af, wfh, wfl, nullptr, nullptr,
                                            (float*)guh, D_, 32, 2 * FFNP, 4);
    // 12. act = silu(gate)*up -> fp16
    act_half_kernel<<<(M_ * FFNP / 4) / 256, blk>>>(guh, af);
    // 13. out = x2 + act @ down_w^T
    CONVW(dw, wfh, wfl, D_, FFN_, D_, FFNP);
    mma_gemm_h<<<dim3(8, 32), blk, GSMH>>>(af, wfh, wfl, nullptr, x2, out, FFNP, 88, D_, 2);
}

// round 9
// speedup vs baseline: 2.3338x; 1.3260x over previous
#include <cuda_runtime.h>
#include <cuda_bf16.h>
#include <cuda_fp16.h>
#include <math.h>
#include <stdint.h>

// ---------------------------------------------------------------------------
// Problem constants
// ---------------------------------------------------------------------------
#define B_   2
#define T_   2048
#define D_   1024
#define NH_  16
#define DH_  64
#define FFN_ 2736
#define FFNP 2816
#define M_   (B_ * T_)
#define EPS_ 1e-6f

// ---------------------------------------------------------------------------
// PTX helpers (arch-generic, sm_80+)
// ---------------------------------------------------------------------------
__device__ __forceinline__ uint32_t smem_u32(const void* p) {
    uint32_t a;
    asm("{ .reg .u64 t; cvta.to.shared.u64 t, %1; cvt.u32.u64 %0, t; }"
        : "=r"(a) : "l"(p));
    return a;
}
#define CP_ASYNC16(dst, src) \
    asm volatile("cp.async.cg.shared.global [%0], [%1], 16;" :: "r"(dst), "l"(src))
#define CP_COMMIT() asm volatile("cp.async.commit_group;" ::: "memory")
#define CP_WAIT0()  asm volatile("cp.async.wait_group 0;" ::: "memory")
#define CP_WAIT1()  asm volatile("cp.async.wait_group 1;" ::: "memory")
#define LDSM_X4(r0, r1, r2, r3, addr) \
    asm volatile("ldmatrix.sync.aligned.m8n8.x4.shared.b16 {%0,%1,%2,%3}, [%4];" \
                 : "=r"(r0), "=r"(r1), "=r"(r2), "=r"(r3) : "r"(addr))
#define MMA16816(d, a, b0, b1) \
    asm volatile("mma.sync.aligned.m16n8k16.row.col.f32.bf16.bf16.f32 " \
                 "{%0,%1,%2,%3},{%4,%5,%6,%7},{%8,%9},{%0,%1,%2,%3};" \
                 : "+f"((d)[0]), "+f"((d)[1]), "+f"((d)[2]), "+f"((d)[3]) \
                 : "r"((a)[0]), "r"((a)[1]), "r"((a)[2]), "r"((a)[3]), \
                   "r"(b0), "r"(b1))
#define MMAH16816(d, a, b0, b1) \
    asm volatile("mma.sync.aligned.m16n8k16.row.col.f32.f16.f16.f32 " \
                 "{%0,%1,%2,%3},{%4,%5,%6,%7},{%8,%9},{%0,%1,%2,%3};" \
                 : "+f"((d)[0]), "+f"((d)[1]), "+f"((d)[2]), "+f"((d)[3]) \
                 : "r"((a)[0]), "r"((a)[1]), "r"((a)[2]), "r"((a)[3]), \
                   "r"(b0), "r"(b1))
#define MMATF32(d, a, b0, b1) \
    asm volatile("mma.sync.aligned.m16n8k8.row.col.f32.tf32.tf32.f32 " \
                 "{%0,%1,%2,%3},{%4,%5,%6,%7},{%8,%9},{%0,%1,%2,%3};" \
                 : "+f"((d)[0]), "+f"((d)[1]), "+f"((d)[2]), "+f"((d)[3]) \
                 : "r"((a)[0]), "r"((a)[1]), "r"((a)[2]), "r"((a)[3]), \
                   "r"(b0), "r"(b1))
__device__ __forceinline__ uint32_t f2tf(float f) {
    uint32_t r;
    asm("cvt.rna.tf32.f32 %0, %1;" : "=r"(r) : "f"(f));
    return r;
}

// ---------------------------------------------------------------------------
// Device scratch
// ---------------------------------------------------------------------------
__device__ float s_glin[M_ * D_];
__device__ float s_xmix[M_ * D_];
__device__ float s_qkv [M_ * 3 * D_];
__device__ float s_dd  [M_ * NH_ * 16];
__device__ float s_csum[B_ * 16 * 256];
__device__ float s_qt  [B_ * NH_ * T_ * DH_];
__device__ float s_kt  [B_ * NH_ * T_ * DH_];
__device__ float s_vt  [B_ * NH_ * T_ * DH_];
__device__ float s_x2  [M_ * D_];
__device__ __half s_guh[(size_t)M_ * 2 * FFNP];     // gate | up combined (fp16)
// bf16 split buffers (dd path only)
__device__ __nv_bfloat16 g_ah[(size_t)M_ * D_];
__device__ __nv_bfloat16 g_al[(size_t)M_ * D_];
__device__ __nv_bfloat16 g_wh[256 * D_];
__device__ __nv_bfloat16 g_wl[256 * D_];
// fp16 buffers (main GEMM path)
__device__ __half g_af[(size_t)M_ * FFNP];
__device__ __half g_wf[(size_t)2 * FFNP * D_];

// ---------------------------------------------------------------------------
// conversions
// ---------------------------------------------------------------------------
__global__ void convsplit(const float* __restrict__ src,
                          __nv_bfloat16* __restrict__ h,
                          __nv_bfloat16* __restrict__ l,
                          int rows, int cols, int rows_pad, int cols_pad)
{
    size_t i = (size_t)blockIdx.x * blockDim.x + threadIdx.x;
    size_t total = (size_t)rows_pad * cols_pad;
    if (i >= total) return;
    int r = (int)(i / cols_pad);
    int c = (int)(i - (size_t)r * cols_pad);
    float v = (r < rows && c < cols) ? src[(size_t)r * cols + c] : 0.f;
    __nv_bfloat16 hi = __float2bfloat16(v);
    h[i] = hi;
    l[i] = __float2bfloat16(v - __bfloat162float(hi));
}

// weights: fp32 -> single fp16 with zero padding
__global__ void conv_whalf(const float* __restrict__ src,
                           __half* __restrict__ d,
                           int rows, int cols, int rows_pad, int cols_pad)
{
    size_t i = (size_t)blockIdx.x * blockDim.x + threadIdx.x;
    size_t total = (size_t)rows_pad * cols_pad;
    if (i >= total) return;
    int r = (int)(i / cols_pad);
    int c = (int)(i - (size_t)r * cols_pad);
    float v = (r < rows && c < cols) ? src[(size_t)r * cols + c] : 0.f;
    d[i] = __float2half(v);
}

__global__ void conv_half(const float* __restrict__ src, __half* __restrict__ d)
{
    size_t i = ((size_t)blockIdx.x * blockDim.x + threadIdx.x) * 4;
    float4 v = *(const float4*)(src + i);
    __half hb[4] = { __float2half(v.x), __float2half(v.y),
                     __float2half(v.z), __float2half(v.w) };
    *(uint2*)(d + i) = *(uint2*)hb;
}

// ---------------------------------------------------------------------------
// fp16 GEMM (A fp16, W single fp16): C = A @ W^T (+bias)(+res)
// CTA 128x128, BK=32, 8 warps, 3-stage cp.async pipeline, 1 barrier/iter,
// 2 CTAs/SM, 1 HMMA per k16 per microtile.  mode&4: fp16 output.
// ---------------------------------------------------------------------------
#define MATB  10240                       // 128 rows * 80 B
#define BUFB  (4 * MATB)                  // bf16 stage (4 matrices)
#define BUFBH (2 * MATB)                  // fp16 stage (A + W)

__global__ __launch_bounds__(256, 2) void mma_gemm_h(
    const __half* __restrict__ Af, const __half* __restrict__ Wf,
    const float* __restrict__ bias, const float* __restrict__ res,
    float* __restrict__ C, int K, int NKB, int ldc, int mode)
{
    extern __shared__ char smem[];
    const uint32_t su = smem_u32(smem);
    const int tid = threadIdx.x;
    const int wid = tid >> 5, lane = tid & 31;
    const int wm = wid >> 2, wn = wid & 3;
    const int m0 = blockIdx.y * 128, n0 = blockIdx.x * 128;

    const uint32_t a_lrow = (uint32_t)(wm * 64 + (lane & 15)) * 80u + ((lane >> 4) * 16u);
    const uint32_t b_lrow = (uint32_t)(wn * 32 + ((lane >> 4) & 1) * 8 + (lane & 7)) * 80u
                          + (((lane >> 3) & 1) * 16u);

    float acc[4][4][4] = {};

    const int ch0 = tid * 2;
    #define LOAD_BUFH(kb, b) do {                                             \
        _Pragma("unroll")                                                     \
        for (int c = 0; c < 2; c++) {                                         \
            const int ch = ch0 + c;                                           \
            const int row = ch >> 2, sub = ch & 3;                            \
            const uint32_t dst = su + (b) * BUFBH + (uint32_t)row * 80u + sub * 16u; \
            const size_t asrc = (size_t)(m0 + row) * K + (kb) * 32 + sub * 8; \
            const size_t wsrc = (size_t)(n0 + row) * K + (kb) * 32 + sub * 8; \
            CP_ASYNC16(dst +    0, Af + asrc);                                \
            CP_ASYNC16(dst + MATB, Wf + wsrc);                                \
        }                                                                     \
    } while (0)

    LOAD_BUFH(0, 0);
    CP_COMMIT();
    LOAD_BUFH(1, 1);
    CP_COMMIT();

    int stage = 0;
    for (int kb = 0; kb < NKB; kb++) {
        if (kb + 1 < NKB) { CP_WAIT1(); } else { CP_WAIT0(); }
        __syncthreads();
        if (kb + 2 < NKB) {
            int ns = stage + 2; if (ns >= 3) ns -= 3;
            LOAD_BUFH(kb + 2, ns);
            CP_COMMIT();
        }

        const uint32_t sb = su + stage * BUFBH;
        #pragma unroll
        for (int ks = 0; ks < 2; ks++) {
            uint32_t af[4][4];
            uint32_t bh[2][4];
            #pragma unroll
            for (int mt = 0; mt < 4; mt++) {
                const uint32_t ra = sb + a_lrow + (uint32_t)mt * 16u * 80u + ks * 32u;
                LDSM_X4(af[mt][0], af[mt][1], af[mt][2], af[mt][3], ra);
            }
            #pragma unroll
            for (int np = 0; np < 2; np++) {
                const uint32_t rb = sb + MATB + b_lrow + (uint32_t)np * 16u * 80u + ks * 32u;
                LDSM_X4(bh[np][0], bh[np][1], bh[np][2], bh[np][3], rb);
            }
            #pragma unroll
            for (int mt = 0; mt < 4; mt++)
                #pragma unroll
                for (int nt = 0; nt < 4; nt++) {
                    const int np = nt >> 1, o = (nt & 1) * 2;
                    MMAH16816(acc[mt][nt], af[mt], bh[np][o], bh[np][o + 1]);
                }
        }
        stage++; if (stage >= 3) stage = 0;
    }

    const int qrow = lane >> 2, qcol = (lane & 3) * 2;
    #pragma unroll
    for (int mt = 0; mt < 4; mt++) {
        const int r0 = m0 + wm * 64 + mt * 16 + qrow;
        #pragma unroll
        for (int nt = 0; nt < 4; nt++) {
            const int c0 = n0 + wn * 32 + nt * 8 + qcol;
            float bx = 0.f, by = 0.f;
            if (mode & 1) { bx = bias[c0]; by = bias[c0 + 1]; }
            float2 v0 = make_float2(acc[mt][nt][0] + bx, acc[mt][nt][1] + by);
            float2 v1 = make_float2(acc[mt][nt][2] + bx, acc[mt][nt][3] + by);
            const size_t i0 = (size_t)r0 * ldc + c0;
            const size_t i1 = (size_t)(r0 + 8) * ldc + c0;
            if (mode & 2) {
                float2 r0v = *(const float2*)(res + i0);
                float2 r1v = *(const float2*)(res + i1);
                v0.x += r0v.x; v0.y += r0v.y;
                v1.x += r1v.x; v1.y += r1v.y;
            }
            if (mode & 4) {
                __half* Ch = (__half*)C;
                __half2 h0, h1;
                h0.x = __float2half(v0.x); h0.y = __float2half(v0.y);
                h1.x = __float2half(v1.x); h1.y = __float2half(v1.y);
                *(__half2*)(Ch + i0) = h0;
                *(__half2*)(Ch + i1) = h1;
            } else {
                *(float2*)(C + i0) = v0;
                *(float2*)(C + i1) = v1;
            }
        }
    }
    #undef LOAD_BUFH
}

// ---------------------------------------------------------------------------
// bf16 3-term split GEMM (dd projection only), 3-stage pipeline
// ---------------------------------------------------------------------------
__global__ __launch_bounds__(256, 1) void mma_gemm(
    const __nv_bfloat16* __restrict__ Ah, const __nv_bfloat16* __restrict__ Al,
    const __nv_bfloat16* __restrict__ Wh, const __nv_bfloat16* __restrict__ Wl,
    const float* __restrict__ bias, const float* __restrict__ res,
    float* __restrict__ C, int K, int NKB, int ldc, int mode)
{
    extern __shared__ char smem[];
    const uint32_t su = smem_u32(smem);
    const int tid = threadIdx.x;
    const int wid = tid >> 5, lane = tid & 31;
    const int wm = wid >> 2, wn = wid & 3;
    const int m0 = blockIdx.y * 128, n0 = blockIdx.x * 128;

    const uint32_t a_lrow = (uint32_t)(wm * 64 + (lane & 15)) * 80u + ((lane >> 4) * 16u);
    const uint32_t b_lrow = (uint32_t)(wn * 32 + ((lane >> 4) & 1) * 8 + (lane & 7)) * 80u
                          + (((lane >> 3) & 1) * 16u);

    float acc[4][4][4] = {};

    const int ch0 = tid * 2;
    #define LOAD_BUF(kb, b) do {                                              \
        _Pragma("unroll")                                                     \
        for (int c = 0; c < 2; c++) {                                         \
            const int ch = ch0 + c;                                           \
            const int row = ch >> 2, sub = ch & 3;                            \
            const uint32_t dst = su + (b) * BUFB + (uint32_t)row * 80u + sub * 16u; \
            const size_t asrc = (size_t)(m0 + row) * K + (kb) * 32 + sub * 8; \
            const size_t wsrc = (size_t)(n0 + row) * K + (kb) * 32 + sub * 8; \
            CP_ASYNC16(dst +        0, Ah + asrc);                            \
            CP_ASYNC16(dst +     MATB, Al + asrc);                            \
            CP_ASYNC16(dst + 2 * MATB, Wh + wsrc);                            \
            CP_ASYNC16(dst + 3 * MATB, Wl + wsrc);                            \
        }                                                                     \
    } while (0)

    LOAD_BUF(0, 0);
    CP_COMMIT();
    LOAD_BUF(1, 1);
    CP_COMMIT();

    int stage = 0;
    for (int kb = 0; kb < NKB; kb++) {
        if (kb + 1 < NKB) { CP_WAIT1(); } else { CP_WAIT0(); }
        __syncthreads();
        if (kb + 2 < NKB) {
            int ns = stage + 2; if (ns >= 3) ns -= 3;
            LOAD_BUF(kb + 2, ns);
            CP_COMMIT();
        }

        const uint32_t sb = su + stage * BUFB;
        #pragma unroll
        for (int ks = 0; ks < 2; ks++) {
            uint32_t ah[4][4], al[4][4];
            uint32_t bh[2][4], bl[2][4];
            #pragma unroll
            for (int mt = 0; mt < 4; mt++) {
                const uint32_t ra = sb + a_lrow + (uint32_t)mt * 16u * 80u + ks * 32u;
                LDSM_X4(ah[mt][0], ah[mt][1], ah[mt][2], ah[mt][3], ra);
                LDSM_X4(al[mt][0], al[mt][1], al[mt][2], al[mt][3], ra + MATB);
            }
            #pragma unroll
            for (int np = 0; np < 2; np++) {
                const uint32_t rb = sb + 2 * MATB + b_lrow + (uint32_t)np * 16u * 80u + ks * 32u;
                LDSM_X4(bh[np][0], bh[np][1], bh[np][2], bh[np][3], rb);
                LDSM_X4(bl[np][0], bl[np][1], bl[np][2], bl[np][3], rb + MATB);
            }
            #pragma unroll
            for (int mt = 0; mt < 4; mt++)
                #pragma unroll
                for (int nt = 0; nt < 4; nt++) {
                    const int np = nt >> 1, o = (nt & 1) * 2;
                    MMA16816(acc[mt][nt], ah[mt], bh[np][o], bh[np][o + 1]);
                    MMA16816(acc[mt][nt], ah[mt], bl[np][o], bl[np][o + 1]);
                    MMA16816(acc[mt][nt], al[mt], bh[np][o], bh[np][o + 1]);
                }
        }
        stage++; if (stage >= 3) stage = 0;
    }

    const int qrow = lane >> 2, qcol = (lane & 3) * 2;
    #pragma unroll
    for (int mt = 0; mt < 4; mt++) {
        const int r0 = m0 + wm * 64 + mt * 16 + qrow;
        #pragma unroll
        for (int nt = 0; nt < 4; nt++) {
            const int c0 = n0 + wn * 32 + nt * 8 + qcol;
            float bx = 0.f, by = 0.f;
            if (mode & 1) { bx = bias[c0]; by = bias[c0 + 1]; }
            float2 v0 = make_float2(acc[mt][nt][0] + bx, acc[mt][nt][1] + by);
            float2 v1 = make_float2(acc[mt][nt][2] + bx, acc[mt][nt][3] + by);
            const size_t i0 = (size_t)r0 * ldc + c0;
            const size_t i1 = (size_t)(r0 + 8) * ldc + c0;
            if (mode & 2) {
                float2 r0v = *(const float2*)(res + i0);
                float2 r1v = *(const float2*)(res + i1);
                v0.x += r0v.x; v0.y += r0v.y;
                v1.x += r1v.x; v1.y += r1v.y;
            }
            *(float2*)(C + i0) = v0;
            *(float2*)(C + i1) = v1;
        }
    }
    #undef LOAD_BUF
}

// ---------------------------------------------------------------------------
// mix: xmix fp32 + bf16 hi/lo split (dd GEMM input)
// ---------------------------------------------------------------------------
__global__ void mix_split_kernel(const float* __restrict__ x,
                                 const float* __restrict__ glin,
                                 float* __restrict__ xmix,
                                 __nv_bfloat16* __restrict__ oh,
                                 __nv_bfloat16* __restrict__ ol)
{
    const size_t i = (size_t)blockIdx.x * blockDim.x + threadIdx.x;
    const int row = (int)(i >> 8);
    const int t = row & (T_ - 1);
    float4 xv = *(const float4*)(x + i * 4);
    float4 gv = *(const float4*)(glin + i * 4);
    float4 pv = make_float4(0.f, 0.f, 0.f, 0.f);
    if (t > 0) pv = *(const float4*)(x + (i - 256) * 4);
    float o[4]; float g;
    g = 1.f / (1.f + __expf(-gv.x)); o[0] = (1.f - g) * xv.x + g * pv.x;
    g = 1.f / (1.f + __expf(-gv.y)); o[1] = (1.f - g) * xv.y + g * pv.y;
    g = 1.f / (1.f + __expf(-gv.z)); o[2] = (1.f - g) * xv.z + g * pv.z;
    g = 1.f / (1.f + __expf(-gv.w)); o[3] = (1.f - g) * xv.w + g * pv.w;
    *(float4*)(xmix + i * 4) = make_float4(o[0], o[1], o[2], o[3]);
    __nv_bfloat16 hb[4], lb[4];
    #pragma unroll
    for (int j = 0; j < 4; j++) {
        hb[j] = __float2bfloat16(o[j]);
        lb[j] = __float2bfloat16(o[j] - __bfloat162float(hb[j]));
    }
    *(uint2*)(oh + i * 4) = *(uint2*)hb;
    *(uint2*)(ol + i * 4) = *(uint2*)lb;
}

// ---------------------------------------------------------------------------
// RMSNorm -> single fp16 output
// ---------------------------------------------------------------------------
__global__ __launch_bounds__(256) void rmsnorm_half_kernel(
    const float* __restrict__ x, const float* __restrict__ w,
    __half* __restrict__ oh)
{
    const int row = blockIdx.x;
    const int tid = threadIdx.x;
    const float* xr = x + (size_t)row * D_;
    float4 v = *(const float4*)(xr + tid * 4);
    float s = v.x * v.x + v.y * v.y + v.z * v.z + v.w * v.w;
    #pragma unroll
    for (int m = 16; m > 0; m >>= 1) s += __shfl_xor_sync(0xffffffffu, s, m);
    __shared__ float red[8];
    if ((tid & 31) == 0) red[tid >> 5] = s;
    __syncthreads();
    if (tid < 32) {
        float t = (tid < 8) ? red[tid] : 0.f;
        #pragma unroll
        for (int m = 4; m > 0; m >>= 1) t += __shfl_xor_sync(0xffffffffu, t, m);
        if (tid == 0) red[0] = t;
    }
    __syncthreads();
    const float inv = rsqrtf(red[0] / (float)D_ + EPS_);
    float4 wv = *(const float4*)(w + tid * 4);
    __half hb[4] = { __float2half(v.x * inv * wv.x), __float2half(v.y * inv * wv.y),
                     __float2half(v.z * inv * wv.z), __float2half(v.w * inv * wv.w) };
    *(uint2*)(oh + (size_t)row * D_ + tid * 4) = *(uint2*)hb;
}

// ---------------------------------------------------------------------------
// 3-phase cumsum
// ---------------------------------------------------------------------------
__global__ void cumsumA(const float* __restrict__ dd, float* __restrict__ cs)
{
    const int c = threadIdx.x;
    const int blk = blockIdx.x;
    const int b = blk >> 4, ch = blk & 15;
    size_t base = ((size_t)b * T_ + ch * 128) * 256 + c;
    float s = 0.f;
    #pragma unroll 8
    for (int t = 0; t < 128; t++) { s += dd[base]; base += 256; }
    cs[(size_t)blk * 256 + c] = s;
}
__global__ void cumsumB(float* __restrict__ cs)
{
    const int c = threadIdx.x;
    const int b = blockIdx.x;
    float run = 0.f;
    #pragma unroll
    for (int ch = 0; ch < 16; ch++) {
        size_t i = ((size_t)b * 16 + ch) * 256 + c;
        float t = cs[i];
        cs[i] = run;
        run += t;
    }
}
__global__ void cumsumC(float* __restrict__ dd, const float* __restrict__ cs)
{
    const int c = threadIdx.x;
    const int blk = blockIdx.x;
    const int b = blk >> 4, ch = blk & 15;
    float acc = cs[(size_t)blk * 256 + c];
    size_t base = ((size_t)b * T_ + ch * 128) * 256 + c;
    #pragma unroll 8
    for (int t = 0; t < 128; t++) { acc += dd[base]; dd[base] = acc; base += 256; }
}

// ---------------------------------------------------------------------------
// q/k head rmsnorm + hybrid rope + head-major scatter
// ---------------------------------------------------------------------------
__global__ __launch_bounds__(256) void qkv_transform_kernel(
    const float* __restrict__ qkv, const float* __restrict__ ddcum,
    const float* __restrict__ rc, const float* __restrict__ rs,
    const float* __restrict__ qnw, const float* __restrict__ knw,
    const float* __restrict__ qpb, const float* __restrict__ kpb,
    float* __restrict__ qt, float* __restrict__ kt, float* __restrict__ vt)
{
    const int w = blockIdx.x * 8 + (threadIdx.x >> 5);
    const int lane = threadIdx.x & 31;
    const int b = w >> 15;
    const int rem = w & 32767;
    const int t = rem >> 4;
    const int h = rem & 15;

    const size_t base = ((size_t)(b * T_ + t) * 3) * D_ + h * DH_;
    float q0 = qkv[base + lane],          q1 = qkv[base + 32 + lane];
    float k0 = qkv[base + D_ + lane],     k1 = qkv[base + D_ + 32 + lane];
    float v0 = qkv[base + 2 * D_ + lane], v1 = qkv[base + 2 * D_ + 32 + lane];

    float sq = q0 * q0 + q1 * q1;
    float sk = k0 * k0 + k1 * k1;
    #pragma unroll
    for (int m = 16; m > 0; m >>= 1) {
        sq += __shfl_xor_sync(0xffffffffu, sq, m);
        sk += __shfl_xor_sync(0xffffffffu, sk, m);
    }
    const float rq = rsqrtf(sq / 64.f + EPS_);
    const float rk = rsqrtf(sk / 64.f + EPS_);
    q0 *= rq * qnw[lane] * qpb[lane];
    q1 *= rq * qnw[lane + 32] * qpb[lane + 32];
    k0 *= rk * knw[lane] * kpb[lane];
    k1 *= rk * knw[lane + 32] * kpb[lane + 32];

    const int j = lane & 15;
    const float c = rc[t * 32 + j], s = rs[t * 32 + j];
    const float ang = ddcum[((size_t)(b * T_ + t)) * 256 + h * 16 + j];
    float s2, c2;
    sincosf(ang, &s2, &c2);

    const float qp0 = __shfl_xor_sync(0xffffffffu, q0, 16);
    const float qp1 = __shfl_xor_sync(0xffffffffu, q1, 16);
    const float kp0 = __shfl_xor_sync(0xffffffffu, k0, 16);
    const float kp1 = __shfl_xor_sync(0xffffffffu, k1, 16);
    float oq0, oq1, ok0, ok1;
    if (lane < 16) {
        oq0 = q0 * c - qp0 * s;  oq1 = q1 * c2 - qp1 * s2;
        ok0 = k0 * c - kp0 * s;  ok1 = k1 * c2 - kp1 * s2;
    } else {
        oq0 = q0 * c + qp0 * s;  oq1 = q1 * c2 + qp1 * s2;
        ok0 = k0 * c + kp0 * s;  ok1 = k1 * c2 + kp1 * s2;
    }

    const size_t ob = ((size_t)(b * NH_ + h) * T_ + t) * DH_;
    qt[ob + lane] = oq0;  qt[ob + 32 + lane] = oq1;
    kt[ob + lane] = ok0;  kt[ob + 32 + lane] = ok1;
    vt[ob + lane] = v0;   vt[ob + 32 + lane] = v1;
}

// ---------------------------------------------------------------------------
// Flash attention (tf32 mma) -> single fp16 output; heavy tiles first
// ---------------------------------------------------------------------------
#define KS_OFF 0
#define VS_OFF (64 * 72)
#define PS_OFF (2 * 64 * 72)
#define FSMEM ((2 * 64 * 72 + 128 * 68) * 4)

__global__ __launch_bounds__(256, 1) void flash_tc(
    const float* __restrict__ qt, const float* __restrict__ kt,
    const float* __restrict__ vt, __half* __restrict__ yh)
{
    extern __shared__ uint32_t fsm[];
    uint32_t* Ks = fsm + KS_OFF;
    uint32_t* Vs = fsm + VS_OFF;
    uint32_t* Ps = fsm + PS_OFF;

    const int tid = threadIdx.x, lane = tid & 31, w = tid >> 5;
    const int bx = gridDim.x - 1 - blockIdx.x;     // heavy q-tiles first
    const int bh = blockIdx.y;
    const int b = bh >> 4, h = bh & 15;
    const int m0 = bx * 128;

    const float* Qb = qt + (size_t)bh * T_ * DH_;
    const float* Kb = kt + (size_t)bh * T_ * DH_;
    const float* Vb = vt + (size_t)bh * T_ * DH_;

    const int r1 = m0 + w * 16 + (lane >> 2);
    uint32_t qf[8][4];
    {
        const float* q1 = Qb + (size_t)r1 * DH_;
        const float* q2 = q1 + 8 * DH_;
        #pragma unroll
        for (int k8 = 0; k8 < 8; k8++) {
            const int c = k8 * 8 + (lane & 3);
            qf[k8][0] = f2tf(q1[c] * 0.125f);
            qf[k8][1] = f2tf(q2[c] * 0.125f);
            qf[k8][2] = f2tf(q1[c + 4] * 0.125f);
            qf[k8][3] = f2tf(q2[c + 4] * 0.125f);
        }
    }

    float mi[2] = { -1e30f, -1e30f }, li[2] = { 0.f, 0.f };
    float O[8][4] = {};

    const int ntiles = 2 * bx + 2;
    for (int nt = 0; nt < ntiles; nt++) {
        const int n0 = nt * 64;
        __syncthreads();
        {
            const int key = tid >> 2, db = (tid & 3) * 16;
            const float* kp = Kb + (size_t)(n0 + key) * DH_ + db;
            const float* vp = Vb + (size_t)(n0 + key) * DH_ + db;
            #pragma unroll
            for (int i = 0; i < 16; i += 4) {
                float4 kv = *(const float4*)(kp + i);
                Ks[(db + i + 0) * 72 + key] = f2tf(kv.x);
                Ks[(db + i + 1) * 72 + key] = f2tf(kv.y);
                Ks[(db + i + 2) * 72 + key] = f2tf(kv.z);
                Ks[(db + i + 3) * 72 + key] = f2tf(kv.w);
                float4 vv = *(const float4*)(vp + i);
                uint4 vo;
                vo.x = f2tf(vv.x); vo.y = f2tf(vv.y);
                vo.z = f2tf(vv.z); vo.w = f2tf(vv.w);
                *(uint4*)&Vs[key * 72 + db + i] = vo;
            }
        }
        __syncthreads();

        float S[8][4] = {};
        #pragma unroll
        for (int k8 = 0; k8 < 8; k8++) {
            const uint32_t* kr0 = &Ks[(k8 * 8 + (lane & 3)) * 72 + (lane >> 2)];
            const uint32_t* kr1 = kr0 + 4 * 72;
            #pragma unroll
            for (int n8 = 0; n8 < 8; n8++) {
                MMATF32(S[n8], qf[k8], kr0[n8 * 8], kr1[n8 * 8]);
            }
        }
        if (nt >= 2 * bx) {
            #pragma unroll
            for (int n8 = 0; n8 < 8; n8++) {
                const int cb = n0 + n8 * 8 + 2 * (lane & 3);
                if (cb     > r1)     S[n8][0] = -1e30f;
                if (cb + 1 > r1)     S[n8][1] = -1e30f;
                if (cb     > r1 + 8) S[n8][2] = -1e30f;
                if (cb + 1 > r1 + 8) S[n8][3] = -1e30f;
            }
        }
        #pragma unroll
        for (int half = 0; half < 2; half++) {
            float mx = -1e30f;
            #pragma unroll
            for (int n8 = 0; n8 < 8; n8++)
                mx = fmaxf(mx, fmaxf(S[n8][half * 2], S[n8][half * 2 + 1]));
            mx = fmaxf(mx, __shfl_xor_sync(0xffffffffu, mx, 1));
            mx = fmaxf(mx, __shfl_xor_sync(0xffffffffu, mx, 2));
            const float mnew = fmaxf(mi[half], mx);
            const float corr = __expf(mi[half] - mnew);
            float rsum = 0.f;
            #pragma unroll
            for (int n8 = 0; n8 < 8; n8++) {
                float e0 = __expf(S[n8][half * 2]     - mnew);
                float e1 = __expf(S[n8][half * 2 + 1] - mnew);
                S[n8][half * 2] = e0; S[n8][half * 2 + 1] = e1;
                rsum += e0 + e1;
            }
            rsum += __shfl_xor_sync(0xffffffffu, rsum, 1);
            rsum += __shfl_xor_sync(0xffffffffu, rsum, 2);
            li[half] = li[half] * corr + rsum;
            mi[half] = mnew;
            #pragma unroll
            for (int n8 = 0; n8 < 8; n8++) {
                O[n8][half * 2]     *= corr;
                O[n8][half * 2 + 1] *= corr;
            }
        }
        {
            const int pr = w * 16 + (lane >> 2);
            #pragma unroll
            for (int n8 = 0; n8 < 8; n8++) {
                const int pc = n8 * 8 + 2 * (lane & 3);
                uint2 p0, p1;
                p0.x = f2tf(S[n8][0]); p0.y = f2tf(S[n8][1]);
                p1.x = f2tf(S[n8][2]); p1.y = f2tf(S[n8][3]);
                *(uint2*)&Ps[pr * 68 + pc]       = p0;
                *(uint2*)&Ps[(pr + 8) * 68 + pc] = p1;
            }
        }
        __syncwarp();
        #pragma unroll
        for (int k8 = 0; k8 < 8; k8++) {
            uint32_t a[4];
            const int pr = w * 16 + (lane >> 2);
            const int pc = k8 * 8 + (lane & 3);
            a[0] = Ps[pr * 68 + pc];
            a[1] = Ps[(pr + 8) * 68 + pc];
            a[2] = Ps[pr * 68 + pc + 4];
            a[3] = Ps[(pr + 8) * 68 + pc + 4];
            const uint32_t* vr0 = &Vs[(k8 * 8 + (lane & 3)) * 72 + (lane >> 2)];
            const uint32_t* vr1 = vr0 + 4 * 72;
            #pragma unroll
            for (int n8 = 0; n8 < 8; n8++) {
                MMATF32(O[n8], a, vr0[n8 * 8], vr1[n8 * 8]);
            }
        }
    }

    const float inv0 = 1.f / li[0], inv1 = 1.f / li[1];
    const size_t o1 = ((size_t)(b * T_ + r1)) * D_ + h * DH_ + 2 * (lane & 3);
    const size_t o2 = o1 + 8 * D_;
    #pragma unroll
    for (int n8 = 0; n8 < 8; n8++) {
        __half2 h0, h1;
        h0.x = __float2half(O[n8][0] * inv0); h0.y = __float2half(O[n8][1] * inv0);
        h1.x = __float2half(O[n8][2] * inv1); h1.y = __float2half(O[n8][3] * inv1);
        *(__half2*)(yh + o1 + n8 * 8) = h0;
        *(__half2*)(yh + o2 + n8 * 8) = h1;
    }
}

// ---------------------------------------------------------------------------
// act = silu(gate)*up from fp16 combined [M, 2*FFNP] -> fp16 [M, FFNP]
// ---------------------------------------------------------------------------
__global__ void act_half_kernel(const __half* __restrict__ gu,
                                __half* __restrict__ oh)
{
    const size_t idx4 = (size_t)blockIdx.x * blockDim.x + threadIdx.x;
    const int row = (int)(idx4 / (FFNP / 4));
    const int c = (int)(idx4 % (FFNP / 4)) * 4;
    const __half* gp = gu + (size_t)row * (2 * FFNP) + c;
    __half gh[4], uh[4];
    *(uint2*)gh = *(const uint2*)gp;
    *(uint2*)uh = *(const uint2*)(gp + FFNP);
    __half hb[4];
    #pragma unroll
    for (int j = 0; j < 4; j++) {
        float g = __half2float(gh[j]);
        float u = __half2float(uh[j]);
        hb[j] = __float2half(g / (1.f + __expf(-g)) * u);
    }
    *(uint2*)(oh + (size_t)row * FFNP + c) = *(uint2*)hb;
}

// ---------------------------------------------------------------------------
// Launch
// ---------------------------------------------------------------------------
static inline int cdiv(long long a, long long b) { return (int)((a + b - 1) / b); }

extern "C" void kernel_launch(void* const* d_in, const int* in_sizes, int n_in,
                              void* d_out, int out_size)
{
    const float* x     = (const float*)d_in[0];
    const float* rc    = (const float*)d_in[1];
    const float* rs    = (const float*)d_in[2];
    const float* lerpw = (const float*)d_in[3];
    const float* lerpb = (const float*)d_in[4];
    const float* anw   = (const float*)d_in[5];
    const float* wqkv  = (const float*)d_in[6];
    const float* qnw   = (const float*)d_in[7];
    const float* knw   = (const float*)d_in[8];
    const float* qpb   = (const float*)d_in[9];
    const float* kpb   = (const float*)d_in[10];
    const float* ddw   = (const float*)d_in[11];
    const float* ddb   = (const float*)d_in[12];
    const float* wo    = (const float*)d_in[13];
    const float* mnw   = (const float*)d_in[14];
    const float* gw    = (const float*)d_in[15];
    const float* uw    = (const float*)d_in[16];
    const float* dw    = (const float*)d_in[17];
    float* out = (float*)d_out;

    float *glin, *xmix, *qkv, *dd, *cs, *qt, *kt, *vt, *x2;
    __half *guh;
    __nv_bfloat16 *ah, *al, *wh, *wl;
    __half *af, *wf;
    cudaGetSymbolAddress((void**)&glin, s_glin);
    cudaGetSymbolAddress((void**)&xmix, s_xmix);
    cudaGetSymbolAddress((void**)&qkv,  s_qkv);
    cudaGetSymbolAddress((void**)&dd,   s_dd);
    cudaGetSymbolAddress((void**)&cs,   s_csum);
    cudaGetSymbolAddress((void**)&qt,   s_qt);
    cudaGetSymbolAddress((void**)&kt,   s_kt);
    cudaGetSymbolAddress((void**)&vt,   s_vt);
    cudaGetSymbolAddress((void**)&x2,   s_x2);
    cudaGetSymbolAddress((void**)&guh,  s_guh);
    cudaGetSymbolAddress((void**)&ah,   g_ah);
    cudaGetSymbolAddress((void**)&al,   g_al);
    cudaGetSymbolAddress((void**)&wh,   g_wh);
    cudaGetSymbolAddress((void**)&wl,   g_wl);
    cudaGetSymbolAddress((void**)&af,   g_af);
    cudaGetSymbolAddress((void**)&wf,   g_wf);

    cudaFuncSetAttribute(mma_gemm,
                         cudaFuncAttributeMaxDynamicSharedMemorySize, 3 * BUFB);
    cudaFuncSetAttribute(mma_gemm_h,
                         cudaFuncAttributeMaxDynamicSharedMemorySize, 3 * BUFBH);
    cudaFuncSetAttribute(flash_tc,
                         cudaFuncAttributeMaxDynamicSharedMemorySize, FSMEM);

    const dim3 blk(256);
    const int GSM  = 3 * BUFB;    // 122880
    const int GSMH = 3 * BUFBH;   // 61440

    #define CONVH(src, d, n) \
        conv_half<<<(int)(((long long)(n) / 4) / 256), blk>>>(src, d)
    #define CONVW(src, d, r, c, rp, cp) \
        conv_whalf<<<cdiv((long long)(rp) * (cp), 256), blk>>>(src, d, r, c, rp, cp)

    // 1. glin = x @ lerp_w^T + lerp_b
    CONVH(x, af, (long long)M_ * D_);
    CONVW(lerpw, wf, D_, D_, D_, D_);
    mma_gemm_h<<<dim3(8, 32), blk, GSMH>>>(af, wf, lerpb, nullptr, glin, D_, 32, D_, 1);
    // 2. xmix (fp32 + bf16 split for dd)
    mix_split_kernel<<<(M_ * D_ / 4) / 256, blk>>>(x, glin, xmix, ah, al);
    // 3. dd = xmix @ dd_w^T + dd_b (bf16 3-term)
    convsplit<<<cdiv(256LL * D_, 256), blk>>>(ddw, wh, wl, 256, D_, 256, D_);
    mma_gemm<<<dim3(2, 32), blk, GSM>>>(ah, al, wh, wl, ddb, nullptr, dd, D_, 32, 256, 1);
    // 4. cumsum along T
    cumsumA<<<B_ * 16, blk>>>(dd, cs);
    cumsumB<<<B_, blk>>>(cs);
    cumsumC<<<B_ * 16, blk>>>(dd, cs);
    // 5. h = rmsnorm(xmix) -> fp16
    rmsnorm_half_kernel<<<M_, blk>>>(xmix, anw, af);
    // 6. qkv = h @ w_qkv^T
    CONVW(wqkv, wf, 3 * D_, D_, 3 * D_, D_);
    mma_gemm_h<<<dim3(24, 32), blk, GSMH>>>(af, wf, nullptr, nullptr, qkv, D_, 32, 3 * D_, 0);
    // 7. q/k transform
    qkv_transform_kernel<<<(B_ * T_ * NH_) / 8, blk>>>(qkv, dd, rc, rs, qnw, knw,
                                                       qpb, kpb, qt, kt, vt);
    // 8. flash attention (tf32) -> y fp16
    flash_tc<<<dim3(T_ / 128, B_ * NH_), blk, FSMEM>>>(qt, kt, vt, af);
    // 9. x2 = xmix + y @ w_o^T
    CONVW(wo, wf, D_, D_, D_, D_);
    mma_gemm_h<<<dim3(8, 32), blk, GSMH>>>(af, wf, nullptr, xmix, x2, D_, 32, D_, 2);
    // 10. h = rmsnorm(x2) -> fp16
    rmsnorm_half_kernel<<<M_, blk>>>(x2, mnw, af);
    // 11. combined gate|up GEMM: N = 2*FFNP = 5632, fp16 output
    CONVW(gw, wf, FFN_, D_, FFNP, D_);
    conv_whalf<<<cdiv((long long)FFNP * D_, 256), blk>>>(uw, wf + (size_t)FFNP * D_,
                                                         FFN_, D_, FFNP, D_);
    mma_gemm_h<<<dim3(44, 32), blk, GSMH>>>(af, wf, nullptr, nullptr,
                                            (float*)guh, D_, 32, 2 * FFNP, 4);
    // 12. act = silu(gate)*up -> fp16
    act_half_kernel<<<(M_ * FFNP / 4) / 256, blk>>>(guh, af);
    // 13. out = x2 + act @ down_w^T
    CONVW(dw, wf, D_, FFN_, D_, FFNP);
    mma_gemm_h<<<dim3(8, 32), blk, GSMH>>>(af, wf, nullptr, x2, out, FFNP, 88, D_, 2);
}

// round 10
// speedup vs baseline: 2.7916x; 1.1962x over previous
#include <cuda_runtime.h>
#include <cuda_bf16.h>
#include <cuda_fp16.h>
#include <math.h>
#include <stdint.h>

// ---------------------------------------------------------------------------
// Problem constants
// ---------------------------------------------------------------------------
#define B_   2
#define T_   2048
#define D_   1024
#define NH_  16
#define DH_  64
#define FFN_ 2736
#define FFNP 2816
#define M_   (B_ * T_)
#define EPS_ 1e-6f

// ---------------------------------------------------------------------------
// PTX helpers (arch-generic, sm_80+)
// ---------------------------------------------------------------------------
__device__ __forceinline__ uint32_t smem_u32(const void* p) {
    uint32_t a;
    asm("{ .reg .u64 t; cvta.to.shared.u64 t, %1; cvt.u32.u64 %0, t; }"
        : "=r"(a) : "l"(p));
    return a;
}
#define CP_ASYNC16(dst, src) \
    asm volatile("cp.async.cg.shared.global [%0], [%1], 16;" :: "r"(dst), "l"(src))
#define CP_COMMIT() asm volatile("cp.async.commit_group;" ::: "memory")
#define CP_WAIT0()  asm volatile("cp.async.wait_group 0;" ::: "memory")
#define CP_WAIT1()  asm volatile("cp.async.wait_group 1;" ::: "memory")
#define LDSM_X4(r0, r1, r2, r3, addr) \
    asm volatile("ldmatrix.sync.aligned.m8n8.x4.shared.b16 {%0,%1,%2,%3}, [%4];" \
                 : "=r"(r0), "=r"(r1), "=r"(r2), "=r"(r3) : "r"(addr))
#define MMA16816(d, a, b0, b1) \
    asm volatile("mma.sync.aligned.m16n8k16.row.col.f32.bf16.bf16.f32 " \
                 "{%0,%1,%2,%3},{%4,%5,%6,%7},{%8,%9},{%0,%1,%2,%3};" \
                 : "+f"((d)[0]), "+f"((d)[1]), "+f"((d)[2]), "+f"((d)[3]) \
                 : "r"((a)[0]), "r"((a)[1]), "r"((a)[2]), "r"((a)[3]), \
                   "r"(b0), "r"(b1))
#define MMAH16816(d, a, b0, b1) \
    asm volatile("mma.sync.aligned.m16n8k16.row.col.f32.f16.f16.f32 " \
                 "{%0,%1,%2,%3},{%4,%5,%6,%7},{%8,%9},{%0,%1,%2,%3};" \
                 : "+f"((d)[0]), "+f"((d)[1]), "+f"((d)[2]), "+f"((d)[3]) \
                 : "r"((a)[0]), "r"((a)[1]), "r"((a)[2]), "r"((a)[3]), \
                   "r"(b0), "r"(b1))
__device__ __forceinline__ uint32_t h2bits(float a, float b) {
    __half2 t = __floats2half2_rn(a, b);
    return *(uint32_t*)&t;
}

// ---------------------------------------------------------------------------
// Device scratch
// ---------------------------------------------------------------------------
__device__ float s_glin[M_ * D_];
__device__ float s_xmix[M_ * D_];
__device__ float s_dd  [M_ * NH_ * 16];
__device__ float s_csum[B_ * 16 * 256];
__device__ float s_x2  [M_ * D_];
__device__ __half s_qkvh[(size_t)M_ * 3 * D_];
__device__ __half s_qth [B_ * NH_ * T_ * DH_];
__device__ __half s_kth [B_ * NH_ * T_ * DH_];
__device__ __half s_vth [B_ * NH_ * T_ * DH_];
__device__ __half s_guh [(size_t)M_ * 2 * FFNP];
// bf16 split buffers (dd path only)
__device__ __nv_bfloat16 g_ah[(size_t)M_ * D_];
__device__ __nv_bfloat16 g_al[(size_t)M_ * D_];
__device__ __nv_bfloat16 g_wh[256 * D_];
__device__ __nv_bfloat16 g_wl[256 * D_];
// fp16 buffers (main GEMM path)
__device__ __half g_af[(size_t)M_ * FFNP];
__device__ __half g_wf[(size_t)2 * FFNP * D_];

// ---------------------------------------------------------------------------
// conversions
// ---------------------------------------------------------------------------
__global__ void convsplit(const float* __restrict__ src,
                          __nv_bfloat16* __restrict__ h,
                          __nv_bfloat16* __restrict__ l,
                          int rows, int cols, int rows_pad, int cols_pad)
{
    size_t i = (size_t)blockIdx.x * blockDim.x + threadIdx.x;
    size_t total = (size_t)rows_pad * cols_pad;
    if (i >= total) return;
    int r = (int)(i / cols_pad);
    int c = (int)(i - (size_t)r * cols_pad);
    float v = (r < rows && c < cols) ? src[(size_t)r * cols + c] : 0.f;
    __nv_bfloat16 hi = __float2bfloat16(v);
    h[i] = hi;
    l[i] = __float2bfloat16(v - __bfloat162float(hi));
}

__global__ void conv_whalf(const float* __restrict__ src,
                           __half* __restrict__ d,
                           int rows, int cols, int rows_pad, int cols_pad)
{
    size_t i = (size_t)blockIdx.x * blockDim.x + threadIdx.x;
    size_t total = (size_t)rows_pad * cols_pad;
    if (i >= total) return;
    int r = (int)(i / cols_pad);
    int c = (int)(i - (size_t)r * cols_pad);
    float v = (r < rows && c < cols) ? src[(size_t)r * cols + c] : 0.f;
    d[i] = __float2half(v);
}

__global__ void conv_half(const float* __restrict__ src, __half* __restrict__ d)
{
    size_t i = ((size_t)blockIdx.x * blockDim.x + threadIdx.x) * 4;
    float4 v = *(const float4*)(src + i);
    __half hb[4] = { __float2half(v.x), __float2half(v.y),
                     __float2half(v.z), __float2half(v.w) };
    *(uint2*)(d + i) = *(uint2*)hb;
}

// ---------------------------------------------------------------------------
// fp16 GEMM (A fp16, W fp16): C = A @ W^T (+bias)(+res); mode&4: fp16 out
// CTA 128x128, BK=32, 3-stage pipeline, 2 CTAs/SM.
// ---------------------------------------------------------------------------
#define MATB  10240
#define BUFB  (4 * MATB)
#define BUFBH (2 * MATB)

__global__ __launch_bounds__(256, 2) void mma_gemm_h(
    const __half* __restrict__ Af, const __half* __restrict__ Wf,
    const float* __restrict__ bias, const float* __restrict__ res,
    float* __restrict__ C, int K, int NKB, int ldc, int mode)
{
    extern __shared__ char smem[];
    const uint32_t su = smem_u32(smem);
    const int tid = threadIdx.x;
    const int wid = tid >> 5, lane = tid & 31;
    const int wm = wid >> 2, wn = wid & 3;
    const int m0 = blockIdx.y * 128, n0 = blockIdx.x * 128;

    const uint32_t a_lrow = (uint32_t)(wm * 64 + (lane & 15)) * 80u + ((lane >> 4) * 16u);
    const uint32_t b_lrow = (uint32_t)(wn * 32 + ((lane >> 4) & 1) * 8 + (lane & 7)) * 80u
                          + (((lane >> 3) & 1) * 16u);

    float acc[4][4][4] = {};

    const int ch0 = tid * 2;
    #define LOAD_BUFH(kb, b) do {                                             \
        _Pragma("unroll")                                                     \
        for (int c = 0; c < 2; c++) {                                         \
            const int ch = ch0 + c;                                           \
            const int row = ch >> 2, sub = ch & 3;                            \
            const uint32_t dst = su + (b) * BUFBH + (uint32_t)row * 80u + sub * 16u; \
            const size_t asrc = (size_t)(m0 + row) * K + (kb) * 32 + sub * 8; \
            const size_t wsrc = (size_t)(n0 + row) * K + (kb) * 32 + sub * 8; \
            CP_ASYNC16(dst +    0, Af + asrc);                                \
            CP_ASYNC16(dst + MATB, Wf + wsrc);                                \
        }                                                                     \
    } while (0)

    LOAD_BUFH(0, 0);
    CP_COMMIT();
    LOAD_BUFH(1, 1);
    CP_COMMIT();

    int stage = 0;
    for (int kb = 0; kb < NKB; kb++) {
        if (kb + 1 < NKB) { CP_WAIT1(); } else { CP_WAIT0(); }
        __syncthreads();
        if (kb + 2 < NKB) {
            int ns = stage + 2; if (ns >= 3) ns -= 3;
            LOAD_BUFH(kb + 2, ns);
            CP_COMMIT();
        }

        const uint32_t sb = su + stage * BUFBH;
        #pragma unroll
        for (int ks = 0; ks < 2; ks++) {
            uint32_t af[4][4];
            uint32_t bh[2][4];
            #pragma unroll
            for (int mt = 0; mt < 4; mt++) {
                const uint32_t ra = sb + a_lrow + (uint32_t)mt * 16u * 80u + ks * 32u;
                LDSM_X4(af[mt][0], af[mt][1], af[mt][2], af[mt][3], ra);
            }
            #pragma unroll
            for (int np = 0; np < 2; np++) {
                const uint32_t rb = sb + MATB + b_lrow + (uint32_t)np * 16u * 80u + ks * 32u;
                LDSM_X4(bh[np][0], bh[np][1], bh[np][2], bh[np][3], rb);
            }
            #pragma unroll
            for (int mt = 0; mt < 4; mt++)
                #pragma unroll
                for (int nt = 0; nt < 4; nt++) {
                    const int np = nt >> 1, o = (nt & 1) * 2;
                    MMAH16816(acc[mt][nt], af[mt], bh[np][o], bh[np][o + 1]);
                }
        }
        stage++; if (stage >= 3) stage = 0;
    }

    const int qrow = lane >> 2, qcol = (lane & 3) * 2;
    #pragma unroll
    for (int mt = 0; mt < 4; mt++) {
        const int r0 = m0 + wm * 64 + mt * 16 + qrow;
        #pragma unroll
        for (int nt = 0; nt < 4; nt++) {
            const int c0 = n0 + wn * 32 + nt * 8 + qcol;
            float bx = 0.f, by = 0.f;
            if (mode & 1) { bx = bias[c0]; by = bias[c0 + 1]; }
            float2 v0 = make_float2(acc[mt][nt][0] + bx, acc[mt][nt][1] + by);
            float2 v1 = make_float2(acc[mt][nt][2] + bx, acc[mt][nt][3] + by);
            const size_t i0 = (size_t)r0 * ldc + c0;
            const size_t i1 = (size_t)(r0 + 8) * ldc + c0;
            if (mode & 2) {
                float2 r0v = *(const float2*)(res + i0);
                float2 r1v = *(const float2*)(res + i1);
                v0.x += r0v.x; v0.y += r0v.y;
                v1.x += r1v.x; v1.y += r1v.y;
            }
            if (mode & 4) {
                __half* Ch = (__half*)C;
                __half2 h0, h1;
                h0.x = __float2half(v0.x); h0.y = __float2half(v0.y);
                h1.x = __float2half(v1.x); h1.y = __float2half(v1.y);
                *(__half2*)(Ch + i0) = h0;
                *(__half2*)(Ch + i1) = h1;
            } else {
                *(float2*)(C + i0) = v0;
                *(float2*)(C + i1) = v1;
            }
        }
    }
    #undef LOAD_BUFH
}

// ---------------------------------------------------------------------------
// bf16 3-term split GEMM (dd projection only)
// ---------------------------------------------------------------------------
__global__ __launch_bounds__(256, 1) void mma_gemm(
    const __nv_bfloat16* __restrict__ Ah, const __nv_bfloat16* __restrict__ Al,
    const __nv_bfloat16* __restrict__ Wh, const __nv_bfloat16* __restrict__ Wl,
    const float* __restrict__ bias, const float* __restrict__ res,
    float* __restrict__ C, int K, int NKB, int ldc, int mode)
{
    extern __shared__ char smem[];
    const uint32_t su = smem_u32(smem);
    const int tid = threadIdx.x;
    const int wid = tid >> 5, lane = tid & 31;
    const int wm = wid >> 2, wn = wid & 3;
    const int m0 = blockIdx.y * 128, n0 = blockIdx.x * 128;

    const uint32_t a_lrow = (uint32_t)(wm * 64 + (lane & 15)) * 80u + ((lane >> 4) * 16u);
    const uint32_t b_lrow = (uint32_t)(wn * 32 + ((lane >> 4) & 1) * 8 + (lane & 7)) * 80u
                          + (((lane >> 3) & 1) * 16u);

    float acc[4][4][4] = {};

    const int ch0 = tid * 2;
    #define LOAD_BUF(kb, b) do {                                              \
        _Pragma("unroll")                                                     \
        for (int c = 0; c < 2; c++) {                                         \
            const int ch = ch0 + c;                                           \
            const int row = ch >> 2, sub = ch & 3;                            \
            const uint32_t dst = su + (b) * BUFB + (uint32_t)row * 80u + sub * 16u; \
            const size_t asrc = (size_t)(m0 + row) * K + (kb) * 32 + sub * 8; \
            const size_t wsrc = (size_t)(n0 + row) * K + (kb) * 32 + sub * 8; \
            CP_ASYNC16(dst +        0, Ah + asrc);                            \
            CP_ASYNC16(dst +     MATB, Al + asrc);                            \
            CP_ASYNC16(dst + 2 * MATB, Wh + wsrc);                            \
            CP_ASYNC16(dst + 3 * MATB, Wl + wsrc);                            \
        }                                                                     \
    } while (0)

    LOAD_BUF(0, 0);
    CP_COMMIT();
    LOAD_BUF(1, 1);
    CP_COMMIT();

    int stage = 0;
    for (int kb = 0; kb < NKB; kb++) {
        if (kb + 1 < NKB) { CP_WAIT1(); } else { CP_WAIT0(); }
        __syncthreads();
        if (kb + 2 < NKB) {
            int ns = stage + 2; if (ns >= 3) ns -= 3;
            LOAD_BUF(kb + 2, ns);
            CP_COMMIT();
        }

        const uint32_t sb = su + stage * BUFB;
        #pragma unroll
        for (int ks = 0; ks < 2; ks++) {
            uint32_t ah[4][4], al[4][4];
            uint32_t bh[2][4], bl[2][4];
            #pragma unroll
            for (int mt = 0; mt < 4; mt++) {
                const uint32_t ra = sb + a_lrow + (uint32_t)mt * 16u * 80u + ks * 32u;
                LDSM_X4(ah[mt][0], ah[mt][1], ah[mt][2], ah[mt][3], ra);
                LDSM_X4(al[mt][0], al[mt][1], al[mt][2], al[mt][3], ra + MATB);
            }
            #pragma unroll
            for (int np = 0; np < 2; np++) {
                const uint32_t rb = sb + 2 * MATB + b_lrow + (uint32_t)np * 16u * 80u + ks * 32u;
                LDSM_X4(bh[np][0], bh[np][1], bh[np][2], bh[np][3], rb);
                LDSM_X4(bl[np][0], bl[np][1], bl[np][2], bl[np][3], rb + MATB);
            }
            #pragma unroll
            for (int mt = 0; mt < 4; mt++)
                #pragma unroll
                for (int nt = 0; nt < 4; nt++) {
                    const int np = nt >> 1, o = (nt & 1) * 2;
                    MMA16816(acc[mt][nt], ah[mt], bh[np][o], bh[np][o + 1]);
                    MMA16816(acc[mt][nt], ah[mt], bl[np][o], bl[np][o + 1]);
                    MMA16816(acc[mt][nt], al[mt], bh[np][o], bh[np][o + 1]);
                }
        }
        stage++; if (stage >= 3) stage = 0;
    }

    const int qrow = lane >> 2, qcol = (lane & 3) * 2;
    #pragma unroll
    for (int mt = 0; mt < 4; mt++) {
        const int r0 = m0 + wm * 64 + mt * 16 + qrow;
        #pragma unroll
        for (int nt = 0; nt < 4; nt++) {
            const int c0 = n0 + wn * 32 + nt * 8 + qcol;
            float bx = 0.f, by = 0.f;
            if (mode & 1) { bx = bias[c0]; by = bias[c0 + 1]; }
            float2 v0 = make_float2(acc[mt][nt][0] + bx, acc[mt][nt][1] + by);
            float2 v1 = make_float2(acc[mt][nt][2] + bx, acc[mt][nt][3] + by);
            const size_t i0 = (size_t)r0 * ldc + c0;
            const size_t i1 = (size_t)(r0 + 8) * ldc + c0;
            if (mode & 2) {
                float2 r0v = *(const float2*)(res + i0);
                float2 r1v = *(const float2*)(res + i1);
                v0.x += r0v.x; v0.y += r0v.y;
                v1.x += r1v.x; v1.y += r1v.y;
            }
            *(float2*)(C + i0) = v0;
            *(float2*)(C + i1) = v1;
        }
    }
    #undef LOAD_BUF
}

// ---------------------------------------------------------------------------
// mix: xmix fp32 + bf16 hi/lo split (dd GEMM input)
// ---------------------------------------------------------------------------
__global__ void mix_split_kernel(const float* __restrict__ x,
                                 const float* __restrict__ glin,
                                 float* __restrict__ xmix,
                                 __nv_bfloat16* __restrict__ oh,
                                 __nv_bfloat16* __restrict__ ol)
{
    const size_t i = (size_t)blockIdx.x * blockDim.x + threadIdx.x;
    const int row = (int)(i >> 8);
    const int t = row & (T_ - 1);
    float4 xv = *(const float4*)(x + i * 4);
    float4 gv = *(const float4*)(glin + i * 4);
    float4 pv = make_float4(0.f, 0.f, 0.f, 0.f);
    if (t > 0) pv = *(const float4*)(x + (i - 256) * 4);
    float o[4]; float g;
    g = 1.f / (1.f + __expf(-gv.x)); o[0] = (1.f - g) * xv.x + g * pv.x;
    g = 1.f / (1.f + __expf(-gv.y)); o[1] = (1.f - g) * xv.y + g * pv.y;
    g = 1.f / (1.f + __expf(-gv.z)); o[2] = (1.f - g) * xv.z + g * pv.z;
    g = 1.f / (1.f + __expf(-gv.w)); o[3] = (1.f - g) * xv.w + g * pv.w;
    *(float4*)(xmix + i * 4) = make_float4(o[0], o[1], o[2], o[3]);
    __nv_bfloat16 hb[4], lb[4];
    #pragma unroll
    for (int j = 0; j < 4; j++) {
        hb[j] = __float2bfloat16(o[j]);
        lb[j] = __float2bfloat16(o[j] - __bfloat162float(hb[j]));
    }
    *(uint2*)(oh + i * 4) = *(uint2*)hb;
    *(uint2*)(ol + i * 4) = *(uint2*)lb;
}

// ---------------------------------------------------------------------------
// RMSNorm -> single fp16 output
// ---------------------------------------------------------------------------
__global__ __launch_bounds__(256) void rmsnorm_half_kernel(
    const float* __restrict__ x, const float* __restrict__ w,
    __half* __restrict__ oh)
{
    const int row = blockIdx.x;
    const int tid = threadIdx.x;
    const float* xr = x + (size_t)row * D_;
    float4 v = *(const float4*)(xr + tid * 4);
    float s = v.x * v.x + v.y * v.y + v.z * v.z + v.w * v.w;
    #pragma unroll
    for (int m = 16; m > 0; m >>= 1) s += __shfl_xor_sync(0xffffffffu, s, m);
    __shared__ float red[8];
    if ((tid & 31) == 0) red[tid >> 5] = s;
    __syncthreads();
    if (tid < 32) {
        float t = (tid < 8) ? red[tid] : 0.f;
        #pragma unroll
        for (int m = 4; m > 0; m >>= 1) t += __shfl_xor_sync(0xffffffffu, t, m);
        if (tid == 0) red[0] = t;
    }
    __syncthreads();
    const float inv = rsqrtf(red[0] / (float)D_ + EPS_);
    float4 wv = *(const float4*)(w + tid * 4);
    __half hb[4] = { __float2half(v.x * inv * wv.x), __float2half(v.y * inv * wv.y),
                     __float2half(v.z * inv * wv.z), __float2half(v.w * inv * wv.w) };
    *(uint2*)(oh + (size_t)row * D_ + tid * 4) = *(uint2*)hb;
}

// ---------------------------------------------------------------------------
// 3-phase cumsum
// ---------------------------------------------------------------------------
__global__ void cumsumA(const float* __restrict__ dd, float* __restrict__ cs)
{
    const int c = threadIdx.x;
    const int blk = blockIdx.x;
    const int b = blk >> 4, ch = blk & 15;
    size_t base = ((size_t)b * T_ + ch * 128) * 256 + c;
    float s = 0.f;
    #pragma unroll 8
    for (int t = 0; t < 128; t++) { s += dd[base]; base += 256; }
    cs[(size_t)blk * 256 + c] = s;
}
__global__ void cumsumB(float* __restrict__ cs)
{
    const int c = threadIdx.x;
    const int b = blockIdx.x;
    float run = 0.f;
    #pragma unroll
    for (int ch = 0; ch < 16; ch++) {
        size_t i = ((size_t)b * 16 + ch) * 256 + c;
        float t = cs[i];
        cs[i] = run;
        run += t;
    }
}
__global__ void cumsumC(float* __restrict__ dd, const float* __restrict__ cs)
{
    const int c = threadIdx.x;
    const int blk = blockIdx.x;
    const int b = blk >> 4, ch = blk & 15;
    float acc = cs[(size_t)blk * 256 + c];
    size_t base = ((size_t)b * T_ + ch * 128) * 256 + c;
    #pragma unroll 8
    for (int t = 0; t < 128; t++) { acc += dd[base]; dd[base] = acc; base += 256; }
}

// ---------------------------------------------------------------------------
// q/k head rmsnorm + hybrid rope + head-major scatter (fp16 in/out)
// q output pre-scaled by 1/sqrt(DH) for flash.
// ---------------------------------------------------------------------------
__global__ __launch_bounds__(256) void qkv_transform_h(
    const __half* __restrict__ qkv, const float* __restrict__ ddcum,
    const float* __restrict__ rc, const float* __restrict__ rs,
    const float* __restrict__ qnw, const float* __restrict__ knw,
    const float* __restrict__ qpb, const float* __restrict__ kpb,
    __half* __restrict__ qt, __half* __restrict__ kt, __half* __restrict__ vt)
{
    const int w = blockIdx.x * 8 + (threadIdx.x >> 5);
    const int lane = threadIdx.x & 31;
    const int b = w >> 15;
    const int rem = w & 32767;
    const int t = rem >> 4;
    const int h = rem & 15;

    const size_t base = ((size_t)(b * T_ + t) * 3) * D_ + h * DH_;
    float q0 = __half2float(qkv[base + lane]);
    float q1 = __half2float(qkv[base + 32 + lane]);
    float k0 = __half2float(qkv[base + D_ + lane]);
    float k1 = __half2float(qkv[base + D_ + 32 + lane]);
    __half v0 = qkv[base + 2 * D_ + lane];
    __half v1 = qkv[base + 2 * D_ + 32 + lane];

    float sq = q0 * q0 + q1 * q1;
    float sk = k0 * k0 + k1 * k1;
    #pragma unroll
    for (int m = 16; m > 0; m >>= 1) {
        sq += __shfl_xor_sync(0xffffffffu, sq, m);
        sk += __shfl_xor_sync(0xffffffffu, sk, m);
    }
    const float rq = rsqrtf(sq / 64.f + EPS_);
    const float rk = rsqrtf(sk / 64.f + EPS_);
    q0 *= rq * qnw[lane] * qpb[lane];
    q1 *= rq * qnw[lane + 32] * qpb[lane + 32];
    k0 *= rk * knw[lane] * kpb[lane];
    k1 *= rk * knw[lane + 32] * kpb[lane + 32];

    const int j = lane & 15;
    const float c = rc[t * 32 + j], s = rs[t * 32 + j];
    const float ang = ddcum[((size_t)(b * T_ + t)) * 256 + h * 16 + j];
    float s2, c2;
    sincosf(ang, &s2, &c2);

    const float qp0 = __shfl_xor_sync(0xffffffffu, q0, 16);
    const float qp1 = __shfl_xor_sync(0xffffffffu, q1, 16);
    const float kp0 = __shfl_xor_sync(0xffffffffu, k0, 16);
    const float kp1 = __shfl_xor_sync(0xffffffffu, k1, 16);
    float oq0, oq1, ok0, ok1;
    if (lane < 16) {
        oq0 = q0 * c - qp0 * s;  oq1 = q1 * c2 - qp1 * s2;
        ok0 = k0 * c - kp0 * s;  ok1 = k1 * c2 - kp1 * s2;
    } else {
        oq0 = q0 * c + qp0 * s;  oq1 = q1 * c2 + qp1 * s2;
        ok0 = k0 * c + kp0 * s;  ok1 = k1 * c2 + kp1 * s2;
    }

    const size_t ob = ((size_t)(b * NH_ + h) * T_ + t) * DH_;
    qt[ob + lane]      = __float2half(oq0 * 0.125f);
    qt[ob + 32 + lane] = __float2half(oq1 * 0.125f);
    kt[ob + lane]      = __float2half(ok0);
    kt[ob + 32 + lane] = __float2half(ok1);
    vt[ob + lane]      = v0;
    vt[ob + 32 + lane] = v1;
}

// ---------------------------------------------------------------------------
// fp16 flash attention: Q tile 128, K tile 64, 8 warps, register-resident P.
// Ks: [64 keys][72 halves]; Vs2: key-pair-packed half2 [32][72].
// 2 CTAs/SM (18.4KB smem). Output fp16 y in [B,T,D].
// ---------------------------------------------------------------------------
#define FSMEMH (64 * 72 * 2 + 32 * 72 * 4)   // 18432 B

__global__ __launch_bounds__(256, 2) void flash_h(
    const __half* __restrict__ qt, const __half* __restrict__ kt,
    const __half* __restrict__ vt, __half* __restrict__ yh)
{
    extern __shared__ __half fsmh[];
    __half* Ks = fsmh;                              // [64][72]
    uint32_t* Vs2 = (uint32_t*)(fsmh + 64 * 72);    // [32][72] half2 cells

    const int tid = threadIdx.x, lane = tid & 31, w = tid >> 5;
    const int bx = gridDim.x - 1 - blockIdx.x;      // heavy q-tiles first
    const int bh = blockIdx.y;
    const int b = bh >> 4, h = bh & 15;
    const int m0 = bx * 128;

    const __half* Qb = qt + (size_t)bh * T_ * DH_;
    const __half* Kb = kt + (size_t)bh * T_ * DH_;
    const __half* Vb = vt + (size_t)bh * T_ * DH_;

    const int r1 = m0 + w * 16 + (lane >> 2);
    uint32_t qf[4][4];
    {
        const __half* q1 = Qb + (size_t)r1 * DH_;
        const __half* q2 = q1 + 8 * DH_;
        #pragma unroll
        for (int c = 0; c < 4; c++) {
            const int col = c * 16 + 2 * (lane & 3);
            qf[c][0] = *(const uint32_t*)(q1 + col);
            qf[c][1] = *(const uint32_t*)(q2 + col);
            qf[c][2] = *(const uint32_t*)(q1 + col + 8);
            qf[c][3] = *(const uint32_t*)(q2 + col + 8);
        }
    }

    float mi[2] = { -1e30f, -1e30f }, li[2] = { 0.f, 0.f };
    float O[8][4] = {};

    const int ntiles = 2 * bx + 2;
    for (int nt = 0; nt < ntiles; nt++) {
        const int n0 = nt * 64;
        __syncthreads();
        {
            // K tile: thread loads 16 halves of one key row
            const int key = tid >> 2, db = (tid & 3) * 16;
            const __half* kp = Kb + (size_t)(n0 + key) * DH_ + db;
            *(uint4*)&Ks[key * 72 + db]     = *(const uint4*)kp;
            *(uint4*)&Ks[key * 72 + db + 8] = *(const uint4*)(kp + 8);
            // V tile: pack key pairs into half2 cells
            const int kp2 = tid >> 3, dv = (tid & 7) * 8;
            const __half* v0p = Vb + (size_t)(n0 + 2 * kp2) * DH_ + dv;
            const __half* v1p = v0p + DH_;
            __half a8[8], b8[8];
            *(uint4*)a8 = *(const uint4*)v0p;
            *(uint4*)b8 = *(const uint4*)v1p;
            uint32_t pk[8];
            #pragma unroll
            for (int i = 0; i < 8; i++) {
                __half2 t2; t2.x = a8[i]; t2.y = b8[i];
                pk[i] = *(uint32_t*)&t2;
            }
            *(uint4*)&Vs2[kp2 * 72 + dv]     = *(uint4*)pk;
            *(uint4*)&Vs2[kp2 * 72 + dv + 4] = *(uint4*)(pk + 4);
        }
        __syncthreads();

        // S = Q K^T (fp16 HMMA, k16)
        float S[8][4] = {};
        #pragma unroll
        for (int c = 0; c < 4; c++) {
            #pragma unroll
            for (int n8 = 0; n8 < 8; n8++) {
                const __half* kr = &Ks[(n8 * 8 + (lane >> 2)) * 72 + c * 16 + 2 * (lane & 3)];
                uint32_t b0 = *(const uint32_t*)kr;
                uint32_t b1 = *(const uint32_t*)(kr + 8);
                MMAH16816(S[n8], qf[c], b0, b1);
            }
        }
        // causal mask
        if (nt >= 2 * bx) {
            #pragma unroll
            for (int n8 = 0; n8 < 8; n8++) {
                const int cb = n0 + n8 * 8 + 2 * (lane & 3);
                if (cb     > r1)     S[n8][0] = -1e30f;
                if (cb + 1 > r1)     S[n8][1] = -1e30f;
                if (cb     > r1 + 8) S[n8][2] = -1e30f;
                if (cb + 1 > r1 + 8) S[n8][3] = -1e30f;
            }
        }
        // online softmax
        #pragma unroll
        for (int half = 0; half < 2; half++) {
            float mx = -1e30f;
            #pragma unroll
            for (int n8 = 0; n8 < 8; n8++)
                mx = fmaxf(mx, fmaxf(S[n8][half * 2], S[n8][half * 2 + 1]));
            mx = fmaxf(mx, __shfl_xor_sync(0xffffffffu, mx, 1));
            mx = fmaxf(mx, __shfl_xor_sync(0xffffffffu, mx, 2));
            const float mnew = fmaxf(mi[half], mx);
            const float corr = __expf(mi[half] - mnew);
            float rsum = 0.f;
            #pragma unroll
            for (int n8 = 0; n8 < 8; n8++) {
                float e0 = __expf(S[n8][half * 2]     - mnew);
                float e1 = __expf(S[n8][half * 2 + 1] - mnew);
                S[n8][half * 2] = e0; S[n8][half * 2 + 1] = e1;
                rsum += e0 + e1;
            }
            rsum += __shfl_xor_sync(0xffffffffu, rsum, 1);
            rsum += __shfl_xor_sync(0xffffffffu, rsum, 2);
            li[half] = li[half] * corr + rsum;
            mi[half] = mnew;
            #pragma unroll
            for (int n8 = 0; n8 < 8; n8++) {
                O[n8][half * 2]     *= corr;
                O[n8][half * 2 + 1] *= corr;
            }
        }
        // O += P V  (P packed straight from S registers — no smem)
        #pragma unroll
        for (int c = 0; c < 4; c++) {
            uint32_t a[4];
            a[0] = h2bits(S[2 * c][0],     S[2 * c][1]);
            a[1] = h2bits(S[2 * c][2],     S[2 * c][3]);
            a[2] = h2bits(S[2 * c + 1][0], S[2 * c + 1][1]);
            a[3] = h2bits(S[2 * c + 1][2], S[2 * c + 1][3]);
            const uint32_t* vr0 = &Vs2[((lane & 3) + c * 8) * 72 + (lane >> 2)];
            const uint32_t* vr1 = vr0 + 4 * 72;
            #pragma unroll
            for (int n8 = 0; n8 < 8; n8++) {
                MMAH16816(O[n8], a, vr0[n8 * 8], vr1[n8 * 8]);
            }
        }
    }

    const float inv0 = 1.f / li[0], inv1 = 1.f / li[1];
    const size_t o1 = ((size_t)(b * T_ + r1)) * D_ + h * DH_ + 2 * (lane & 3);
    const size_t o2 = o1 + 8 * D_;
    #pragma unroll
    for (int n8 = 0; n8 < 8; n8++) {
        __half2 h0, h1;
        h0.x = __float2half(O[n8][0] * inv0); h0.y = __float2half(O[n8][1] * inv0);
        h1.x = __float2half(O[n8][2] * inv1); h1.y = __float2half(O[n8][3] * inv1);
        *(__half2*)(yh + o1 + n8 * 8) = h0;
        *(__half2*)(yh + o2 + n8 * 8) = h1;
    }
}

// ---------------------------------------------------------------------------
// act = silu(gate)*up from fp16 combined -> fp16
// ---------------------------------------------------------------------------
__global__ void act_half_kernel(const __half* __restrict__ gu,
                                __half* __restrict__ oh)
{
    const size_t idx4 = (size_t)blockIdx.x * blockDim.x + threadIdx.x;
    const int row = (int)(idx4 / (FFNP / 4));
    const int c = (int)(idx4 % (FFNP / 4)) * 4;
    const __half* gp = gu + (size_t)row * (2 * FFNP) + c;
    __half gh[4], uh[4];
    *(uint2*)gh = *(const uint2*)gp;
    *(uint2*)uh = *(const uint2*)(gp + FFNP);
    __half hb[4];
    #pragma unroll
    for (int j = 0; j < 4; j++) {
        float g = __half2float(gh[j]);
        float u = __half2float(uh[j]);
        hb[j] = __float2half(g / (1.f + __expf(-g)) * u);
    }
    *(uint2*)(oh + (size_t)row * FFNP + c) = *(uint2*)hb;
}

// ---------------------------------------------------------------------------
// Launch
// ---------------------------------------------------------------------------
static inline int cdiv(long long a, long long b) { return (int)((a + b - 1) / b); }

extern "C" void kernel_launch(void* const* d_in, const int* in_sizes, int n_in,
                              void* d_out, int out_size)
{
    const float* x     = (const float*)d_in[0];
    const float* rc    = (const float*)d_in[1];
    const float* rs    = (const float*)d_in[2];
    const float* lerpw = (const float*)d_in[3];
    const float* lerpb = (const float*)d_in[4];
    const float* anw   = (const float*)d_in[5];
    const float* wqkv  = (const float*)d_in[6];
    const float* qnw   = (const float*)d_in[7];
    const float* knw   = (const float*)d_in[8];
    const float* qpb   = (const float*)d_in[9];
    const float* kpb   = (const float*)d_in[10];
    const float* ddw   = (const float*)d_in[11];
    const float* ddb   = (const float*)d_in[12];
    const float* wo    = (const float*)d_in[13];
    const float* mnw   = (const float*)d_in[14];
    const float* gw    = (const float*)d_in[15];
    const float* uw    = (const float*)d_in[16];
    const float* dw    = (const float*)d_in[17];
    float* out = (float*)d_out;

    float *glin, *xmix, *dd, *cs, *x2;
    __half *qkvh, *qth, *kth, *vth, *guh;
    __nv_bfloat16 *ah, *al, *wh, *wl;
    __half *af, *wf;
    cudaGetSymbolAddress((void**)&glin, s_glin);
    cudaGetSymbolAddress((void**)&xmix, s_xmix);
    cudaGetSymbolAddress((void**)&dd,   s_dd);
    cudaGetSymbolAddress((void**)&cs,   s_csum);
    cudaGetSymbolAddress((void**)&x2,   s_x2);
    cudaGetSymbolAddress((void**)&qkvh, s_qkvh);
    cudaGetSymbolAddress((void**)&qth,  s_qth);
    cudaGetSymbolAddress((void**)&kth,  s_kth);
    cudaGetSymbolAddress((void**)&vth,  s_vth);
    cudaGetSymbolAddress((void**)&guh,  s_guh);
    cudaGetSymbolAddress((void**)&ah,   g_ah);
    cudaGetSymbolAddress((void**)&al,   g_al);
    cudaGetSymbolAddress((void**)&wh,   g_wh);
    cudaGetSymbolAddress((void**)&wl,   g_wl);
    cudaGetSymbolAddress((void**)&af,   g_af);
    cudaGetSymbolAddress((void**)&wf,   g_wf);

    cudaFuncSetAttribute(mma_gemm,
                         cudaFuncAttributeMaxDynamicSharedMemorySize, 3 * BUFB);
    cudaFuncSetAttribute(mma_gemm_h,
                         cudaFuncAttributeMaxDynamicSharedMemorySize, 3 * BUFBH);
    cudaFuncSetAttribute(flash_h,
                         cudaFuncAttributeMaxDynamicSharedMemorySize, FSMEMH);

    const dim3 blk(256);
    const int GSM  = 3 * BUFB;    // 122880
    const int GSMH = 3 * BUFBH;   // 61440

    #define CONVH(src, d, n) \
        conv_half<<<(int)(((long long)(n) / 4) / 256), blk>>>(src, d)
    #define CONVW(src, d, r, c, rp, cp) \
        conv_whalf<<<cdiv((long long)(rp) * (cp), 256), blk>>>(src, d, r, c, rp, cp)

    // 1. glin = x @ lerp_w^T + lerp_b
    CONVH(x, af, (long long)M_ * D_);
    CONVW(lerpw, wf, D_, D_, D_, D_);
    mma_gemm_h<<<dim3(8, 32), blk, GSMH>>>(af, wf, lerpb, nullptr, glin, D_, 32, D_, 1);
    // 2. xmix (fp32 + bf16 split for dd)
    mix_split_kernel<<<(M_ * D_ / 4) / 256, blk>>>(x, glin, xmix, ah, al);
    // 3. dd = xmix @ dd_w^T + dd_b (bf16 3-term)
    convsplit<<<cdiv(256LL * D_, 256), blk>>>(ddw, wh, wl, 256, D_, 256, D_);
    mma_gemm<<<dim3(2, 32), blk, GSM>>>(ah, al, wh, wl, ddb, nullptr, dd, D_, 32, 256, 1);
    // 4. cumsum along T
    cumsumA<<<B_ * 16, blk>>>(dd, cs);
    cumsumB<<<B_, blk>>>(cs);
    cumsumC<<<B_ * 16, blk>>>(dd, cs);
    // 5. h = rmsnorm(xmix) -> fp16
    rmsnorm_half_kernel<<<M_, blk>>>(xmix, anw, af);
    // 6. qkv = h @ w_qkv^T -> fp16
    CONVW(wqkv, wf, 3 * D_, D_, 3 * D_, D_);
    mma_gemm_h<<<dim3(24, 32), blk, GSMH>>>(af, wf, nullptr, nullptr,
                                            (float*)qkvh, D_, 32, 3 * D_, 4);
    // 7. q/k transform (fp16 in/out, q pre-scaled)
    qkv_transform_h<<<(B_ * T_ * NH_) / 8, blk>>>(qkvh, dd, rc, rs, qnw, knw,
                                                  qpb, kpb, qth, kth, vth);
    // 8. flash attention (fp16) -> y fp16
    flash_h<<<dim3(T_ / 128, B_ * NH_), blk, FSMEMH>>>(qth, kth, vth, af);
    // 9. x2 = xmix + y @ w_o^T
    CONVW(wo, wf, D_, D_, D_, D_);
    mma_gemm_h<<<dim3(8, 32), blk, GSMH>>>(af, wf, nullptr, xmix, x2, D_, 32, D_, 2);
    // 10. h = rmsnorm(x2) -> fp16
    rmsnorm_half_kernel<<<M_, blk>>>(x2, mnw, af);
    // 11. combined gate|up GEMM -> fp16
    CONVW(gw, wf, FFN_, D_, FFNP, D_);
    conv_whalf<<<cdiv((long long)FFNP * D_, 256), blk>>>(uw, wf + (size_t)FFNP * D_,
                                                         FFN_, D_, FFNP, D_);
    mma_gemm_h<<<dim3(44, 32), blk, GSMH>>>(af, wf, nullptr, nullptr,
                                            (float*)guh, D_, 32, 2 * FFNP, 4);
    // 12. act = silu(gate)*up -> fp16
    act_half_kernel<<<(M_ * FFNP / 4) / 256, blk>>>(guh, af);
    // 13. out = x2 + act @ down_w^T
    CONVW(dw, wf, D_, FFN_, D_, FFNP);
    mma_gemm_h<<<dim3(8, 32), blk, GSMH>>>(af, wf, nullptr, x2, out, FFNP, 88, D_, 2);
}